// round 6
// baseline (speedup 1.0000x reference)
#include <cuda_runtime.h>
#include <cuda_bf16.h>
#include <cstdint>
#include <math.h>

// Problem constants
#define BB 2
#define LL 2048
#define DD 1024
#define HH 16
#define DHH 64
#define TT (BB*LL)          // 4096 tokens
#define EPS 1e-5f

// -------- scratch (device globals: allocation-free rule) --------
__device__ float g_h[TT * DD];            // LN1 output
__device__ float g_qkv[TT * 3 * DD];      // QKV GEMM output
__device__ float g_q[TT * DD];            // [B,H,L,DH] roped q
__device__ float g_k[TT * DD];            // [B,H,L,DH] roped k
__device__ float g_v[TT * DD];            // [B,H,L,DH] v
__device__ float g_ctx[TT * DD];          // attention output

__device__ __forceinline__ uint32_t f2tf32(float f) {
    uint32_t r; asm("cvt.rna.tf32.f32 %0, %1;" : "=r"(r) : "f"(f)); return r;
}

__device__ __forceinline__ void mma16n8k8(float* d, const uint32_t* a,
                                          uint32_t b0, uint32_t b1) {
    asm volatile(
        "mma.sync.aligned.m16n8k8.row.col.f32.tf32.tf32.f32 "
        "{%0,%1,%2,%3}, {%4,%5,%6,%7}, {%8,%9}, {%0,%1,%2,%3};"
        : "+f"(d[0]), "+f"(d[1]), "+f"(d[2]), "+f"(d[3])
        : "r"(a[0]), "r"(a[1]), "r"(a[2]), "r"(a[3]), "r"(b0), "r"(b1));
}

// bf16 helpers for attention MMA
__device__ __forceinline__ uint32_t bfpack(float a, float b) {
    __nv_bfloat162 t = __floats2bfloat162_rn(a, b);
    return *reinterpret_cast<uint32_t*>(&t);
}
__device__ __forceinline__ void bfsplit(float a, float b, uint32_t& hi, uint32_t& lo) {
    __nv_bfloat16 ha = __float2bfloat16_rn(a), hb = __float2bfloat16_rn(b);
    float ra = a - __bfloat162float(ha);
    float rb = b - __bfloat162float(hb);
    __nv_bfloat162 h; h.x = ha; h.y = hb;
    hi = *reinterpret_cast<uint32_t*>(&h);
    lo = bfpack(ra, rb);
}
__device__ __forceinline__ void mma16816(float* c, uint32_t a0, uint32_t a1,
                                         uint32_t a2, uint32_t a3,
                                         uint32_t b0, uint32_t b1) {
    asm volatile(
        "mma.sync.aligned.m16n8k16.row.col.f32.bf16.bf16.f32 "
        "{%0,%1,%2,%3}, {%4,%5,%6,%7}, {%8,%9}, {%0,%1,%2,%3};"
        : "+f"(c[0]), "+f"(c[1]), "+f"(c[2]), "+f"(c[3])
        : "r"(a0), "r"(a1), "r"(a2), "r"(a3), "r"(b0), "r"(b1));
}

// ===================== tf32 mma.sync GEMM (64x64 warp tile) =====================
// C[M,N] = A[M,1024] * B[N,1024]^T. CTA tile 256x128, BK=16, 8 warps
// as 4(m) x 2(n); each warp computes 64x64 -> 64 B of smem fragment
// traffic per MMA (3x less than 32x64 tiling) => tensor-bound.
#define GK 1024
#define BKc 16
#define NCHUNK (GK / BKc)    // 64
#define PADg 20              // 16 k-words + 4 pad
#define ABUF (256 * PADg)
#define BBUF (128 * PADg)
#define GEMM_SMEM ((2 * ABUF + 2 * BBUF) * 4)   // 61440 B

__global__ __launch_bounds__(256)
void gemm_mma_tf32(const float* __restrict__ A, const float* __restrict__ B,
                   float* __restrict__ C, int N) {
    extern __shared__ float sm[];
    float* As = sm;                  // [2][256][PADg]
    float* Bs = sm + 2 * ABUF;       // [2][128][PADg]

    const int tid = threadIdx.x;
    const int wid = tid >> 5, lane = tid & 31;
    const int grp = lane >> 2, qd = lane & 3;
    const int wm = wid >> 1, wn = wid & 1;   // 4 m-warps x 2 n-warps
    const int m0 = blockIdx.y * 256;
    const int n0 = blockIdx.x * 128;

    const int brow = tid >> 1;           // B staging row (0..127)
    const int bc4  = (tid & 1) * 2;      // quad offset 0 or 2

    float acc[4][8][4];
    #pragma unroll
    for (int i = 0; i < 4; i++)
        #pragma unroll
        for (int j = 0; j < 8; j++)
            #pragma unroll
            for (int q = 0; q < 4; q++) acc[i][j][q] = 0.f;

    float4 pa[4], pb[2];
    // ---- load chunk 0 ----
    {
        const float* Ar = A + (size_t)(m0 + tid) * GK;
        #pragma unroll
        for (int i = 0; i < 4; i++) pa[i] = *(const float4*)(Ar + i * 4);
        const float* Br = B + (size_t)(n0 + brow) * GK + bc4 * 4;
        pb[0] = *(const float4*)(Br);
        pb[1] = *(const float4*)(Br + 4);
    }
    {
        float* pA = As + tid * PADg;
        #pragma unroll
        for (int i = 0; i < 4; i++) {
            pA[i*4+0] = __uint_as_float(f2tf32(pa[i].x));
            pA[i*4+1] = __uint_as_float(f2tf32(pa[i].y));
            pA[i*4+2] = __uint_as_float(f2tf32(pa[i].z));
            pA[i*4+3] = __uint_as_float(f2tf32(pa[i].w));
        }
        float* pB = Bs + brow * PADg + bc4 * 4;
        pB[0] = __uint_as_float(f2tf32(pb[0].x));
        pB[1] = __uint_as_float(f2tf32(pb[0].y));
        pB[2] = __uint_as_float(f2tf32(pb[0].z));
        pB[3] = __uint_as_float(f2tf32(pb[0].w));
        pB[4] = __uint_as_float(f2tf32(pb[1].x));
        pB[5] = __uint_as_float(f2tf32(pb[1].y));
        pB[6] = __uint_as_float(f2tf32(pb[1].z));
        pB[7] = __uint_as_float(f2tf32(pb[1].w));
    }
    __syncthreads();

    for (int ic = 0; ic < NCHUNK; ic++) {
        // prefetch next chunk into registers
        if (ic + 1 < NCHUNK) {
            const float* Ar = A + (size_t)(m0 + tid) * GK + (ic + 1) * BKc;
            #pragma unroll
            for (int i = 0; i < 4; i++) pa[i] = *(const float4*)(Ar + i * 4);
            const float* Br = B + (size_t)(n0 + brow) * GK + (ic + 1) * BKc + bc4 * 4;
            pb[0] = *(const float4*)(Br);
            pb[1] = *(const float4*)(Br + 4);
        }

        const float* Ab = As + (ic & 1) * ABUF;
        const float* Bb = Bs + (ic & 1) * BBUF;
        #pragma unroll
        for (int ks = 0; ks < 2; ks++) {
            int kb = ks * 8 + qd;
            uint32_t af[4][4];
            #pragma unroll
            for (int mt = 0; mt < 4; mt++) {
                int r = wm * 64 + mt * 16 + grp;
                af[mt][0] = __float_as_uint(Ab[r * PADg + kb]);
                af[mt][1] = __float_as_uint(Ab[(r + 8) * PADg + kb]);
                af[mt][2] = __float_as_uint(Ab[r * PADg + kb + 4]);
                af[mt][3] = __float_as_uint(Ab[(r + 8) * PADg + kb + 4]);
            }
            #pragma unroll
            for (int nt = 0; nt < 8; nt++) {
                int c = wn * 64 + nt * 8 + grp;
                uint32_t b0 = __float_as_uint(Bb[c * PADg + kb]);
                uint32_t b1 = __float_as_uint(Bb[c * PADg + kb + 4]);
                #pragma unroll
                for (int mt = 0; mt < 4; mt++)
                    mma16n8k8(acc[mt][nt], af[mt], b0, b1);
            }
        }

        if (ic + 1 < NCHUNK) {
            float* Ad = As + ((ic + 1) & 1) * ABUF + tid * PADg;
            #pragma unroll
            for (int i = 0; i < 4; i++) {
                Ad[i*4+0] = __uint_as_float(f2tf32(pa[i].x));
                Ad[i*4+1] = __uint_as_float(f2tf32(pa[i].y));
                Ad[i*4+2] = __uint_as_float(f2tf32(pa[i].z));
                Ad[i*4+3] = __uint_as_float(f2tf32(pa[i].w));
            }
            float* Bd = Bs + ((ic + 1) & 1) * BBUF + brow * PADg + bc4 * 4;
            Bd[0] = __uint_as_float(f2tf32(pb[0].x));
            Bd[1] = __uint_as_float(f2tf32(pb[0].y));
            Bd[2] = __uint_as_float(f2tf32(pb[0].z));
            Bd[3] = __uint_as_float(f2tf32(pb[0].w));
            Bd[4] = __uint_as_float(f2tf32(pb[1].x));
            Bd[5] = __uint_as_float(f2tf32(pb[1].y));
            Bd[6] = __uint_as_float(f2tf32(pb[1].z));
            Bd[7] = __uint_as_float(f2tf32(pb[1].w));
            __syncthreads();
        }
    }

    // epilogue: direct float2 stores
    #pragma unroll
    for (int mt = 0; mt < 4; mt++) {
        #pragma unroll
        for (int nt = 0; nt < 8; nt++) {
            int r = m0 + wm * 64 + mt * 16 + grp;
            int c = n0 + wn * 64 + nt * 8 + qd * 2;
            *(float2*)(C + (size_t)r * N + c) =
                make_float2(acc[mt][nt][0], acc[mt][nt][1]);
            *(float2*)(C + (size_t)(r + 8) * N + c) =
                make_float2(acc[mt][nt][2], acc[mt][nt][3]);
        }
    }
}

// ---------------- block reduction helper (256 threads) ----------------
__device__ __forceinline__ void block_reduce4(float& a, float& b, float& c, float& d) {
    #pragma unroll
    for (int o = 16; o; o >>= 1) {
        a += __shfl_xor_sync(0xffffffffu, a, o);
        b += __shfl_xor_sync(0xffffffffu, b, o);
        c += __shfl_xor_sync(0xffffffffu, c, o);
        d += __shfl_xor_sync(0xffffffffu, d, o);
    }
    __shared__ float s[4][8];
    int w = threadIdx.x >> 5, lane = threadIdx.x & 31;
    if (lane == 0) { s[0][w] = a; s[1][w] = b; s[2][w] = c; s[3][w] = d; }
    __syncthreads();
    a = b = c = d = 0.f;
    #pragma unroll
    for (int i = 0; i < 8; i++) { a += s[0][i]; b += s[1][i]; c += s[2][i]; d += s[3][i]; }
    __syncthreads();
}

// ---------------- kernel 1: LN1 ----------------
__global__ void ln1_kernel(const float* __restrict__ x,
                           const float* __restrict__ w,
                           const float* __restrict__ bia) {
    int t = blockIdx.x;
    int tid = threadIdx.x;
    const float4* xr = (const float4*)(x + (size_t)t * DD);
    float4 v = xr[tid];
    float s  = v.x + v.y + v.z + v.w;
    float ss = v.x*v.x + v.y*v.y + v.z*v.z + v.w*v.w;
    float z0 = 0.f, z1 = 0.f;
    block_reduce4(s, ss, z0, z1);
    float mu  = s * (1.0f / DD);
    float var = ss * (1.0f / DD) - mu * mu;
    float inv = rsqrtf(var + EPS);
    float4 wv = ((const float4*)w)[tid];
    float4 bv = ((const float4*)bia)[tid];
    float4 o;
    o.x = (v.x - mu) * inv * wv.x + bv.x;
    o.y = (v.y - mu) * inv * wv.y + bv.y;
    o.z = (v.z - mu) * inv * wv.z + bv.z;
    o.w = (v.w - mu) * inv * wv.w + bv.w;
    ((float4*)(g_h + (size_t)t * DD))[tid] = o;
}

// ---------------- kernel 3: QK LayerNorm + RoPE + transpose ----------------
__global__ void qk_rope_kernel(const float* __restrict__ qw,
                               const float* __restrict__ kw) {
    int t = blockIdx.x;
    int b = t >> 11;
    int l = t & 2047;
    int tid = threadIdx.x;
    const float4* row = (const float4*)(g_qkv + (size_t)t * 3 * DD);
    float4 q = row[tid];
    float4 k = row[256 + tid];
    float4 v = row[512 + tid];

    float qs  = q.x + q.y + q.z + q.w;
    float qss = q.x*q.x + q.y*q.y + q.z*q.z + q.w*q.w;
    float ks  = k.x + k.y + k.z + k.w;
    float kss = k.x*k.x + k.y*k.y + k.z*k.z + k.w*k.w;
    block_reduce4(qs, qss, ks, kss);
    float muq = qs * (1.0f / DD);
    float vq  = qss * (1.0f / DD) - muq * muq;
    float iq  = rsqrtf(vq + EPS);
    float muk = ks * (1.0f / DD);
    float vk  = kss * (1.0f / DD) - muk * muk;
    float ik  = rsqrtf(vk + EPS);

    __shared__ float qn[DD];
    __shared__ float kn[DD];
    float4 qwv = ((const float4*)qw)[tid];
    float4 kwv = ((const float4*)kw)[tid];
    int d0 = tid * 4;
    qn[d0+0] = (q.x - muq) * iq * qwv.x;
    qn[d0+1] = (q.y - muq) * iq * qwv.y;
    qn[d0+2] = (q.z - muq) * iq * qwv.z;
    qn[d0+3] = (q.w - muq) * iq * qwv.w;
    kn[d0+0] = (k.x - muk) * ik * kwv.x;
    kn[d0+1] = (k.y - muk) * ik * kwv.y;
    kn[d0+2] = (k.z - muk) * ik * kwv.z;
    kn[d0+3] = (k.w - muk) * ik * kwv.w;
    __syncthreads();

    int h   = d0 >> 6;
    int dh0 = d0 & 63;
    float oq[4], ok[4];
    #pragma unroll
    for (int j = 0; j < 4; j++) {
        int dh = dh0 + j;
        int fi = dh & 31;
        float invf = powf(10000.0f, -((float)(2 * fi)) / 64.0f);
        float ang  = (float)l * invf;
        float c = cosf(ang), s = sinf(ang);
        float qv = qn[d0 + j];
        float kv = kn[d0 + j];
        float qp = (dh < 32) ? -qn[d0 + j + 32] : qn[d0 + j - 32];
        float kp = (dh < 32) ? -kn[d0 + j + 32] : kn[d0 + j - 32];
        oq[j] = qv * c + qp * s;
        ok[j] = kv * c + kp * s;
    }
    size_t oidx = (((size_t)(b * HH + h) * LL + l) * DHH + dh0);
    *(float4*)(g_q + oidx) = make_float4(oq[0], oq[1], oq[2], oq[3]);
    *(float4*)(g_k + oidx) = make_float4(ok[0], ok[1], ok[2], ok[3]);
    *(float4*)(g_v + oidx) = v;
}

// ---------------- kernel 4: flash attention, bf16-split3 mma.sync ----------------
#define AW 36   // 32 data words + 4 pad
#define ATTN_SMEM (6 * 64 * AW * 4)   // 55296 B

__global__ __launch_bounds__(128)
void attn_kernel(const int* __restrict__ seq_id) {
    extern __shared__ uint32_t smw[];
    uint32_t* Qh  = smw;                // [64][AW] bf16x2 (k-pairs)
    uint32_t* Ql  = Qh  + 64 * AW;
    uint32_t* KPh = Ql  + 64 * AW;      // K (then P) hi
    uint32_t* KPl = KPh + 64 * AW;
    uint32_t* VTh = KPl + 64 * AW;      // V^T: [d][n-pairs]
    uint32_t* VTl = VTh + 64 * AW;
    __shared__ int kseq[64];

    const int qt = blockIdx.x, bh = blockIdx.y;
    const int b = bh >> 4, hh = bh & 15;
    const int tid = threadIdx.x;
    const int w = tid >> 5, lane = tid & 31;
    const int grp = lane >> 2, qd = lane & 3;

    const int qbase = b * LL + qt * 64;
    const int qmin = seq_id[qbase];
    const int qmax = seq_id[qbase + 63];

    // stage Q (scale 1/8 folded in exactly; split into bf16 hi/lo planes)
    {
        const float4* Qg = (const float4*)(g_q + ((size_t)bh * LL + qt * 64) * DHH);
        #pragma unroll
        for (int i = 0; i < 8; i++) {
            int idx = tid + i * 128;
            int r = idx >> 4, c4 = idx & 15;
            float4 qv = Qg[r * 16 + c4];
            qv.x *= 0.125f; qv.y *= 0.125f; qv.z *= 0.125f; qv.w *= 0.125f;
            uint32_t h0, l0, h1, l1;
            bfsplit(qv.x, qv.y, h0, l0);
            bfsplit(qv.z, qv.w, h1, l1);
            Qh[r * AW + c4 * 2]     = h0;  Qh[r * AW + c4 * 2 + 1] = h1;
            Ql[r * AW + c4 * 2]     = l0;  Ql[r * AW + c4 * 2 + 1] = l1;
        }
    }
    const int row0 = w * 16 + grp, row1 = row0 + 8;
    const int qs0 = seq_id[qbase + row0];
    const int qs1 = seq_id[qbase + row1];

    float m0 = -1e30f, m1 = -1e30f, l0s = 0.f, l1s = 0.f;
    float O[8][4];
    #pragma unroll
    for (int dt = 0; dt < 8; dt++)
        #pragma unroll
        for (int q = 0; q < 4; q++) O[dt][q] = 0.f;

    for (int kt = 0; kt < LL / 64; kt++) {
        const int kb = b * LL + kt * 64;
        if (seq_id[kb + 63] < qmin || seq_id[kb] > qmax) continue;  // exact no-op tile

        __syncthreads();   // prior-iteration smem reads complete
        // stage K
        {
            const float4* Kg = (const float4*)(g_k + ((size_t)bh * LL + kt * 64) * DHH);
            #pragma unroll
            for (int i = 0; i < 8; i++) {
                int idx = tid + i * 128;
                int r = idx >> 4, c4 = idx & 15;
                float4 kv = Kg[r * 16 + c4];
                uint32_t h0, l0, h1, l1;
                bfsplit(kv.x, kv.y, h0, l0);
                bfsplit(kv.z, kv.w, h1, l1);
                KPh[r * AW + c4 * 2]     = h0;  KPh[r * AW + c4 * 2 + 1] = h1;
                KPl[r * AW + c4 * 2]     = l0;  KPl[r * AW + c4 * 2 + 1] = l1;
            }
        }
        // stage V transposed: VT[d][n-pair]
        {
            const float* Vg = g_v + ((size_t)bh * LL + kt * 64) * DHH;
            #pragma unroll
            for (int i = 0; i < 4; i++) {
                int idx = tid + i * 128;
                int p = idx & 31, c4 = idx >> 5;     // n-pair p, d-group c4 (0..15)
                float4 v0 = *(const float4*)(Vg + (2 * p) * DHH + c4 * 4);
                float4 v1 = *(const float4*)(Vg + (2 * p + 1) * DHH + c4 * 4);
                const float a0[4] = {v0.x, v0.y, v0.z, v0.w};
                const float a1[4] = {v1.x, v1.y, v1.z, v1.w};
                #pragma unroll
                for (int j = 0; j < 4; j++) {
                    uint32_t h, l;
                    bfsplit(a0[j], a1[j], h, l);
                    VTh[(c4 * 4 + j) * AW + p] = h;
                    VTl[(c4 * 4 + j) * AW + p] = l;
                }
            }
        }
        if (tid < 64) kseq[tid] = seq_id[kb + tid];
        __syncthreads();

        // ---- S = Q K^T (3-term split) ----
        float S[8][4];
        #pragma unroll
        for (int nt = 0; nt < 8; nt++)
            #pragma unroll
            for (int q = 0; q < 4; q++) S[nt][q] = 0.f;
        #pragma unroll
        for (int ks = 0; ks < 4; ks++) {
            int r0w = (w * 16 + grp) * AW, r1w = (w * 16 + grp + 8) * AW;
            int kw0 = ks * 8 + qd;
            uint32_t ah0 = Qh[r0w + kw0],     ah1 = Qh[r1w + kw0];
            uint32_t ah2 = Qh[r0w + kw0 + 4], ah3 = Qh[r1w + kw0 + 4];
            uint32_t al0 = Ql[r0w + kw0],     al1 = Ql[r1w + kw0];
            uint32_t al2 = Ql[r0w + kw0 + 4], al3 = Ql[r1w + kw0 + 4];
            #pragma unroll
            for (int nt = 0; nt < 8; nt++) {
                int nw = (nt * 8 + grp) * AW;
                uint32_t bh0 = KPh[nw + kw0], bh1 = KPh[nw + kw0 + 4];
                uint32_t bl0 = KPl[nw + kw0], bl1 = KPl[nw + kw0 + 4];
                mma16816(S[nt], ah0, ah1, ah2, ah3, bh0, bh1);
                mma16816(S[nt], ah0, ah1, ah2, ah3, bl0, bl1);
                mma16816(S[nt], al0, al1, al2, al3, bh0, bh1);
            }
        }

        // ---- mask ----
        #pragma unroll
        for (int nt = 0; nt < 8; nt++) {
            int c0 = kseq[nt * 8 + 2 * qd];
            int c1 = kseq[nt * 8 + 2 * qd + 1];
            if (c0 != qs0) S[nt][0] = -1e30f;
            if (c1 != qs0) S[nt][1] = -1e30f;
            if (c0 != qs1) S[nt][2] = -1e30f;
            if (c1 != qs1) S[nt][3] = -1e30f;
        }

        // ---- online softmax (row reductions within qd group) ----
        float mx0 = -1e30f, mx1 = -1e30f;
        #pragma unroll
        for (int nt = 0; nt < 8; nt++) {
            mx0 = fmaxf(mx0, fmaxf(S[nt][0], S[nt][1]));
            mx1 = fmaxf(mx1, fmaxf(S[nt][2], S[nt][3]));
        }
        mx0 = fmaxf(mx0, __shfl_xor_sync(0xffffffffu, mx0, 1));
        mx0 = fmaxf(mx0, __shfl_xor_sync(0xffffffffu, mx0, 2));
        mx1 = fmaxf(mx1, __shfl_xor_sync(0xffffffffu, mx1, 1));
        mx1 = fmaxf(mx1, __shfl_xor_sync(0xffffffffu, mx1, 2));
        float mn0 = fmaxf(m0, mx0), mn1 = fmaxf(m1, mx1);
        float sc0 = __expf(m0 - mn0), sc1 = __expf(m1 - mn1);
        m0 = mn0; m1 = mn1;
        float s0 = 0.f, s1 = 0.f;
        #pragma unroll
        for (int nt = 0; nt < 8; nt++) {
            S[nt][0] = __expf(S[nt][0] - mn0);
            S[nt][1] = __expf(S[nt][1] - mn0);
            S[nt][2] = __expf(S[nt][2] - mn1);
            S[nt][3] = __expf(S[nt][3] - mn1);
            s0 += S[nt][0] + S[nt][1];
            s1 += S[nt][2] + S[nt][3];
        }
        s0 += __shfl_xor_sync(0xffffffffu, s0, 1);
        s0 += __shfl_xor_sync(0xffffffffu, s0, 2);
        s1 += __shfl_xor_sync(0xffffffffu, s1, 1);
        s1 += __shfl_xor_sync(0xffffffffu, s1, 2);
        l0s = l0s * sc0 + s0;
        l1s = l1s * sc1 + s1;
        #pragma unroll
        for (int dt = 0; dt < 8; dt++) {
            O[dt][0] *= sc0; O[dt][1] *= sc0;
            O[dt][2] *= sc1; O[dt][3] *= sc1;
        }

        __syncthreads();   // all K fragment reads done before P overwrite
        // ---- write P (split) into KP buffers as [m][n-pair] ----
        #pragma unroll
        for (int nt = 0; nt < 8; nt++) {
            uint32_t h, l;
            bfsplit(S[nt][0], S[nt][1], h, l);
            KPh[(w * 16 + grp) * AW + nt * 4 + qd] = h;
            KPl[(w * 16 + grp) * AW + nt * 4 + qd] = l;
            bfsplit(S[nt][2], S[nt][3], h, l);
            KPh[(w * 16 + grp + 8) * AW + nt * 4 + qd] = h;
            KPl[(w * 16 + grp + 8) * AW + nt * 4 + qd] = l;
        }
        __syncthreads();

        // ---- O += P V (3-term split, K-dim = n) ----
        #pragma unroll
        for (int ks = 0; ks < 4; ks++) {
            int r0w = (w * 16 + grp) * AW, r1w = (w * 16 + grp + 8) * AW;
            int kw0 = ks * 8 + qd;
            uint32_t ah0 = KPh[r0w + kw0],     ah1 = KPh[r1w + kw0];
            uint32_t ah2 = KPh[r0w + kw0 + 4], ah3 = KPh[r1w + kw0 + 4];
            uint32_t al0 = KPl[r0w + kw0],     al1 = KPl[r1w + kw0];
            uint32_t al2 = KPl[r0w + kw0 + 4], al3 = KPl[r1w + kw0 + 4];
            #pragma unroll
            for (int dt = 0; dt < 8; dt++) {
                int dw = (dt * 8 + grp) * AW;
                uint32_t bh0 = VTh[dw + kw0], bh1 = VTh[dw + kw0 + 4];
                uint32_t bl0 = VTl[dw + kw0], bl1 = VTl[dw + kw0 + 4];
                mma16816(O[dt], ah0, ah1, ah2, ah3, bh0, bh1);
                mma16816(O[dt], ah0, ah1, ah2, ah3, bl0, bl1);
                mma16816(O[dt], al0, al1, al2, al3, bh0, bh1);
            }
        }
    }

    // epilogue
    float inv0 = 1.0f / l0s, inv1 = 1.0f / l1s;
    const int t0 = b * LL + qt * 64 + row0;
    const int t1 = b * LL + qt * 64 + row1;
    #pragma unroll
    for (int dt = 0; dt < 8; dt++) {
        int c = hh * DHH + dt * 8 + 2 * qd;
        *(float2*)(g_ctx + (size_t)t0 * DD + c) =
            make_float2(O[dt][0] * inv0, O[dt][1] * inv0);
        *(float2*)(g_ctx + (size_t)t1 * DD + c) =
            make_float2(O[dt][2] * inv1, O[dt][3] * inv1);
    }
}

// ---------------- launch ----------------
extern "C" void kernel_launch(void* const* d_in, const int* in_sizes, int n_in,
                              void* d_out, int out_size) {
    const float* x     = (const float*)d_in[0];
    const int*   seq   = (const int*)  d_in[1];
    const float* ln1w  = (const float*)d_in[2];
    const float* ln1b  = (const float*)d_in[3];
    const float* wqkv  = (const float*)d_in[4];
    const float* qlnw  = (const float*)d_in[5];
    const float* klnw  = (const float*)d_in[6];
    const float* outw  = (const float*)d_in[7];
    float* out = (float*)d_out;

    void *ph, *pqkv, *pctx;
    cudaGetSymbolAddress(&ph, g_h);
    cudaGetSymbolAddress(&pqkv, g_qkv);
    cudaGetSymbolAddress(&pctx, g_ctx);

    cudaFuncSetAttribute(gemm_mma_tf32, cudaFuncAttributeMaxDynamicSharedMemorySize, GEMM_SMEM);
    cudaFuncSetAttribute(attn_kernel, cudaFuncAttributeMaxDynamicSharedMemorySize, ATTN_SMEM);

    // 1) LN1
    ln1_kernel<<<TT, 256>>>(x, ln1w, ln1b);

    // 2) QKV GEMM: [4096,3072] = h x wqkv^T  (tf32 mma.sync, 64x64 warp tile)
    gemm_mma_tf32<<<dim3(3 * DD / 128, TT / 256), 256, GEMM_SMEM>>>(
        (const float*)ph, wqkv, (float*)pqkv, 3 * DD);

    // 3) QK LN + RoPE + transpose
    qk_rope_kernel<<<TT, 256>>>(qlnw, klnw);

    // 4) attention (tile-skip + bf16-split3 mma)
    attn_kernel<<<dim3(LL / 64, BB * HH), 128, ATTN_SMEM>>>(seq);

    // 5) output projection: [4096,1024] = ctx x out_w^T  (tf32 mma.sync)
    gemm_mma_tf32<<<dim3(DD / 128, TT / 256), 256, GEMM_SMEM>>>(
        (const float*)pctx, outw, out, DD);
}

// round 7
// speedup vs baseline: 1.4804x; 1.4804x over previous
#include <cuda_runtime.h>
#include <cuda_bf16.h>
#include <cstdint>
#include <math.h>

// Problem constants
#define BB 2
#define LL 2048
#define DD 1024
#define HH 16
#define DHH 64
#define TT (BB*LL)          // 4096 tokens
#define EPS 1e-5f
#define NBH (BB*HH)         // 32

// -------- scratch (device globals: allocation-free rule) --------
__device__ float g_h[TT * DD];            // LN1 output
__device__ float g_qkv[TT * 3 * DD];      // QKV GEMM output
__device__ float g_v[TT * DD];            // [B,H,L,DH] v (row-major, float)
__device__ float g_ctx[TT * DD];          // attention output
// pre-split bf16 planes, word = bf16x2 of adjacent head-dims: [bh][l][32 words]
__device__ __align__(16) uint32_t g_qh[NBH * LL * 32];
__device__ __align__(16) uint32_t g_ql[NBH * LL * 32];
__device__ __align__(16) uint32_t g_kh[NBH * LL * 32];
__device__ __align__(16) uint32_t g_kl[NBH * LL * 32];
// pre-split transposed V tiles: [bh][kt(32)][d(64)][32 l-pair words]
__device__ __align__(16) uint32_t g_vth[NBH * 32 * 64 * 32];
__device__ __align__(16) uint32_t g_vtl[NBH * 32 * 64 * 32];

__device__ __forceinline__ uint32_t f2tf32(float f) {
    uint32_t r; asm("cvt.rna.tf32.f32 %0, %1;" : "=r"(r) : "f"(f)); return r;
}

__device__ __forceinline__ void mma16n8k8(float* d, const uint32_t* a,
                                          uint32_t b0, uint32_t b1) {
    asm volatile(
        "mma.sync.aligned.m16n8k8.row.col.f32.tf32.tf32.f32 "
        "{%0,%1,%2,%3}, {%4,%5,%6,%7}, {%8,%9}, {%0,%1,%2,%3};"
        : "+f"(d[0]), "+f"(d[1]), "+f"(d[2]), "+f"(d[3])
        : "r"(a[0]), "r"(a[1]), "r"(a[2]), "r"(a[3]), "r"(b0), "r"(b1));
}

// bf16 helpers
__device__ __forceinline__ uint32_t bfpack(float a, float b) {
    __nv_bfloat162 t = __floats2bfloat162_rn(a, b);
    return *reinterpret_cast<uint32_t*>(&t);
}
__device__ __forceinline__ void bfsplit(float a, float b, uint32_t& hi, uint32_t& lo) {
    __nv_bfloat16 ha = __float2bfloat16_rn(a), hb = __float2bfloat16_rn(b);
    float ra = a - __bfloat162float(ha);
    float rb = b - __bfloat162float(hb);
    __nv_bfloat162 h; h.x = ha; h.y = hb;
    hi = *reinterpret_cast<uint32_t*>(&h);
    lo = bfpack(ra, rb);
}
__device__ __forceinline__ void mma16816(float* c, uint32_t a0, uint32_t a1,
                                         uint32_t a2, uint32_t a3,
                                         uint32_t b0, uint32_t b1) {
    asm volatile(
        "mma.sync.aligned.m16n8k16.row.col.f32.bf16.bf16.f32 "
        "{%0,%1,%2,%3}, {%4,%5,%6,%7}, {%8,%9}, {%0,%1,%2,%3};"
        : "+f"(c[0]), "+f"(c[1]), "+f"(c[2]), "+f"(c[3])
        : "r"(a0), "r"(a1), "r"(a2), "r"(a3), "r"(b0), "r"(b1));
}

__device__ __forceinline__ void cp16(uint32_t dst, const void* src) {
    asm volatile("cp.async.ca.shared.global [%0], [%1], 16;"
                 :: "r"(dst), "l"(src));
}
__device__ __forceinline__ void cp_commit() {
    asm volatile("cp.async.commit_group;");
}
__device__ __forceinline__ void cp_wait_all() {
    asm volatile("cp.async.wait_all;" ::: "memory");
}

// ===================== tf32 mma.sync GEMM (R5 version: 128x128, BK=32) ==========
#define GK 1024
#define BKc 32
#define NCHUNK (GK / BKc)    // 32
#define PADs 36
#define BUF_F (128 * PADs)
#define GEMM_SMEM (4 * BUF_F * 4)   // 73728 B

__global__ __launch_bounds__(256)
void gemm_mma_tf32(const float* __restrict__ A, const float* __restrict__ B,
                   float* __restrict__ C, int N) {
    extern __shared__ float sm[];
    float* As = sm;
    float* Bs = sm + 2 * BUF_F;

    const int tid = threadIdx.x;
    const int wid = tid >> 5, lane = tid & 31;
    const int grp = lane >> 2, qd = lane & 3;
    const int wm = wid >> 1, wn = wid & 1;
    const int m0 = blockIdx.y * 128;
    const int n0 = blockIdx.x * 128;

    float acc[2][8][4];
    #pragma unroll
    for (int i = 0; i < 2; i++)
        #pragma unroll
        for (int j = 0; j < 8; j++)
            #pragma unroll
            for (int q = 0; q < 4; q++) acc[i][j][q] = 0.f;

    float4 pa[4], pb[4];
    #pragma unroll
    for (int i = 0; i < 4; i++) {
        int u = tid + i * 256;
        int r = u >> 3, c4 = u & 7;
        pa[i] = *(const float4*)(A + (size_t)(m0 + r) * GK + c4 * 4);
        pb[i] = *(const float4*)(B + (size_t)(n0 + r) * GK + c4 * 4);
    }
    #pragma unroll
    for (int i = 0; i < 4; i++) {
        int u = tid + i * 256;
        int r = u >> 3, c4 = u & 7;
        float* pA = As + r * PADs + c4 * 4;
        pA[0] = __uint_as_float(f2tf32(pa[i].x));
        pA[1] = __uint_as_float(f2tf32(pa[i].y));
        pA[2] = __uint_as_float(f2tf32(pa[i].z));
        pA[3] = __uint_as_float(f2tf32(pa[i].w));
        float* pB = Bs + r * PADs + c4 * 4;
        pB[0] = __uint_as_float(f2tf32(pb[i].x));
        pB[1] = __uint_as_float(f2tf32(pb[i].y));
        pB[2] = __uint_as_float(f2tf32(pb[i].z));
        pB[3] = __uint_as_float(f2tf32(pb[i].w));
    }
    __syncthreads();

    for (int ic = 0; ic < NCHUNK; ic++) {
        if (ic + 1 < NCHUNK) {
            const float* An = A + (ic + 1) * BKc;
            const float* Bn = B + (ic + 1) * BKc;
            #pragma unroll
            for (int i = 0; i < 4; i++) {
                int u = tid + i * 256;
                int r = u >> 3, c4 = u & 7;
                pa[i] = *(const float4*)(An + (size_t)(m0 + r) * GK + c4 * 4);
                pb[i] = *(const float4*)(Bn + (size_t)(n0 + r) * GK + c4 * 4);
            }
        }

        const float* Ab = As + (ic & 1) * BUF_F;
        const float* Bb = Bs + (ic & 1) * BUF_F;
        #pragma unroll
        for (int ks = 0; ks < 4; ks++) {
            int kb = ks * 8;
            uint32_t af[2][4];
            #pragma unroll
            for (int mt = 0; mt < 2; mt++) {
                int r = wm * 32 + mt * 16 + grp;
                af[mt][0] = __float_as_uint(Ab[r * PADs + kb + qd]);
                af[mt][1] = __float_as_uint(Ab[(r + 8) * PADs + kb + qd]);
                af[mt][2] = __float_as_uint(Ab[r * PADs + kb + qd + 4]);
                af[mt][3] = __float_as_uint(Ab[(r + 8) * PADs + kb + qd + 4]);
            }
            #pragma unroll
            for (int nt = 0; nt < 8; nt++) {
                int c = wn * 64 + nt * 8 + grp;
                uint32_t b0 = __float_as_uint(Bb[c * PADs + kb + qd]);
                uint32_t b1 = __float_as_uint(Bb[c * PADs + kb + qd + 4]);
                mma16n8k8(acc[0][nt], af[0], b0, b1);
                mma16n8k8(acc[1][nt], af[1], b0, b1);
            }
        }

        if (ic + 1 < NCHUNK) {
            float* Ad = As + ((ic + 1) & 1) * BUF_F;
            float* Bd = Bs + ((ic + 1) & 1) * BUF_F;
            #pragma unroll
            for (int i = 0; i < 4; i++) {
                int u = tid + i * 256;
                int r = u >> 3, c4 = u & 7;
                float* pA = Ad + r * PADs + c4 * 4;
                pA[0] = __uint_as_float(f2tf32(pa[i].x));
                pA[1] = __uint_as_float(f2tf32(pa[i].y));
                pA[2] = __uint_as_float(f2tf32(pa[i].z));
                pA[3] = __uint_as_float(f2tf32(pa[i].w));
                float* pB = Bd + r * PADs + c4 * 4;
                pB[0] = __uint_as_float(f2tf32(pb[i].x));
                pB[1] = __uint_as_float(f2tf32(pb[i].y));
                pB[2] = __uint_as_float(f2tf32(pb[i].z));
                pB[3] = __uint_as_float(f2tf32(pb[i].w));
            }
            __syncthreads();
        }
    }

    #pragma unroll
    for (int mt = 0; mt < 2; mt++) {
        #pragma unroll
        for (int nt = 0; nt < 8; nt++) {
            int r = m0 + wm * 32 + mt * 16 + grp;
            int c = n0 + wn * 64 + nt * 8 + qd * 2;
            *(float2*)(C + (size_t)r * N + c) =
                make_float2(acc[mt][nt][0], acc[mt][nt][1]);
            *(float2*)(C + (size_t)(r + 8) * N + c) =
                make_float2(acc[mt][nt][2], acc[mt][nt][3]);
        }
    }
}

// ---------------- block reduction helper (256 threads) ----------------
__device__ __forceinline__ void block_reduce4(float& a, float& b, float& c, float& d) {
    #pragma unroll
    for (int o = 16; o; o >>= 1) {
        a += __shfl_xor_sync(0xffffffffu, a, o);
        b += __shfl_xor_sync(0xffffffffu, b, o);
        c += __shfl_xor_sync(0xffffffffu, c, o);
        d += __shfl_xor_sync(0xffffffffu, d, o);
    }
    __shared__ float s[4][8];
    int w = threadIdx.x >> 5, lane = threadIdx.x & 31;
    if (lane == 0) { s[0][w] = a; s[1][w] = b; s[2][w] = c; s[3][w] = d; }
    __syncthreads();
    a = b = c = d = 0.f;
    #pragma unroll
    for (int i = 0; i < 8; i++) { a += s[0][i]; b += s[1][i]; c += s[2][i]; d += s[3][i]; }
    __syncthreads();
}

// ---------------- kernel 1: LN1 ----------------
__global__ void ln1_kernel(const float* __restrict__ x,
                           const float* __restrict__ w,
                           const float* __restrict__ bia) {
    int t = blockIdx.x;
    int tid = threadIdx.x;
    const float4* xr = (const float4*)(x + (size_t)t * DD);
    float4 v = xr[tid];
    float s  = v.x + v.y + v.z + v.w;
    float ss = v.x*v.x + v.y*v.y + v.z*v.z + v.w*v.w;
    float z0 = 0.f, z1 = 0.f;
    block_reduce4(s, ss, z0, z1);
    float mu  = s * (1.0f / DD);
    float var = ss * (1.0f / DD) - mu * mu;
    float inv = rsqrtf(var + EPS);
    float4 wv = ((const float4*)w)[tid];
    float4 bv = ((const float4*)bia)[tid];
    float4 o;
    o.x = (v.x - mu) * inv * wv.x + bv.x;
    o.y = (v.y - mu) * inv * wv.y + bv.y;
    o.z = (v.z - mu) * inv * wv.z + bv.z;
    o.w = (v.w - mu) * inv * wv.w + bv.w;
    ((float4*)(g_h + (size_t)t * DD))[tid] = o;
}

// ---------------- kernel 3: QK LN + RoPE + pre-split bf16 planes ----------------
__global__ void qk_rope_kernel(const float* __restrict__ qw,
                               const float* __restrict__ kw) {
    int t = blockIdx.x;
    int b = t >> 11;
    int l = t & 2047;
    int tid = threadIdx.x;
    const float4* row = (const float4*)(g_qkv + (size_t)t * 3 * DD);
    float4 q = row[tid];
    float4 k = row[256 + tid];
    float4 v = row[512 + tid];

    float qs  = q.x + q.y + q.z + q.w;
    float qss = q.x*q.x + q.y*q.y + q.z*q.z + q.w*q.w;
    float ks  = k.x + k.y + k.z + k.w;
    float kss = k.x*k.x + k.y*k.y + k.z*k.z + k.w*k.w;
    block_reduce4(qs, qss, ks, kss);
    float muq = qs * (1.0f / DD);
    float vq  = qss * (1.0f / DD) - muq * muq;
    float iq  = rsqrtf(vq + EPS);
    float muk = ks * (1.0f / DD);
    float vk  = kss * (1.0f / DD) - muk * muk;
    float ik  = rsqrtf(vk + EPS);

    __shared__ float qn[DD];
    __shared__ float kn[DD];
    float4 qwv = ((const float4*)qw)[tid];
    float4 kwv = ((const float4*)kw)[tid];
    int d0 = tid * 4;
    qn[d0+0] = (q.x - muq) * iq * qwv.x;
    qn[d0+1] = (q.y - muq) * iq * qwv.y;
    qn[d0+2] = (q.z - muq) * iq * qwv.z;
    qn[d0+3] = (q.w - muq) * iq * qwv.w;
    kn[d0+0] = (k.x - muk) * ik * kwv.x;
    kn[d0+1] = (k.y - muk) * ik * kwv.y;
    kn[d0+2] = (k.z - muk) * ik * kwv.z;
    kn[d0+3] = (k.w - muk) * ik * kwv.w;
    __syncthreads();

    int h   = d0 >> 6;
    int dh0 = d0 & 63;
    float oq[4], ok[4];
    #pragma unroll
    for (int j = 0; j < 4; j++) {
        int dh = dh0 + j;
        int fi = dh & 31;
        float invf = powf(10000.0f, -((float)(2 * fi)) / 64.0f);
        float ang  = (float)l * invf;
        float c = cosf(ang), s = sinf(ang);
        float qv = qn[d0 + j];
        float kv = kn[d0 + j];
        float qp = (dh < 32) ? -qn[d0 + j + 32] : qn[d0 + j - 32];
        float kp = (dh < 32) ? -kn[d0 + j + 32] : kn[d0 + j - 32];
        oq[j] = (qv * c + qp * s) * 0.125f;   // fold 1/sqrt(DH) exactly
        ok[j] = kv * c + kp * s;
    }
    size_t pb = ((size_t)(b * HH + h) * LL + l) * 32 + (dh0 >> 1);
    uint32_t h0, l0, h1, l1;
    bfsplit(oq[0], oq[1], h0, l0);
    bfsplit(oq[2], oq[3], h1, l1);
    g_qh[pb] = h0; g_qh[pb + 1] = h1;
    g_ql[pb] = l0; g_ql[pb + 1] = l1;
    bfsplit(ok[0], ok[1], h0, l0);
    bfsplit(ok[2], ok[3], h1, l1);
    g_kh[pb] = h0; g_kh[pb + 1] = h1;
    g_kl[pb] = l0; g_kl[pb + 1] = l1;

    size_t oidx = (((size_t)(b * HH + h) * LL + l) * DHH + dh0);
    *(float4*)(g_v + oidx) = v;
}

// ---------------- kernel 3b: V transpose + split into tile planes ----------------
// grid (kt=32, bh=32), 128 threads.
__global__ void vtrans_kernel() {
    __shared__ float vs[64 * 65];   // [l][d], pad 65
    const int kt = blockIdx.x, bh = blockIdx.y;
    const int tid = threadIdx.x;
    const float4* Vg = (const float4*)(g_v + ((size_t)bh * LL + kt * 64) * DHH);
    #pragma unroll
    for (int i = 0; i < 8; i++) {
        int idx = tid + i * 128;
        int l = idx >> 4, c4 = idx & 15;
        float4 v = Vg[l * 16 + c4];
        vs[l * 65 + c4 * 4 + 0] = v.x;
        vs[l * 65 + c4 * 4 + 1] = v.y;
        vs[l * 65 + c4 * 4 + 2] = v.z;
        vs[l * 65 + c4 * 4 + 3] = v.w;
    }
    __syncthreads();
    size_t base = ((size_t)bh * 32 + kt) * 64 * 32;
    #pragma unroll
    for (int i = 0; i < 16; i++) {
        int idx = tid + i * 128;
        int d = idx >> 5, lp = idx & 31;
        float a = vs[(2 * lp) * 65 + d];
        float b = vs[(2 * lp + 1) * 65 + d];
        uint32_t h, l;
        bfsplit(a, b, h, l);
        g_vth[base + d * 32 + lp] = h;
        g_vtl[base + d * 32 + lp] = l;
    }
}

// ---------------- kernel 4: flash attention, cp.async staged pre-split planes ----
#define AW 36
#define ATTN_SMEM (6 * 64 * AW * 4)   // 55296 B

__global__ __launch_bounds__(128, 4)
void attn_kernel(const int* __restrict__ seq_id) {
    extern __shared__ uint32_t smw[];
    uint32_t* Qh  = smw;                // [64][AW]
    uint32_t* Ql  = Qh  + 64 * AW;
    uint32_t* KPh = Ql  + 64 * AW;      // K (then P) hi
    uint32_t* KPl = KPh + 64 * AW;
    uint32_t* VTh = KPl + 64 * AW;      // V^T hi
    uint32_t* VTl = VTh + 64 * AW;
    __shared__ int kseq[64];

    const int qt = blockIdx.x, bh = blockIdx.y;
    const int b = bh >> 4, hh = bh & 15;
    const int tid = threadIdx.x;
    const int w = tid >> 5, lane = tid & 31;
    const int grp = lane >> 2, qd = lane & 3;

    const int qbase = b * LL + qt * 64;
    const int qmin = seq_id[qbase];
    const int qmax = seq_id[qbase + 63];

    const uint32_t sb = (uint32_t)__cvta_generic_to_shared(smw);
    const uint32_t sQh = sb, sQl = sb + 64 * AW * 4;
    const uint32_t sKPh = sQl + 64 * AW * 4, sKPl = sKPh + 64 * AW * 4;
    const uint32_t sVTh = sKPl + 64 * AW * 4, sVTl = sVTh + 64 * AW * 4;

    // stage Q hi/lo via cp.async (issued once; waited with first tile)
    {
        const size_t qrow = ((size_t)bh * LL + qt * 64) * 32;
        #pragma unroll
        for (int i = 0; i < 4; i++) {
            int idx = tid + i * 128;
            int r = idx >> 3, c = idx & 7;
            cp16(sQh + (r * AW + c * 4) * 4, g_qh + qrow + r * 32 + c * 4);
        }
        #pragma unroll
        for (int i = 0; i < 4; i++) {
            int idx = tid + i * 128;
            int r = idx >> 3, c = idx & 7;
            cp16(sQl + (r * AW + c * 4) * 4, g_ql + qrow + r * 32 + c * 4);
        }
        cp_commit();
    }
    const int row0 = w * 16 + grp, row1 = row0 + 8;
    const int qs0 = seq_id[qbase + row0];
    const int qs1 = seq_id[qbase + row1];

    float m0 = -1e30f, m1 = -1e30f, l0s = 0.f, l1s = 0.f;
    float O[8][4];
    #pragma unroll
    for (int dt = 0; dt < 8; dt++)
        #pragma unroll
        for (int q = 0; q < 4; q++) O[dt][q] = 0.f;

    for (int kt = 0; kt < LL / 64; kt++) {
        const int kb = b * LL + kt * 64;
        if (seq_id[kb + 63] < qmin || seq_id[kb] > qmax) continue;  // exact no-op tile

        __syncthreads();   // prior-iteration smem reads complete
        // stage K hi/lo + V^T hi/lo via cp.async
        {
            const size_t krow = ((size_t)bh * LL + kt * 64) * 32;
            const size_t vbase = ((size_t)bh * 32 + kt) * 64 * 32;
            #pragma unroll
            for (int i = 0; i < 4; i++) {
                int idx = tid + i * 128;
                int r = idx >> 3, c = idx & 7;
                cp16(sKPh + (r * AW + c * 4) * 4, g_kh + krow + r * 32 + c * 4);
            }
            #pragma unroll
            for (int i = 0; i < 4; i++) {
                int idx = tid + i * 128;
                int r = idx >> 3, c = idx & 7;
                cp16(sKPl + (r * AW + c * 4) * 4, g_kl + krow + r * 32 + c * 4);
            }
            #pragma unroll
            for (int i = 0; i < 4; i++) {
                int idx = tid + i * 128;
                int r = idx >> 3, c = idx & 7;
                cp16(sVTh + (r * AW + c * 4) * 4, g_vth + vbase + r * 32 + c * 4);
            }
            #pragma unroll
            for (int i = 0; i < 4; i++) {
                int idx = tid + i * 128;
                int r = idx >> 3, c = idx & 7;
                cp16(sVTl + (r * AW + c * 4) * 4, g_vtl + vbase + r * 32 + c * 4);
            }
            cp_commit();
        }
        if (tid < 64) kseq[tid] = seq_id[kb + tid];
        cp_wait_all();
        __syncthreads();

        // ---- S = Q K^T (3-term split) ----
        float S[8][4];
        #pragma unroll
        for (int nt = 0; nt < 8; nt++)
            #pragma unroll
            for (int q = 0; q < 4; q++) S[nt][q] = 0.f;
        #pragma unroll
        for (int ks = 0; ks < 4; ks++) {
            int r0w = (w * 16 + grp) * AW, r1w = (w * 16 + grp + 8) * AW;
            int kw0 = ks * 8 + qd;
            uint32_t ah0 = Qh[r0w + kw0],     ah1 = Qh[r1w + kw0];
            uint32_t ah2 = Qh[r0w + kw0 + 4], ah3 = Qh[r1w + kw0 + 4];
            uint32_t al0 = Ql[r0w + kw0],     al1 = Ql[r1w + kw0];
            uint32_t al2 = Ql[r0w + kw0 + 4], al3 = Ql[r1w + kw0 + 4];
            #pragma unroll
            for (int nt = 0; nt < 8; nt++) {
                int nw = (nt * 8 + grp) * AW;
                uint32_t bh0 = KPh[nw + kw0], bh1 = KPh[nw + kw0 + 4];
                uint32_t bl0 = KPl[nw + kw0], bl1 = KPl[nw + kw0 + 4];
                mma16816(S[nt], ah0, ah1, ah2, ah3, bh0, bh1);
                mma16816(S[nt], ah0, ah1, ah2, ah3, bl0, bl1);
                mma16816(S[nt], al0, al1, al2, al3, bh0, bh1);
            }
        }

        // ---- mask ----
        #pragma unroll
        for (int nt = 0; nt < 8; nt++) {
            int c0 = kseq[nt * 8 + 2 * qd];
            int c1 = kseq[nt * 8 + 2 * qd + 1];
            if (c0 != qs0) S[nt][0] = -1e30f;
            if (c1 != qs0) S[nt][1] = -1e30f;
            if (c0 != qs1) S[nt][2] = -1e30f;
            if (c1 != qs1) S[nt][3] = -1e30f;
        }

        // ---- online softmax ----
        float mx0 = -1e30f, mx1 = -1e30f;
        #pragma unroll
        for (int nt = 0; nt < 8; nt++) {
            mx0 = fmaxf(mx0, fmaxf(S[nt][0], S[nt][1]));
            mx1 = fmaxf(mx1, fmaxf(S[nt][2], S[nt][3]));
        }
        mx0 = fmaxf(mx0, __shfl_xor_sync(0xffffffffu, mx0, 1));
        mx0 = fmaxf(mx0, __shfl_xor_sync(0xffffffffu, mx0, 2));
        mx1 = fmaxf(mx1, __shfl_xor_sync(0xffffffffu, mx1, 1));
        mx1 = fmaxf(mx1, __shfl_xor_sync(0xffffffffu, mx1, 2));
        float mn0 = fmaxf(m0, mx0), mn1 = fmaxf(m1, mx1);
        float sc0 = __expf(m0 - mn0), sc1 = __expf(m1 - mn1);
        m0 = mn0; m1 = mn1;
        float s0 = 0.f, s1 = 0.f;
        #pragma unroll
        for (int nt = 0; nt < 8; nt++) {
            S[nt][0] = __expf(S[nt][0] - mn0);
            S[nt][1] = __expf(S[nt][1] - mn0);
            S[nt][2] = __expf(S[nt][2] - mn1);
            S[nt][3] = __expf(S[nt][3] - mn1);
            s0 += S[nt][0] + S[nt][1];
            s1 += S[nt][2] + S[nt][3];
        }
        s0 += __shfl_xor_sync(0xffffffffu, s0, 1);
        s0 += __shfl_xor_sync(0xffffffffu, s0, 2);
        s1 += __shfl_xor_sync(0xffffffffu, s1, 1);
        s1 += __shfl_xor_sync(0xffffffffu, s1, 2);
        l0s = l0s * sc0 + s0;
        l1s = l1s * sc1 + s1;
        #pragma unroll
        for (int dt = 0; dt < 8; dt++) {
            O[dt][0] *= sc0; O[dt][1] *= sc0;
            O[dt][2] *= sc1; O[dt][3] *= sc1;
        }

        __syncthreads();   // all K fragment reads done before P overwrite
        #pragma unroll
        for (int nt = 0; nt < 8; nt++) {
            uint32_t h, l;
            bfsplit(S[nt][0], S[nt][1], h, l);
            KPh[(w * 16 + grp) * AW + nt * 4 + qd] = h;
            KPl[(w * 16 + grp) * AW + nt * 4 + qd] = l;
            bfsplit(S[nt][2], S[nt][3], h, l);
            KPh[(w * 16 + grp + 8) * AW + nt * 4 + qd] = h;
            KPl[(w * 16 + grp + 8) * AW + nt * 4 + qd] = l;
        }
        __syncthreads();

        // ---- O += P V (3-term split) ----
        #pragma unroll
        for (int ks = 0; ks < 4; ks++) {
            int r0w = (w * 16 + grp) * AW, r1w = (w * 16 + grp + 8) * AW;
            int kw0 = ks * 8 + qd;
            uint32_t ah0 = KPh[r0w + kw0],     ah1 = KPh[r1w + kw0];
            uint32_t ah2 = KPh[r0w + kw0 + 4], ah3 = KPh[r1w + kw0 + 4];
            uint32_t al0 = KPl[r0w + kw0],     al1 = KPl[r1w + kw0];
            uint32_t al2 = KPl[r0w + kw0 + 4], al3 = KPl[r1w + kw0 + 4];
            #pragma unroll
            for (int dt = 0; dt < 8; dt++) {
                int dw = (dt * 8 + grp) * AW;
                uint32_t bh0 = VTh[dw + kw0], bh1 = VTh[dw + kw0 + 4];
                uint32_t bl0 = VTl[dw + kw0], bl1 = VTl[dw + kw0 + 4];
                mma16816(O[dt], ah0, ah1, ah2, ah3, bh0, bh1);
                mma16816(O[dt], ah0, ah1, ah2, ah3, bl0, bl1);
                mma16816(O[dt], al0, al1, al2, al3, bh0, bh1);
            }
        }
    }

    // epilogue
    float inv0 = 1.0f / l0s, inv1 = 1.0f / l1s;
    const int t0 = b * LL + qt * 64 + row0;
    const int t1 = b * LL + qt * 64 + row1;
    #pragma unroll
    for (int dt = 0; dt < 8; dt++) {
        int c = hh * DHH + dt * 8 + 2 * qd;
        *(float2*)(g_ctx + (size_t)t0 * DD + c) =
            make_float2(O[dt][0] * inv0, O[dt][1] * inv0);
        *(float2*)(g_ctx + (size_t)t1 * DD + c) =
            make_float2(O[dt][2] * inv1, O[dt][3] * inv1);
    }
}

// ---------------- launch ----------------
extern "C" void kernel_launch(void* const* d_in, const int* in_sizes, int n_in,
                              void* d_out, int out_size) {
    const float* x     = (const float*)d_in[0];
    const int*   seq   = (const int*)  d_in[1];
    const float* ln1w  = (const float*)d_in[2];
    const float* ln1b  = (const float*)d_in[3];
    const float* wqkv  = (const float*)d_in[4];
    const float* qlnw  = (const float*)d_in[5];
    const float* klnw  = (const float*)d_in[6];
    const float* outw  = (const float*)d_in[7];
    float* out = (float*)d_out;

    void *ph, *pqkv, *pctx;
    cudaGetSymbolAddress(&ph, g_h);
    cudaGetSymbolAddress(&pqkv, g_qkv);
    cudaGetSymbolAddress(&pctx, g_ctx);

    cudaFuncSetAttribute(gemm_mma_tf32, cudaFuncAttributeMaxDynamicSharedMemorySize, GEMM_SMEM);
    cudaFuncSetAttribute(attn_kernel, cudaFuncAttributeMaxDynamicSharedMemorySize, ATTN_SMEM);

    // 1) LN1
    ln1_kernel<<<TT, 256>>>(x, ln1w, ln1b);

    // 2) QKV GEMM (tf32 mma.sync, 128x128 tile)
    gemm_mma_tf32<<<dim3(3 * DD / 128, TT / 128), 256, GEMM_SMEM>>>(
        (const float*)ph, wqkv, (float*)pqkv, 3 * DD);

    // 3) QK LN + RoPE -> pre-split planes; V row-major
    qk_rope_kernel<<<TT, 256>>>(qlnw, klnw);

    // 3b) V transpose + split
    vtrans_kernel<<<dim3(32, NBH), 128>>>();

    // 4) attention (tile-skip + cp.async staging + bf16-split3 mma)
    attn_kernel<<<dim3(LL / 64, NBH), 128, ATTN_SMEM>>>(seq);

    // 5) output projection
    gemm_mma_tf32<<<dim3(DD / 128, TT / 128), 256, GEMM_SMEM>>>(
        (const float*)pctx, outw, out, DD);
}

// round 8
// speedup vs baseline: 1.4855x; 1.0035x over previous
#include <cuda_runtime.h>
#include <cuda_bf16.h>
#include <cstdint>
#include <math.h>

// Problem constants
#define BB 2
#define LL 2048
#define DD 1024
#define HH 16
#define DHH 64
#define TT (BB*LL)          // 4096 tokens
#define EPS 1e-5f
#define NBH (BB*HH)         // 32

// -------- scratch (device globals: allocation-free rule) --------
__device__ float g_h[TT * DD];            // LN1 output
__device__ float g_qkv[TT * 3 * DD];      // QKV GEMM output
__device__ float g_v[TT * DD];            // [B,H,L,DH] v (row-major, float)
__device__ float g_ctx[TT * DD];          // attention output
__device__ float2 g_cs[LL * 32];          // RoPE cos/sin table [l][fi]
// pre-split bf16 planes, word = bf16x2 of adjacent head-dims: [bh][l][32 words]
__device__ __align__(16) uint32_t g_qh[NBH * LL * 32];
__device__ __align__(16) uint32_t g_ql[NBH * LL * 32];
__device__ __align__(16) uint32_t g_kh[NBH * LL * 32];
__device__ __align__(16) uint32_t g_kl[NBH * LL * 32];
// pre-split transposed V tiles: [bh][kt(32)][d(64)][32 l-pair words]
__device__ __align__(16) uint32_t g_vth[NBH * 32 * 64 * 32];
__device__ __align__(16) uint32_t g_vtl[NBH * 32 * 64 * 32];

__device__ __forceinline__ uint32_t f2tf32(float f) {
    uint32_t r; asm("cvt.rna.tf32.f32 %0, %1;" : "=r"(r) : "f"(f)); return r;
}

__device__ __forceinline__ void mma16n8k8(float* d, const uint32_t* a,
                                          uint32_t b0, uint32_t b1) {
    asm volatile(
        "mma.sync.aligned.m16n8k8.row.col.f32.tf32.tf32.f32 "
        "{%0,%1,%2,%3}, {%4,%5,%6,%7}, {%8,%9}, {%0,%1,%2,%3};"
        : "+f"(d[0]), "+f"(d[1]), "+f"(d[2]), "+f"(d[3])
        : "r"(a[0]), "r"(a[1]), "r"(a[2]), "r"(a[3]), "r"(b0), "r"(b1));
}

// bf16 helpers
__device__ __forceinline__ uint32_t bfpack(float a, float b) {
    __nv_bfloat162 t = __floats2bfloat162_rn(a, b);
    return *reinterpret_cast<uint32_t*>(&t);
}
__device__ __forceinline__ void bfsplit(float a, float b, uint32_t& hi, uint32_t& lo) {
    __nv_bfloat16 ha = __float2bfloat16_rn(a), hb = __float2bfloat16_rn(b);
    float ra = a - __bfloat162float(ha);
    float rb = b - __bfloat162float(hb);
    __nv_bfloat162 h; h.x = ha; h.y = hb;
    hi = *reinterpret_cast<uint32_t*>(&h);
    lo = bfpack(ra, rb);
}
__device__ __forceinline__ void mma16816(float* c, uint32_t a0, uint32_t a1,
                                         uint32_t a2, uint32_t a3,
                                         uint32_t b0, uint32_t b1) {
    asm volatile(
        "mma.sync.aligned.m16n8k16.row.col.f32.bf16.bf16.f32 "
        "{%0,%1,%2,%3}, {%4,%5,%6,%7}, {%8,%9}, {%0,%1,%2,%3};"
        : "+f"(c[0]), "+f"(c[1]), "+f"(c[2]), "+f"(c[3])
        : "r"(a0), "r"(a1), "r"(a2), "r"(a3), "r"(b0), "r"(b1));
}

__device__ __forceinline__ void cp16(uint32_t dst, const void* src) {
    asm volatile("cp.async.ca.shared.global [%0], [%1], 16;"
                 :: "r"(dst), "l"(src));
}
__device__ __forceinline__ void cp_commit() {
    asm volatile("cp.async.commit_group;");
}
__device__ __forceinline__ void cp_wait_all() {
    asm volatile("cp.async.wait_all;" ::: "memory");
}

// ===================== tf32 mma.sync GEMM (128x128, BK=32) ==========
#define GK 1024
#define BKc 32
#define NCHUNK (GK / BKc)    // 32
#define PADs 36
#define BUF_F (128 * PADs)
#define GEMM_SMEM (4 * BUF_F * 4)   // 73728 B

__global__ __launch_bounds__(256)
void gemm_mma_tf32(const float* __restrict__ A, const float* __restrict__ B,
                   float* __restrict__ C, int N) {
    extern __shared__ float sm[];
    float* As = sm;
    float* Bs = sm + 2 * BUF_F;

    const int tid = threadIdx.x;
    const int wid = tid >> 5, lane = tid & 31;
    const int grp = lane >> 2, qd = lane & 3;
    const int wm = wid >> 1, wn = wid & 1;
    const int m0 = blockIdx.y * 128;
    const int n0 = blockIdx.x * 128;

    float acc[2][8][4];
    #pragma unroll
    for (int i = 0; i < 2; i++)
        #pragma unroll
        for (int j = 0; j < 8; j++)
            #pragma unroll
            for (int q = 0; q < 4; q++) acc[i][j][q] = 0.f;

    float4 pa[4], pb[4];
    #pragma unroll
    for (int i = 0; i < 4; i++) {
        int u = tid + i * 256;
        int r = u >> 3, c4 = u & 7;
        pa[i] = *(const float4*)(A + (size_t)(m0 + r) * GK + c4 * 4);
        pb[i] = *(const float4*)(B + (size_t)(n0 + r) * GK + c4 * 4);
    }
    #pragma unroll
    for (int i = 0; i < 4; i++) {
        int u = tid + i * 256;
        int r = u >> 3, c4 = u & 7;
        float* pA = As + r * PADs + c4 * 4;
        pA[0] = __uint_as_float(f2tf32(pa[i].x));
        pA[1] = __uint_as_float(f2tf32(pa[i].y));
        pA[2] = __uint_as_float(f2tf32(pa[i].z));
        pA[3] = __uint_as_float(f2tf32(pa[i].w));
        float* pB = Bs + r * PADs + c4 * 4;
        pB[0] = __uint_as_float(f2tf32(pb[i].x));
        pB[1] = __uint_as_float(f2tf32(pb[i].y));
        pB[2] = __uint_as_float(f2tf32(pb[i].z));
        pB[3] = __uint_as_float(f2tf32(pb[i].w));
    }
    __syncthreads();

    for (int ic = 0; ic < NCHUNK; ic++) {
        if (ic + 1 < NCHUNK) {
            const float* An = A + (ic + 1) * BKc;
            const float* Bn = B + (ic + 1) * BKc;
            #pragma unroll
            for (int i = 0; i < 4; i++) {
                int u = tid + i * 256;
                int r = u >> 3, c4 = u & 7;
                pa[i] = *(const float4*)(An + (size_t)(m0 + r) * GK + c4 * 4);
                pb[i] = *(const float4*)(Bn + (size_t)(n0 + r) * GK + c4 * 4);
            }
        }

        const float* Ab = As + (ic & 1) * BUF_F;
        const float* Bb = Bs + (ic & 1) * BUF_F;
        #pragma unroll
        for (int ks = 0; ks < 4; ks++) {
            int kb = ks * 8;
            uint32_t af[2][4];
            #pragma unroll
            for (int mt = 0; mt < 2; mt++) {
                int r = wm * 32 + mt * 16 + grp;
                af[mt][0] = __float_as_uint(Ab[r * PADs + kb + qd]);
                af[mt][1] = __float_as_uint(Ab[(r + 8) * PADs + kb + qd]);
                af[mt][2] = __float_as_uint(Ab[r * PADs + kb + qd + 4]);
                af[mt][3] = __float_as_uint(Ab[(r + 8) * PADs + kb + qd + 4]);
            }
            #pragma unroll
            for (int nt = 0; nt < 8; nt++) {
                int c = wn * 64 + nt * 8 + grp;
                uint32_t b0 = __float_as_uint(Bb[c * PADs + kb + qd]);
                uint32_t b1 = __float_as_uint(Bb[c * PADs + kb + qd + 4]);
                mma16n8k8(acc[0][nt], af[0], b0, b1);
                mma16n8k8(acc[1][nt], af[1], b0, b1);
            }
        }

        if (ic + 1 < NCHUNK) {
            float* Ad = As + ((ic + 1) & 1) * BUF_F;
            float* Bd = Bs + ((ic + 1) & 1) * BUF_F;
            #pragma unroll
            for (int i = 0; i < 4; i++) {
                int u = tid + i * 256;
                int r = u >> 3, c4 = u & 7;
                float* pA = Ad + r * PADs + c4 * 4;
                pA[0] = __uint_as_float(f2tf32(pa[i].x));
                pA[1] = __uint_as_float(f2tf32(pa[i].y));
                pA[2] = __uint_as_float(f2tf32(pa[i].z));
                pA[3] = __uint_as_float(f2tf32(pa[i].w));
                float* pB = Bd + r * PADs + c4 * 4;
                pB[0] = __uint_as_float(f2tf32(pb[i].x));
                pB[1] = __uint_as_float(f2tf32(pb[i].y));
                pB[2] = __uint_as_float(f2tf32(pb[i].z));
                pB[3] = __uint_as_float(f2tf32(pb[i].w));
            }
            __syncthreads();
        }
    }

    #pragma unroll
    for (int mt = 0; mt < 2; mt++) {
        #pragma unroll
        for (int nt = 0; nt < 8; nt++) {
            int r = m0 + wm * 32 + mt * 16 + grp;
            int c = n0 + wn * 64 + nt * 8 + qd * 2;
            *(float2*)(C + (size_t)r * N + c) =
                make_float2(acc[mt][nt][0], acc[mt][nt][1]);
            *(float2*)(C + (size_t)(r + 8) * N + c) =
                make_float2(acc[mt][nt][2], acc[mt][nt][3]);
        }
    }
}

// ---------------- block reduction helper (256 threads) ----------------
__device__ __forceinline__ void block_reduce4(float& a, float& b, float& c, float& d) {
    #pragma unroll
    for (int o = 16; o; o >>= 1) {
        a += __shfl_xor_sync(0xffffffffu, a, o);
        b += __shfl_xor_sync(0xffffffffu, b, o);
        c += __shfl_xor_sync(0xffffffffu, c, o);
        d += __shfl_xor_sync(0xffffffffu, d, o);
    }
    __shared__ float s[4][8];
    int w = threadIdx.x >> 5, lane = threadIdx.x & 31;
    if (lane == 0) { s[0][w] = a; s[1][w] = b; s[2][w] = c; s[3][w] = d; }
    __syncthreads();
    a = b = c = d = 0.f;
    #pragma unroll
    for (int i = 0; i < 8; i++) { a += s[0][i]; b += s[1][i]; c += s[2][i]; d += s[3][i]; }
    __syncthreads();
}

// ---------------- kernel 0: RoPE cos/sin table ----------------
// identical float expressions to the previous in-loop computation -> bit-identical
__global__ void rope_table_kernel() {
    int idx = blockIdx.x * 256 + threadIdx.x;
    if (idx >= LL * 32) return;
    int l = idx >> 5, fi = idx & 31;
    float invf = powf(10000.0f, -((float)(2 * fi)) / 64.0f);
    float ang  = (float)l * invf;
    g_cs[idx] = make_float2(cosf(ang), sinf(ang));
}

// ---------------- kernel 1: LN1 ----------------
__global__ void ln1_kernel(const float* __restrict__ x,
                           const float* __restrict__ w,
                           const float* __restrict__ bia) {
    int t = blockIdx.x;
    int tid = threadIdx.x;
    const float4* xr = (const float4*)(x + (size_t)t * DD);
    float4 v = xr[tid];
    float s  = v.x + v.y + v.z + v.w;
    float ss = v.x*v.x + v.y*v.y + v.z*v.z + v.w*v.w;
    float z0 = 0.f, z1 = 0.f;
    block_reduce4(s, ss, z0, z1);
    float mu  = s * (1.0f / DD);
    float var = ss * (1.0f / DD) - mu * mu;
    float inv = rsqrtf(var + EPS);
    float4 wv = ((const float4*)w)[tid];
    float4 bv = ((const float4*)bia)[tid];
    float4 o;
    o.x = (v.x - mu) * inv * wv.x + bv.x;
    o.y = (v.y - mu) * inv * wv.y + bv.y;
    o.z = (v.z - mu) * inv * wv.z + bv.z;
    o.w = (v.w - mu) * inv * wv.w + bv.w;
    ((float4*)(g_h + (size_t)t * DD))[tid] = o;
}

// ---------------- kernel 3: QK LN + RoPE (table) + pre-split bf16 planes --------
__global__ void qk_rope_kernel(const float* __restrict__ qw,
                               const float* __restrict__ kw) {
    int t = blockIdx.x;
    int b = t >> 11;
    int l = t & 2047;
    int tid = threadIdx.x;
    const float4* row = (const float4*)(g_qkv + (size_t)t * 3 * DD);
    float4 q = row[tid];
    float4 k = row[256 + tid];
    float4 v = row[512 + tid];

    float qs  = q.x + q.y + q.z + q.w;
    float qss = q.x*q.x + q.y*q.y + q.z*q.z + q.w*q.w;
    float ks  = k.x + k.y + k.z + k.w;
    float kss = k.x*k.x + k.y*k.y + k.z*k.z + k.w*k.w;
    block_reduce4(qs, qss, ks, kss);
    float muq = qs * (1.0f / DD);
    float vq  = qss * (1.0f / DD) - muq * muq;
    float iq  = rsqrtf(vq + EPS);
    float muk = ks * (1.0f / DD);
    float vk  = kss * (1.0f / DD) - muk * muk;
    float ik  = rsqrtf(vk + EPS);

    __shared__ float qn[DD];
    __shared__ float kn[DD];
    float4 qwv = ((const float4*)qw)[tid];
    float4 kwv = ((const float4*)kw)[tid];
    int d0 = tid * 4;
    qn[d0+0] = (q.x - muq) * iq * qwv.x;
    qn[d0+1] = (q.y - muq) * iq * qwv.y;
    qn[d0+2] = (q.z - muq) * iq * qwv.z;
    qn[d0+3] = (q.w - muq) * iq * qwv.w;
    kn[d0+0] = (k.x - muk) * ik * kwv.x;
    kn[d0+1] = (k.y - muk) * ik * kwv.y;
    kn[d0+2] = (k.z - muk) * ik * kwv.z;
    kn[d0+3] = (k.w - muk) * ik * kwv.w;
    __syncthreads();

    int h   = d0 >> 6;
    int dh0 = d0 & 63;
    float oq[4], ok[4];
    #pragma unroll
    for (int j = 0; j < 4; j++) {
        int dh = dh0 + j;
        int fi = dh & 31;
        float2 cs = g_cs[l * 32 + fi];
        float c = cs.x, s = cs.y;
        float qv = qn[d0 + j];
        float kv = kn[d0 + j];
        float qp = (dh < 32) ? -qn[d0 + j + 32] : qn[d0 + j - 32];
        float kp = (dh < 32) ? -kn[d0 + j + 32] : kn[d0 + j - 32];
        oq[j] = (qv * c + qp * s) * 0.125f;   // fold 1/sqrt(DH) exactly
        ok[j] = kv * c + kp * s;
    }
    size_t pb = ((size_t)(b * HH + h) * LL + l) * 32 + (dh0 >> 1);
    uint32_t h0, l0, h1, l1;
    bfsplit(oq[0], oq[1], h0, l0);
    bfsplit(oq[2], oq[3], h1, l1);
    g_qh[pb] = h0; g_qh[pb + 1] = h1;
    g_ql[pb] = l0; g_ql[pb + 1] = l1;
    bfsplit(ok[0], ok[1], h0, l0);
    bfsplit(ok[2], ok[3], h1, l1);
    g_kh[pb] = h0; g_kh[pb + 1] = h1;
    g_kl[pb] = l0; g_kl[pb + 1] = l1;

    size_t oidx = (((size_t)(b * HH + h) * LL + l) * DHH + dh0);
    *(float4*)(g_v + oidx) = v;
}

// ---------------- kernel 3b: V transpose + split into tile planes ----------------
__global__ void vtrans_kernel() {
    __shared__ float vs[64 * 65];   // [l][d], pad 65
    const int kt = blockIdx.x, bh = blockIdx.y;
    const int tid = threadIdx.x;
    const float4* Vg = (const float4*)(g_v + ((size_t)bh * LL + kt * 64) * DHH);
    #pragma unroll
    for (int i = 0; i < 8; i++) {
        int idx = tid + i * 128;
        int l = idx >> 4, c4 = idx & 15;
        float4 v = Vg[l * 16 + c4];
        vs[l * 65 + c4 * 4 + 0] = v.x;
        vs[l * 65 + c4 * 4 + 1] = v.y;
        vs[l * 65 + c4 * 4 + 2] = v.z;
        vs[l * 65 + c4 * 4 + 3] = v.w;
    }
    __syncthreads();
    size_t base = ((size_t)bh * 32 + kt) * 64 * 32;
    #pragma unroll
    for (int i = 0; i < 16; i++) {
        int idx = tid + i * 128;
        int d = idx >> 5, lp = idx & 31;
        float a = vs[(2 * lp) * 65 + d];
        float b = vs[(2 * lp + 1) * 65 + d];
        uint32_t h, l;
        bfsplit(a, b, h, l);
        g_vth[base + d * 32 + lp] = h;
        g_vtl[base + d * 32 + lp] = l;
    }
}

// ---------------- kernel 4: flash attention, cp.async staged pre-split planes ----
#define AW 36
#define ATTN_SMEM (6 * 64 * AW * 4)   // 55296 B

__global__ __launch_bounds__(128, 4)
void attn_kernel(const int* __restrict__ seq_id) {
    extern __shared__ uint32_t smw[];
    uint32_t* Qh  = smw;                // [64][AW]
    uint32_t* Ql  = Qh  + 64 * AW;
    uint32_t* KPh = Ql  + 64 * AW;      // K (then P) hi
    uint32_t* KPl = KPh + 64 * AW;
    uint32_t* VTh = KPl + 64 * AW;      // V^T hi
    uint32_t* VTl = VTh + 64 * AW;
    __shared__ int kseq[64];

    const int qt = blockIdx.x, bh = blockIdx.y;
    const int b = bh >> 4, hh = bh & 15;
    const int tid = threadIdx.x;
    const int w = tid >> 5, lane = tid & 31;
    const int grp = lane >> 2, qd = lane & 3;

    const int qbase = b * LL + qt * 64;
    const int qmin = seq_id[qbase];
    const int qmax = seq_id[qbase + 63];

    const uint32_t sb = (uint32_t)__cvta_generic_to_shared(smw);
    const uint32_t sQh = sb, sQl = sb + 64 * AW * 4;
    const uint32_t sKPh = sQl + 64 * AW * 4, sKPl = sKPh + 64 * AW * 4;
    const uint32_t sVTh = sKPl + 64 * AW * 4, sVTl = sVTh + 64 * AW * 4;

    // stage Q hi/lo via cp.async
    {
        const size_t qrow = ((size_t)bh * LL + qt * 64) * 32;
        #pragma unroll
        for (int i = 0; i < 4; i++) {
            int idx = tid + i * 128;
            int r = idx >> 3, c = idx & 7;
            cp16(sQh + (r * AW + c * 4) * 4, g_qh + qrow + r * 32 + c * 4);
        }
        #pragma unroll
        for (int i = 0; i < 4; i++) {
            int idx = tid + i * 128;
            int r = idx >> 3, c = idx & 7;
            cp16(sQl + (r * AW + c * 4) * 4, g_ql + qrow + r * 32 + c * 4);
        }
        cp_commit();
    }
    const int row0 = w * 16 + grp, row1 = row0 + 8;
    const int qs0 = seq_id[qbase + row0];
    const int qs1 = seq_id[qbase + row1];

    float m0 = -1e30f, m1 = -1e30f, l0s = 0.f, l1s = 0.f;
    float O[8][4];
    #pragma unroll
    for (int dt = 0; dt < 8; dt++)
        #pragma unroll
        for (int q = 0; q < 4; q++) O[dt][q] = 0.f;

    for (int kt = 0; kt < LL / 64; kt++) {
        const int kb = b * LL + kt * 64;
        if (seq_id[kb + 63] < qmin || seq_id[kb] > qmax) continue;  // exact no-op tile

        __syncthreads();   // prior-iteration smem reads complete
        // stage K hi/lo + V^T hi/lo via cp.async
        {
            const size_t krow = ((size_t)bh * LL + kt * 64) * 32;
            const size_t vbase = ((size_t)bh * 32 + kt) * 64 * 32;
            #pragma unroll
            for (int i = 0; i < 4; i++) {
                int idx = tid + i * 128;
                int r = idx >> 3, c = idx & 7;
                cp16(sKPh + (r * AW + c * 4) * 4, g_kh + krow + r * 32 + c * 4);
            }
            #pragma unroll
            for (int i = 0; i < 4; i++) {
                int idx = tid + i * 128;
                int r = idx >> 3, c = idx & 7;
                cp16(sKPl + (r * AW + c * 4) * 4, g_kl + krow + r * 32 + c * 4);
            }
            #pragma unroll
            for (int i = 0; i < 4; i++) {
                int idx = tid + i * 128;
                int r = idx >> 3, c = idx & 7;
                cp16(sVTh + (r * AW + c * 4) * 4, g_vth + vbase + r * 32 + c * 4);
            }
            #pragma unroll
            for (int i = 0; i < 4; i++) {
                int idx = tid + i * 128;
                int r = idx >> 3, c = idx & 7;
                cp16(sVTl + (r * AW + c * 4) * 4, g_vtl + vbase + r * 32 + c * 4);
            }
            cp_commit();
        }
        if (tid < 64) kseq[tid] = seq_id[kb + tid];
        cp_wait_all();
        __syncthreads();

        // ---- S = Q K^T (3-term split) ----
        float S[8][4];
        #pragma unroll
        for (int nt = 0; nt < 8; nt++)
            #pragma unroll
            for (int q = 0; q < 4; q++) S[nt][q] = 0.f;
        #pragma unroll
        for (int ks = 0; ks < 4; ks++) {
            int r0w = (w * 16 + grp) * AW, r1w = (w * 16 + grp + 8) * AW;
            int kw0 = ks * 8 + qd;
            uint32_t ah0 = Qh[r0w + kw0],     ah1 = Qh[r1w + kw0];
            uint32_t ah2 = Qh[r0w + kw0 + 4], ah3 = Qh[r1w + kw0 + 4];
            uint32_t al0 = Ql[r0w + kw0],     al1 = Ql[r1w + kw0];
            uint32_t al2 = Ql[r0w + kw0 + 4], al3 = Ql[r1w + kw0 + 4];
            #pragma unroll
            for (int nt = 0; nt < 8; nt++) {
                int nw = (nt * 8 + grp) * AW;
                uint32_t bh0 = KPh[nw + kw0], bh1 = KPh[nw + kw0 + 4];
                uint32_t bl0 = KPl[nw + kw0], bl1 = KPl[nw + kw0 + 4];
                mma16816(S[nt], ah0, ah1, ah2, ah3, bh0, bh1);
                mma16816(S[nt], ah0, ah1, ah2, ah3, bl0, bl1);
                mma16816(S[nt], al0, al1, al2, al3, bh0, bh1);
            }
        }

        // ---- mask ----
        #pragma unroll
        for (int nt = 0; nt < 8; nt++) {
            int c0 = kseq[nt * 8 + 2 * qd];
            int c1 = kseq[nt * 8 + 2 * qd + 1];
            if (c0 != qs0) S[nt][0] = -1e30f;
            if (c1 != qs0) S[nt][1] = -1e30f;
            if (c0 != qs1) S[nt][2] = -1e30f;
            if (c1 != qs1) S[nt][3] = -1e30f;
        }

        // ---- online softmax ----
        float mx0 = -1e30f, mx1 = -1e30f;
        #pragma unroll
        for (int nt = 0; nt < 8; nt++) {
            mx0 = fmaxf(mx0, fmaxf(S[nt][0], S[nt][1]));
            mx1 = fmaxf(mx1, fmaxf(S[nt][2], S[nt][3]));
        }
        mx0 = fmaxf(mx0, __shfl_xor_sync(0xffffffffu, mx0, 1));
        mx0 = fmaxf(mx0, __shfl_xor_sync(0xffffffffu, mx0, 2));
        mx1 = fmaxf(mx1, __shfl_xor_sync(0xffffffffu, mx1, 1));
        mx1 = fmaxf(mx1, __shfl_xor_sync(0xffffffffu, mx1, 2));
        float mn0 = fmaxf(m0, mx0), mn1 = fmaxf(m1, mx1);
        float sc0 = __expf(m0 - mn0), sc1 = __expf(m1 - mn1);
        m0 = mn0; m1 = mn1;
        float s0 = 0.f, s1 = 0.f;
        #pragma unroll
        for (int nt = 0; nt < 8; nt++) {
            S[nt][0] = __expf(S[nt][0] - mn0);
            S[nt][1] = __expf(S[nt][1] - mn0);
            S[nt][2] = __expf(S[nt][2] - mn1);
            S[nt][3] = __expf(S[nt][3] - mn1);
            s0 += S[nt][0] + S[nt][1];
            s1 += S[nt][2] + S[nt][3];
        }
        s0 += __shfl_xor_sync(0xffffffffu, s0, 1);
        s0 += __shfl_xor_sync(0xffffffffu, s0, 2);
        s1 += __shfl_xor_sync(0xffffffffu, s1, 1);
        s1 += __shfl_xor_sync(0xffffffffu, s1, 2);
        l0s = l0s * sc0 + s0;
        l1s = l1s * sc1 + s1;
        #pragma unroll
        for (int dt = 0; dt < 8; dt++) {
            O[dt][0] *= sc0; O[dt][1] *= sc0;
            O[dt][2] *= sc1; O[dt][3] *= sc1;
        }

        __syncthreads();   // all K fragment reads done before P overwrite
        #pragma unroll
        for (int nt = 0; nt < 8; nt++) {
            uint32_t h, l;
            bfsplit(S[nt][0], S[nt][1], h, l);
            KPh[(w * 16 + grp) * AW + nt * 4 + qd] = h;
            KPl[(w * 16 + grp) * AW + nt * 4 + qd] = l;
            bfsplit(S[nt][2], S[nt][3], h, l);
            KPh[(w * 16 + grp + 8) * AW + nt * 4 + qd] = h;
            KPl[(w * 16 + grp + 8) * AW + nt * 4 + qd] = l;
        }
        __syncthreads();

        // ---- O += P V (3-term split) ----
        #pragma unroll
        for (int ks = 0; ks < 4; ks++) {
            int r0w = (w * 16 + grp) * AW, r1w = (w * 16 + grp + 8) * AW;
            int kw0 = ks * 8 + qd;
            uint32_t ah0 = KPh[r0w + kw0],     ah1 = KPh[r1w + kw0];
            uint32_t ah2 = KPh[r0w + kw0 + 4], ah3 = KPh[r1w + kw0 + 4];
            uint32_t al0 = KPl[r0w + kw0],     al1 = KPl[r1w + kw0];
            uint32_t al2 = KPl[r0w + kw0 + 4], al3 = KPl[r1w + kw0 + 4];
            #pragma unroll
            for (int dt = 0; dt < 8; dt++) {
                int dw = (dt * 8 + grp) * AW;
                uint32_t bh0 = VTh[dw + kw0], bh1 = VTh[dw + kw0 + 4];
                uint32_t bl0 = VTl[dw + kw0], bl1 = VTl[dw + kw0 + 4];
                mma16816(O[dt], ah0, ah1, ah2, ah3, bh0, bh1);
                mma16816(O[dt], ah0, ah1, ah2, ah3, bl0, bl1);
                mma16816(O[dt], al0, al1, al2, al3, bh0, bh1);
            }
        }
    }

    // epilogue
    float inv0 = 1.0f / l0s, inv1 = 1.0f / l1s;
    const int t0 = b * LL + qt * 64 + row0;
    const int t1 = b * LL + qt * 64 + row1;
    #pragma unroll
    for (int dt = 0; dt < 8; dt++) {
        int c = hh * DHH + dt * 8 + 2 * qd;
        *(float2*)(g_ctx + (size_t)t0 * DD + c) =
            make_float2(O[dt][0] * inv0, O[dt][1] * inv0);
        *(float2*)(g_ctx + (size_t)t1 * DD + c) =
            make_float2(O[dt][2] * inv1, O[dt][3] * inv1);
    }
}

// ---------------- launch ----------------
extern "C" void kernel_launch(void* const* d_in, const int* in_sizes, int n_in,
                              void* d_out, int out_size) {
    const float* x     = (const float*)d_in[0];
    const int*   seq   = (const int*)  d_in[1];
    const float* ln1w  = (const float*)d_in[2];
    const float* ln1b  = (const float*)d_in[3];
    const float* wqkv  = (const float*)d_in[4];
    const float* qlnw  = (const float*)d_in[5];
    const float* klnw  = (const float*)d_in[6];
    const float* outw  = (const float*)d_in[7];
    float* out = (float*)d_out;

    void *ph, *pqkv, *pctx;
    cudaGetSymbolAddress(&ph, g_h);
    cudaGetSymbolAddress(&pqkv, g_qkv);
    cudaGetSymbolAddress(&pctx, g_ctx);

    cudaFuncSetAttribute(gemm_mma_tf32, cudaFuncAttributeMaxDynamicSharedMemorySize, GEMM_SMEM);
    cudaFuncSetAttribute(attn_kernel, cudaFuncAttributeMaxDynamicSharedMemorySize, ATTN_SMEM);

    // 0) RoPE table (overlaps serial chain start; tiny)
    rope_table_kernel<<<(LL * 32 + 255) / 256, 256>>>();

    // 1) LN1
    ln1_kernel<<<TT, 256>>>(x, ln1w, ln1b);

    // 2) QKV GEMM (tf32 mma.sync, 128x128 tile)
    gemm_mma_tf32<<<dim3(3 * DD / 128, TT / 128), 256, GEMM_SMEM>>>(
        (const float*)ph, wqkv, (float*)pqkv, 3 * DD);

    // 3) QK LN + RoPE (table) -> pre-split planes; V row-major
    qk_rope_kernel<<<TT, 256>>>(qlnw, klnw);

    // 3b) V transpose + split
    vtrans_kernel<<<dim3(32, NBH), 128>>>();

    // 4) attention (tile-skip + cp.async staging + bf16-split3 mma)
    attn_kernel<<<dim3(LL / 64, NBH), 128, ATTN_SMEM>>>(seq);

    // 5) output projection
    gemm_mma_tf32<<<dim3(DD / 128, TT / 128), 256, GEMM_SMEM>>>(
        (const float*)pctx, outw, out, DD);
}

// round 9
// speedup vs baseline: 1.9146x; 1.2888x over previous
#include <cuda_runtime.h>
#include <cuda_bf16.h>
#include <cuda_fp16.h>
#include <cstdint>
#include <math.h>

// Problem constants
#define BB 2
#define LL 2048
#define DD 1024
#define HH 16
#define DHH 64
#define TT (BB*LL)          // 4096 tokens
#define EPS 1e-5f
#define NBH (BB*HH)         // 32

// -------- scratch (device globals: allocation-free rule) --------
__device__ float g_h[TT * DD];            // LN1 output
__device__ float g_qkv[TT * 3 * DD];      // QKV GEMM output
__device__ float g_v[TT * DD];            // [B,H,L,DH] v (row-major, float)
__device__ float g_ctx[TT * DD];          // attention output
__device__ float2 g_cs[LL * 32];          // RoPE cos/sin table [l][fi]
// pre-split bf16 planes, word = bf16x2 of adjacent head-dims: [bh][l][32 words]
__device__ __align__(16) uint32_t g_qh[NBH * LL * 32];
__device__ __align__(16) uint32_t g_ql[NBH * LL * 32];
__device__ __align__(16) uint32_t g_kh[NBH * LL * 32];
__device__ __align__(16) uint32_t g_kl[NBH * LL * 32];
// pre-split transposed V tiles: [bh][kt(32)][d(64)][32 l-pair words]
__device__ __align__(16) uint32_t g_vth[NBH * 32 * 64 * 32];
__device__ __align__(16) uint32_t g_vtl[NBH * 32 * 64 * 32];

// bf16 helpers (attention)
__device__ __forceinline__ uint32_t bfpack(float a, float b) {
    __nv_bfloat162 t = __floats2bfloat162_rn(a, b);
    return *reinterpret_cast<uint32_t*>(&t);
}
__device__ __forceinline__ void bfsplit(float a, float b, uint32_t& hi, uint32_t& lo) {
    __nv_bfloat16 ha = __float2bfloat16_rn(a), hb = __float2bfloat16_rn(b);
    float ra = a - __bfloat162float(ha);
    float rb = b - __bfloat162float(hb);
    __nv_bfloat162 h; h.x = ha; h.y = hb;
    hi = *reinterpret_cast<uint32_t*>(&h);
    lo = bfpack(ra, rb);
}
__device__ __forceinline__ uint32_t h2pack(float a, float b) {
    __half2 t = __floats2half2_rn(a, b);
    return *reinterpret_cast<uint32_t*>(&t);
}
// bf16 m16n8k16 (attention)
__device__ __forceinline__ void mma16816(float* c, uint32_t a0, uint32_t a1,
                                         uint32_t a2, uint32_t a3,
                                         uint32_t b0, uint32_t b1) {
    asm volatile(
        "mma.sync.aligned.m16n8k16.row.col.f32.bf16.bf16.f32 "
        "{%0,%1,%2,%3}, {%4,%5,%6,%7}, {%8,%9}, {%0,%1,%2,%3};"
        : "+f"(c[0]), "+f"(c[1]), "+f"(c[2]), "+f"(c[3])
        : "r"(a0), "r"(a1), "r"(a2), "r"(a3), "r"(b0), "r"(b1));
}
// fp16 m16n8k16 (projection GEMMs; fp16 mantissa == tf32 mantissa, 2x K rate)
__device__ __forceinline__ void mma16816h(float* c, uint32_t a0, uint32_t a1,
                                          uint32_t a2, uint32_t a3,
                                          uint32_t b0, uint32_t b1) {
    asm volatile(
        "mma.sync.aligned.m16n8k16.row.col.f32.f16.f16.f32 "
        "{%0,%1,%2,%3}, {%4,%5,%6,%7}, {%8,%9}, {%0,%1,%2,%3};"
        : "+f"(c[0]), "+f"(c[1]), "+f"(c[2]), "+f"(c[3])
        : "r"(a0), "r"(a1), "r"(a2), "r"(a3), "r"(b0), "r"(b1));
}

__device__ __forceinline__ void cp16(uint32_t dst, const void* src) {
    asm volatile("cp.async.ca.shared.global [%0], [%1], 16;"
                 :: "r"(dst), "l"(src));
}
__device__ __forceinline__ void cp_commit() {
    asm volatile("cp.async.commit_group;");
}
__device__ __forceinline__ void cp_wait_all() {
    asm volatile("cp.async.wait_all;" ::: "memory");
}

// ===================== fp16 mma.sync GEMM (128x128, BK=32) ==========
// C[M,N] = A[M,1024] * B[N,1024]^T. Operands rounded to fp16 (2^-11 rel, same
// as tf32) packed as half2-per-k-pair words; fp32 accumulate.
#define GK 1024
#define BKc 32
#define NCHUNK (GK / BKc)    // 32
#define PADh 20              // 16 k-pair words + 4 pad (stride%32=20 -> all banks)
#define BUFW (128 * PADh)
#define GEMM_SMEM (4 * BUFW * 4)   // 40960 B

__global__ __launch_bounds__(256)
void gemm_mma_fp16(const float* __restrict__ A, const float* __restrict__ B,
                   float* __restrict__ C, int N) {
    extern __shared__ uint32_t smg[];
    uint32_t* As = smg;              // [2][128][PADh]
    uint32_t* Bs = smg + 2 * BUFW;

    const int tid = threadIdx.x;
    const int wid = tid >> 5, lane = tid & 31;
    const int grp = lane >> 2, qd = lane & 3;
    const int wm = wid >> 1, wn = wid & 1;   // 4 m-warps x 2 n-warps, 32x64 tile
    const int m0 = blockIdx.y * 128;
    const int n0 = blockIdx.x * 128;

    float acc[2][8][4];
    #pragma unroll
    for (int i = 0; i < 2; i++)
        #pragma unroll
        for (int j = 0; j < 8; j++)
            #pragma unroll
            for (int q = 0; q < 4; q++) acc[i][j][q] = 0.f;

    float4 pa[4], pb[4];
    #pragma unroll
    for (int i = 0; i < 4; i++) {
        int u = tid + i * 256;
        int r = u >> 3, c4 = u & 7;
        pa[i] = *(const float4*)(A + (size_t)(m0 + r) * GK + c4 * 4);
        pb[i] = *(const float4*)(B + (size_t)(n0 + r) * GK + c4 * 4);
    }
    #pragma unroll
    for (int i = 0; i < 4; i++) {
        int u = tid + i * 256;
        int r = u >> 3, c4 = u & 7;
        *(uint2*)&As[r * PADh + c4 * 2] =
            make_uint2(h2pack(pa[i].x, pa[i].y), h2pack(pa[i].z, pa[i].w));
        *(uint2*)&Bs[r * PADh + c4 * 2] =
            make_uint2(h2pack(pb[i].x, pb[i].y), h2pack(pb[i].z, pb[i].w));
    }
    __syncthreads();

    for (int ic = 0; ic < NCHUNK; ic++) {
        if (ic + 1 < NCHUNK) {
            const float* An = A + (ic + 1) * BKc;
            const float* Bn = B + (ic + 1) * BKc;
            #pragma unroll
            for (int i = 0; i < 4; i++) {
                int u = tid + i * 256;
                int r = u >> 3, c4 = u & 7;
                pa[i] = *(const float4*)(An + (size_t)(m0 + r) * GK + c4 * 4);
                pb[i] = *(const float4*)(Bn + (size_t)(n0 + r) * GK + c4 * 4);
            }
        }

        const uint32_t* Ab = As + (ic & 1) * BUFW;
        const uint32_t* Bb = Bs + (ic & 1) * BUFW;
        #pragma unroll
        for (int ks = 0; ks < 2; ks++) {       // two k16 steps cover BK=32
            int kw = ks * 8 + qd;
            uint32_t af[2][4];
            #pragma unroll
            for (int mt = 0; mt < 2; mt++) {
                int r = wm * 32 + mt * 16 + grp;
                af[mt][0] = Ab[r * PADh + kw];
                af[mt][1] = Ab[(r + 8) * PADh + kw];
                af[mt][2] = Ab[r * PADh + kw + 4];
                af[mt][3] = Ab[(r + 8) * PADh + kw + 4];
            }
            #pragma unroll
            for (int nt = 0; nt < 8; nt++) {
                int c = wn * 64 + nt * 8 + grp;
                uint32_t b0 = Bb[c * PADh + kw];
                uint32_t b1 = Bb[c * PADh + kw + 4];
                mma16816h(acc[0][nt], af[0][0], af[0][1], af[0][2], af[0][3], b0, b1);
                mma16816h(acc[1][nt], af[1][0], af[1][1], af[1][2], af[1][3], b0, b1);
            }
        }

        if (ic + 1 < NCHUNK) {
            uint32_t* Ad = As + ((ic + 1) & 1) * BUFW;
            uint32_t* Bd = Bs + ((ic + 1) & 1) * BUFW;
            #pragma unroll
            for (int i = 0; i < 4; i++) {
                int u = tid + i * 256;
                int r = u >> 3, c4 = u & 7;
                *(uint2*)&Ad[r * PADh + c4 * 2] =
                    make_uint2(h2pack(pa[i].x, pa[i].y), h2pack(pa[i].z, pa[i].w));
                *(uint2*)&Bd[r * PADh + c4 * 2] =
                    make_uint2(h2pack(pb[i].x, pb[i].y), h2pack(pb[i].z, pb[i].w));
            }
            __syncthreads();
        }
    }

    #pragma unroll
    for (int mt = 0; mt < 2; mt++) {
        #pragma unroll
        for (int nt = 0; nt < 8; nt++) {
            int r = m0 + wm * 32 + mt * 16 + grp;
            int c = n0 + wn * 64 + nt * 8 + qd * 2;
            *(float2*)(C + (size_t)r * N + c) =
                make_float2(acc[mt][nt][0], acc[mt][nt][1]);
            *(float2*)(C + (size_t)(r + 8) * N + c) =
                make_float2(acc[mt][nt][2], acc[mt][nt][3]);
        }
    }
}

// ---------------- block reduction helper (256 threads) ----------------
__device__ __forceinline__ void block_reduce4(float& a, float& b, float& c, float& d) {
    #pragma unroll
    for (int o = 16; o; o >>= 1) {
        a += __shfl_xor_sync(0xffffffffu, a, o);
        b += __shfl_xor_sync(0xffffffffu, b, o);
        c += __shfl_xor_sync(0xffffffffu, c, o);
        d += __shfl_xor_sync(0xffffffffu, d, o);
    }
    __shared__ float s[4][8];
    int w = threadIdx.x >> 5, lane = threadIdx.x & 31;
    if (lane == 0) { s[0][w] = a; s[1][w] = b; s[2][w] = c; s[3][w] = d; }
    __syncthreads();
    a = b = c = d = 0.f;
    #pragma unroll
    for (int i = 0; i < 8; i++) { a += s[0][i]; b += s[1][i]; c += s[2][i]; d += s[3][i]; }
    __syncthreads();
}

// ---------------- kernel 0: RoPE cos/sin table ----------------
__global__ void rope_table_kernel() {
    int idx = blockIdx.x * 256 + threadIdx.x;
    if (idx >= LL * 32) return;
    int l = idx >> 5, fi = idx & 31;
    float invf = powf(10000.0f, -((float)(2 * fi)) / 64.0f);
    float ang  = (float)l * invf;
    g_cs[idx] = make_float2(cosf(ang), sinf(ang));
}

// ---------------- kernel 1: LN1 ----------------
__global__ void ln1_kernel(const float* __restrict__ x,
                           const float* __restrict__ w,
                           const float* __restrict__ bia) {
    int t = blockIdx.x;
    int tid = threadIdx.x;
    const float4* xr = (const float4*)(x + (size_t)t * DD);
    float4 v = xr[tid];
    float s  = v.x + v.y + v.z + v.w;
    float ss = v.x*v.x + v.y*v.y + v.z*v.z + v.w*v.w;
    float z0 = 0.f, z1 = 0.f;
    block_reduce4(s, ss, z0, z1);
    float mu  = s * (1.0f / DD);
    float var = ss * (1.0f / DD) - mu * mu;
    float inv = rsqrtf(var + EPS);
    float4 wv = ((const float4*)w)[tid];
    float4 bv = ((const float4*)bia)[tid];
    float4 o;
    o.x = (v.x - mu) * inv * wv.x + bv.x;
    o.y = (v.y - mu) * inv * wv.y + bv.y;
    o.z = (v.z - mu) * inv * wv.z + bv.z;
    o.w = (v.w - mu) * inv * wv.w + bv.w;
    ((float4*)(g_h + (size_t)t * DD))[tid] = o;
}

// ---------------- kernel 3: QK LN + RoPE (table) + pre-split bf16 planes --------
__global__ void qk_rope_kernel(const float* __restrict__ qw,
                               const float* __restrict__ kw) {
    int t = blockIdx.x;
    int b = t >> 11;
    int l = t & 2047;
    int tid = threadIdx.x;
    const float4* row = (const float4*)(g_qkv + (size_t)t * 3 * DD);
    float4 q = row[tid];
    float4 k = row[256 + tid];
    float4 v = row[512 + tid];

    float qs  = q.x + q.y + q.z + q.w;
    float qss = q.x*q.x + q.y*q.y + q.z*q.z + q.w*q.w;
    float ks  = k.x + k.y + k.z + k.w;
    float kss = k.x*k.x + k.y*k.y + k.z*k.z + k.w*k.w;
    block_reduce4(qs, qss, ks, kss);
    float muq = qs * (1.0f / DD);
    float vq  = qss * (1.0f / DD) - muq * muq;
    float iq  = rsqrtf(vq + EPS);
    float muk = ks * (1.0f / DD);
    float vk  = kss * (1.0f / DD) - muk * muk;
    float ik  = rsqrtf(vk + EPS);

    __shared__ float qn[DD];
    __shared__ float kn[DD];
    float4 qwv = ((const float4*)qw)[tid];
    float4 kwv = ((const float4*)kw)[tid];
    int d0 = tid * 4;
    qn[d0+0] = (q.x - muq) * iq * qwv.x;
    qn[d0+1] = (q.y - muq) * iq * qwv.y;
    qn[d0+2] = (q.z - muq) * iq * qwv.z;
    qn[d0+3] = (q.w - muq) * iq * qwv.w;
    kn[d0+0] = (k.x - muk) * ik * kwv.x;
    kn[d0+1] = (k.y - muk) * ik * kwv.y;
    kn[d0+2] = (k.z - muk) * ik * kwv.z;
    kn[d0+3] = (k.w - muk) * ik * kwv.w;
    __syncthreads();

    int h   = d0 >> 6;
    int dh0 = d0 & 63;
    float oq[4], ok[4];
    #pragma unroll
    for (int j = 0; j < 4; j++) {
        int dh = dh0 + j;
        int fi = dh & 31;
        float2 cs = g_cs[l * 32 + fi];
        float c = cs.x, s = cs.y;
        float qv = qn[d0 + j];
        float kv = kn[d0 + j];
        float qp = (dh < 32) ? -qn[d0 + j + 32] : qn[d0 + j - 32];
        float kp = (dh < 32) ? -kn[d0 + j + 32] : kn[d0 + j - 32];
        oq[j] = (qv * c + qp * s) * 0.125f;   // fold 1/sqrt(DH) exactly
        ok[j] = kv * c + kp * s;
    }
    size_t pb = ((size_t)(b * HH + h) * LL + l) * 32 + (dh0 >> 1);
    uint32_t h0, l0, h1, l1;
    bfsplit(oq[0], oq[1], h0, l0);
    bfsplit(oq[2], oq[3], h1, l1);
    g_qh[pb] = h0; g_qh[pb + 1] = h1;
    g_ql[pb] = l0; g_ql[pb + 1] = l1;
    bfsplit(ok[0], ok[1], h0, l0);
    bfsplit(ok[2], ok[3], h1, l1);
    g_kh[pb] = h0; g_kh[pb + 1] = h1;
    g_kl[pb] = l0; g_kl[pb + 1] = l1;

    size_t oidx = (((size_t)(b * HH + h) * LL + l) * DHH + dh0);
    *(float4*)(g_v + oidx) = v;
}

// ---------------- kernel 3b: V transpose + split into tile planes ----------------
__global__ void vtrans_kernel() {
    __shared__ float vs[64 * 65];   // [l][d], pad 65
    const int kt = blockIdx.x, bh = blockIdx.y;
    const int tid = threadIdx.x;
    const float4* Vg = (const float4*)(g_v + ((size_t)bh * LL + kt * 64) * DHH);
    #pragma unroll
    for (int i = 0; i < 8; i++) {
        int idx = tid + i * 128;
        int l = idx >> 4, c4 = idx & 15;
        float4 v = Vg[l * 16 + c4];
        vs[l * 65 + c4 * 4 + 0] = v.x;
        vs[l * 65 + c4 * 4 + 1] = v.y;
        vs[l * 65 + c4 * 4 + 2] = v.z;
        vs[l * 65 + c4 * 4 + 3] = v.w;
    }
    __syncthreads();
    size_t base = ((size_t)bh * 32 + kt) * 64 * 32;
    #pragma unroll
    for (int i = 0; i < 16; i++) {
        int idx = tid + i * 128;
        int d = idx >> 5, lp = idx & 31;
        float a = vs[(2 * lp) * 65 + d];
        float b = vs[(2 * lp + 1) * 65 + d];
        uint32_t h, l;
        bfsplit(a, b, h, l);
        g_vth[base + d * 32 + lp] = h;
        g_vtl[base + d * 32 + lp] = l;
    }
}

// ---------------- kernel 4: flash attention, cp.async staged pre-split planes ----
#define AW 36
#define ATTN_SMEM (6 * 64 * AW * 4)   // 55296 B

__global__ __launch_bounds__(128, 4)
void attn_kernel(const int* __restrict__ seq_id) {
    extern __shared__ uint32_t smw[];
    uint32_t* Qh  = smw;                // [64][AW]
    uint32_t* Ql  = Qh  + 64 * AW;
    uint32_t* KPh = Ql  + 64 * AW;      // K (then P) hi
    uint32_t* KPl = KPh + 64 * AW;
    uint32_t* VTh = KPl + 64 * AW;      // V^T hi
    uint32_t* VTl = VTh + 64 * AW;
    __shared__ int kseq[64];

    const int qt = blockIdx.x, bh = blockIdx.y;
    const int b = bh >> 4, hh = bh & 15;
    const int tid = threadIdx.x;
    const int w = tid >> 5, lane = tid & 31;
    const int grp = lane >> 2, qd = lane & 3;

    const int qbase = b * LL + qt * 64;
    const int qmin = seq_id[qbase];
    const int qmax = seq_id[qbase + 63];

    const uint32_t sb = (uint32_t)__cvta_generic_to_shared(smw);
    const uint32_t sQh = sb, sQl = sb + 64 * AW * 4;
    const uint32_t sKPh = sQl + 64 * AW * 4, sKPl = sKPh + 64 * AW * 4;
    const uint32_t sVTh = sKPl + 64 * AW * 4, sVTl = sVTh + 64 * AW * 4;

    // stage Q hi/lo via cp.async
    {
        const size_t qrow = ((size_t)bh * LL + qt * 64) * 32;
        #pragma unroll
        for (int i = 0; i < 4; i++) {
            int idx = tid + i * 128;
            int r = idx >> 3, c = idx & 7;
            cp16(sQh + (r * AW + c * 4) * 4, g_qh + qrow + r * 32 + c * 4);
        }
        #pragma unroll
        for (int i = 0; i < 4; i++) {
            int idx = tid + i * 128;
            int r = idx >> 3, c = idx & 7;
            cp16(sQl + (r * AW + c * 4) * 4, g_ql + qrow + r * 32 + c * 4);
        }
        cp_commit();
    }
    const int row0 = w * 16 + grp, row1 = row0 + 8;
    const int qs0 = seq_id[qbase + row0];
    const int qs1 = seq_id[qbase + row1];

    float m0 = -1e30f, m1 = -1e30f, l0s = 0.f, l1s = 0.f;
    float O[8][4];
    #pragma unroll
    for (int dt = 0; dt < 8; dt++)
        #pragma unroll
        for (int q = 0; q < 4; q++) O[dt][q] = 0.f;

    for (int kt = 0; kt < LL / 64; kt++) {
        const int kb = b * LL + kt * 64;
        if (seq_id[kb + 63] < qmin || seq_id[kb] > qmax) continue;  // exact no-op tile

        __syncthreads();   // prior-iteration smem reads complete
        // stage K hi/lo + V^T hi/lo via cp.async
        {
            const size_t krow = ((size_t)bh * LL + kt * 64) * 32;
            const size_t vbase = ((size_t)bh * 32 + kt) * 64 * 32;
            #pragma unroll
            for (int i = 0; i < 4; i++) {
                int idx = tid + i * 128;
                int r = idx >> 3, c = idx & 7;
                cp16(sKPh + (r * AW + c * 4) * 4, g_kh + krow + r * 32 + c * 4);
            }
            #pragma unroll
            for (int i = 0; i < 4; i++) {
                int idx = tid + i * 128;
                int r = idx >> 3, c = idx & 7;
                cp16(sKPl + (r * AW + c * 4) * 4, g_kl + krow + r * 32 + c * 4);
            }
            #pragma unroll
            for (int i = 0; i < 4; i++) {
                int idx = tid + i * 128;
                int r = idx >> 3, c = idx & 7;
                cp16(sVTh + (r * AW + c * 4) * 4, g_vth + vbase + r * 32 + c * 4);
            }
            #pragma unroll
            for (int i = 0; i < 4; i++) {
                int idx = tid + i * 128;
                int r = idx >> 3, c = idx & 7;
                cp16(sVTl + (r * AW + c * 4) * 4, g_vtl + vbase + r * 32 + c * 4);
            }
            cp_commit();
        }
        if (tid < 64) kseq[tid] = seq_id[kb + tid];
        cp_wait_all();
        __syncthreads();

        // ---- S = Q K^T (3-term split) ----
        float S[8][4];
        #pragma unroll
        for (int nt = 0; nt < 8; nt++)
            #pragma unroll
            for (int q = 0; q < 4; q++) S[nt][q] = 0.f;
        #pragma unroll
        for (int ks = 0; ks < 4; ks++) {
            int r0w = (w * 16 + grp) * AW, r1w = (w * 16 + grp + 8) * AW;
            int kw0 = ks * 8 + qd;
            uint32_t ah0 = Qh[r0w + kw0],     ah1 = Qh[r1w + kw0];
            uint32_t ah2 = Qh[r0w + kw0 + 4], ah3 = Qh[r1w + kw0 + 4];
            uint32_t al0 = Ql[r0w + kw0],     al1 = Ql[r1w + kw0];
            uint32_t al2 = Ql[r0w + kw0 + 4], al3 = Ql[r1w + kw0 + 4];
            #pragma unroll
            for (int nt = 0; nt < 8; nt++) {
                int nw = (nt * 8 + grp) * AW;
                uint32_t bh0 = KPh[nw + kw0], bh1 = KPh[nw + kw0 + 4];
                uint32_t bl0 = KPl[nw + kw0], bl1 = KPl[nw + kw0 + 4];
                mma16816(S[nt], ah0, ah1, ah2, ah3, bh0, bh1);
                mma16816(S[nt], ah0, ah1, ah2, ah3, bl0, bl1);
                mma16816(S[nt], al0, al1, al2, al3, bh0, bh1);
            }
        }

        // ---- mask ----
        #pragma unroll
        for (int nt = 0; nt < 8; nt++) {
            int c0 = kseq[nt * 8 + 2 * qd];
            int c1 = kseq[nt * 8 + 2 * qd + 1];
            if (c0 != qs0) S[nt][0] = -1e30f;
            if (c1 != qs0) S[nt][1] = -1e30f;
            if (c0 != qs1) S[nt][2] = -1e30f;
            if (c1 != qs1) S[nt][3] = -1e30f;
        }

        // ---- online softmax ----
        float mx0 = -1e30f, mx1 = -1e30f;
        #pragma unroll
        for (int nt = 0; nt < 8; nt++) {
            mx0 = fmaxf(mx0, fmaxf(S[nt][0], S[nt][1]));
            mx1 = fmaxf(mx1, fmaxf(S[nt][2], S[nt][3]));
        }
        mx0 = fmaxf(mx0, __shfl_xor_sync(0xffffffffu, mx0, 1));
        mx0 = fmaxf(mx0, __shfl_xor_sync(0xffffffffu, mx0, 2));
        mx1 = fmaxf(mx1, __shfl_xor_sync(0xffffffffu, mx1, 1));
        mx1 = fmaxf(mx1, __shfl_xor_sync(0xffffffffu, mx1, 2));
        float mn0 = fmaxf(m0, mx0), mn1 = fmaxf(m1, mx1);
        float sc0 = __expf(m0 - mn0), sc1 = __expf(m1 - mn1);
        m0 = mn0; m1 = mn1;
        float s0 = 0.f, s1 = 0.f;
        #pragma unroll
        for (int nt = 0; nt < 8; nt++) {
            S[nt][0] = __expf(S[nt][0] - mn0);
            S[nt][1] = __expf(S[nt][1] - mn0);
            S[nt][2] = __expf(S[nt][2] - mn1);
            S[nt][3] = __expf(S[nt][3] - mn1);
            s0 += S[nt][0] + S[nt][1];
            s1 += S[nt][2] + S[nt][3];
        }
        s0 += __shfl_xor_sync(0xffffffffu, s0, 1);
        s0 += __shfl_xor_sync(0xffffffffu, s0, 2);
        s1 += __shfl_xor_sync(0xffffffffu, s1, 1);
        s1 += __shfl_xor_sync(0xffffffffu, s1, 2);
        l0s = l0s * sc0 + s0;
        l1s = l1s * sc1 + s1;
        #pragma unroll
        for (int dt = 0; dt < 8; dt++) {
            O[dt][0] *= sc0; O[dt][1] *= sc0;
            O[dt][2] *= sc1; O[dt][3] *= sc1;
        }

        __syncthreads();   // all K fragment reads done before P overwrite
        #pragma unroll
        for (int nt = 0; nt < 8; nt++) {
            uint32_t h, l;
            bfsplit(S[nt][0], S[nt][1], h, l);
            KPh[(w * 16 + grp) * AW + nt * 4 + qd] = h;
            KPl[(w * 16 + grp) * AW + nt * 4 + qd] = l;
            bfsplit(S[nt][2], S[nt][3], h, l);
            KPh[(w * 16 + grp + 8) * AW + nt * 4 + qd] = h;
            KPl[(w * 16 + grp + 8) * AW + nt * 4 + qd] = l;
        }
        __syncthreads();

        // ---- O += P V (3-term split) ----
        #pragma unroll
        for (int ks = 0; ks < 4; ks++) {
            int r0w = (w * 16 + grp) * AW, r1w = (w * 16 + grp + 8) * AW;
            int kw0 = ks * 8 + qd;
            uint32_t ah0 = KPh[r0w + kw0],     ah1 = KPh[r1w + kw0];
            uint32_t ah2 = KPh[r0w + kw0 + 4], ah3 = KPh[r1w + kw0 + 4];
            uint32_t al0 = KPl[r0w + kw0],     al1 = KPl[r1w + kw0];
            uint32_t al2 = KPl[r0w + kw0 + 4], al3 = KPl[r1w + kw0 + 4];
            #pragma unroll
            for (int dt = 0; dt < 8; dt++) {
                int dw = (dt * 8 + grp) * AW;
                uint32_t bh0 = VTh[dw + kw0], bh1 = VTh[dw + kw0 + 4];
                uint32_t bl0 = VTl[dw + kw0], bl1 = VTl[dw + kw0 + 4];
                mma16816(O[dt], ah0, ah1, ah2, ah3, bh0, bh1);
                mma16816(O[dt], ah0, ah1, ah2, ah3, bl0, bl1);
                mma16816(O[dt], al0, al1, al2, al3, bh0, bh1);
            }
        }
    }

    // epilogue
    float inv0 = 1.0f / l0s, inv1 = 1.0f / l1s;
    const int t0 = b * LL + qt * 64 + row0;
    const int t1 = b * LL + qt * 64 + row1;
    #pragma unroll
    for (int dt = 0; dt < 8; dt++) {
        int c = hh * DHH + dt * 8 + 2 * qd;
        *(float2*)(g_ctx + (size_t)t0 * DD + c) =
            make_float2(O[dt][0] * inv0, O[dt][1] * inv0);
        *(float2*)(g_ctx + (size_t)t1 * DD + c) =
            make_float2(O[dt][2] * inv1, O[dt][3] * inv1);
    }
}

// ---------------- launch ----------------
extern "C" void kernel_launch(void* const* d_in, const int* in_sizes, int n_in,
                              void* d_out, int out_size) {
    const float* x     = (const float*)d_in[0];
    const int*   seq   = (const int*)  d_in[1];
    const float* ln1w  = (const float*)d_in[2];
    const float* ln1b  = (const float*)d_in[3];
    const float* wqkv  = (const float*)d_in[4];
    const float* qlnw  = (const float*)d_in[5];
    const float* klnw  = (const float*)d_in[6];
    const float* outw  = (const float*)d_in[7];
    float* out = (float*)d_out;

    void *ph, *pqkv, *pctx;
    cudaGetSymbolAddress(&ph, g_h);
    cudaGetSymbolAddress(&pqkv, g_qkv);
    cudaGetSymbolAddress(&pctx, g_ctx);

    cudaFuncSetAttribute(gemm_mma_fp16, cudaFuncAttributeMaxDynamicSharedMemorySize, GEMM_SMEM);
    cudaFuncSetAttribute(attn_kernel, cudaFuncAttributeMaxDynamicSharedMemorySize, ATTN_SMEM);

    // 0) RoPE table
    rope_table_kernel<<<(LL * 32 + 255) / 256, 256>>>();

    // 1) LN1
    ln1_kernel<<<TT, 256>>>(x, ln1w, ln1b);

    // 2) QKV GEMM (fp16 mma.sync k16, fp32 accum)
    gemm_mma_fp16<<<dim3(3 * DD / 128, TT / 128), 256, GEMM_SMEM>>>(
        (const float*)ph, wqkv, (float*)pqkv, 3 * DD);

    // 3) QK LN + RoPE (table) -> pre-split planes; V row-major
    qk_rope_kernel<<<TT, 256>>>(qlnw, klnw);

    // 3b) V transpose + split
    vtrans_kernel<<<dim3(32, NBH), 128>>>();

    // 4) attention (tile-skip + cp.async staging + bf16-split3 mma)
    attn_kernel<<<dim3(LL / 64, NBH), 128, ATTN_SMEM>>>(seq);

    // 5) output projection (fp16 mma.sync)
    gemm_mma_fp16<<<dim3(DD / 128, TT / 128), 256, GEMM_SMEM>>>(
        (const float*)pctx, outw, out, DD);
}

// round 10
// speedup vs baseline: 2.1334x; 1.1143x over previous
#include <cuda_runtime.h>
#include <cuda_bf16.h>
#include <cuda_fp16.h>
#include <cstdint>
#include <math.h>

// Problem constants
#define BB 2
#define LL 2048
#define DD 1024
#define HH 16
#define DHH 64
#define TT (BB*LL)          // 4096 tokens
#define EPS 1e-5f
#define NBH (BB*HH)         // 32
#define KW 512              // k-pair words per row (GK/2)

// -------- scratch (device globals: allocation-free rule) --------
__device__ float g_qkv[TT * 3 * DD];      // QKV GEMM output (fp32, LN needs it)
__device__ float g_v[TT * DD];            // [B,H,L,DH] v (row-major, float)
__device__ float2 g_cs[LL * 32];          // RoPE cos/sin table [l][fi]
// fp16 operand planes for projection GEMMs (half2 k-pair words)
__device__ __align__(16) uint32_t g_hh[TT * KW];        // LN1 out, fp16
__device__ __align__(16) uint32_t g_wqkv16[3 * DD * KW];
__device__ __align__(16) uint32_t g_outw16[DD * KW];
__device__ __align__(16) uint32_t g_ctx16[TT * KW];     // attention out, fp16
// pre-split bf16 planes, word = bf16x2 of adjacent head-dims: [bh][l][32 words]
__device__ __align__(16) uint32_t g_qh[NBH * LL * 32];
__device__ __align__(16) uint32_t g_ql[NBH * LL * 32];
__device__ __align__(16) uint32_t g_kh[NBH * LL * 32];
__device__ __align__(16) uint32_t g_kl[NBH * LL * 32];
// pre-split transposed V tiles: [bh][kt(32)][d(64)][32 l-pair words]
__device__ __align__(16) uint32_t g_vth[NBH * 32 * 64 * 32];
__device__ __align__(16) uint32_t g_vtl[NBH * 32 * 64 * 32];

// bf16 helpers (attention)
__device__ __forceinline__ uint32_t bfpack(float a, float b) {
    __nv_bfloat162 t = __floats2bfloat162_rn(a, b);
    return *reinterpret_cast<uint32_t*>(&t);
}
__device__ __forceinline__ void bfsplit(float a, float b, uint32_t& hi, uint32_t& lo) {
    __nv_bfloat16 ha = __float2bfloat16_rn(a), hb = __float2bfloat16_rn(b);
    float ra = a - __bfloat162float(ha);
    float rb = b - __bfloat162float(hb);
    __nv_bfloat162 h; h.x = ha; h.y = hb;
    hi = *reinterpret_cast<uint32_t*>(&h);
    lo = bfpack(ra, rb);
}
__device__ __forceinline__ uint32_t h2pack(float a, float b) {
    __half2 t = __floats2half2_rn(a, b);
    return *reinterpret_cast<uint32_t*>(&t);
}
// bf16 m16n8k16 (attention)
__device__ __forceinline__ void mma16816(float* c, uint32_t a0, uint32_t a1,
                                         uint32_t a2, uint32_t a3,
                                         uint32_t b0, uint32_t b1) {
    asm volatile(
        "mma.sync.aligned.m16n8k16.row.col.f32.bf16.bf16.f32 "
        "{%0,%1,%2,%3}, {%4,%5,%6,%7}, {%8,%9}, {%0,%1,%2,%3};"
        : "+f"(c[0]), "+f"(c[1]), "+f"(c[2]), "+f"(c[3])
        : "r"(a0), "r"(a1), "r"(a2), "r"(a3), "r"(b0), "r"(b1));
}
// fp16 m16n8k16 (projection GEMMs)
__device__ __forceinline__ void mma16816h(float* c, uint32_t a0, uint32_t a1,
                                          uint32_t a2, uint32_t a3,
                                          uint32_t b0, uint32_t b1) {
    asm volatile(
        "mma.sync.aligned.m16n8k16.row.col.f32.f16.f16.f32 "
        "{%0,%1,%2,%3}, {%4,%5,%6,%7}, {%8,%9}, {%0,%1,%2,%3};"
        : "+f"(c[0]), "+f"(c[1]), "+f"(c[2]), "+f"(c[3])
        : "r"(a0), "r"(a1), "r"(a2), "r"(a3), "r"(b0), "r"(b1));
}

__device__ __forceinline__ void cp16(uint32_t dst, const void* src) {
    asm volatile("cp.async.ca.shared.global [%0], [%1], 16;"
                 :: "r"(dst), "l"(src));
}
__device__ __forceinline__ void cp_commit() {
    asm volatile("cp.async.commit_group;");
}
__device__ __forceinline__ void cp_wait_all() {
    asm volatile("cp.async.wait_all;" ::: "memory");
}

// ---------------- fp32 -> fp16-words conversion ----------------
__global__ void cvt16_kernel(const float* __restrict__ in,
                             uint32_t* __restrict__ out, int nwords) {
    int i = blockIdx.x * 256 + threadIdx.x;
    if (i < nwords) {
        float2 v = ((const float2*)in)[i];
        out[i] = h2pack(v.x, v.y);
    }
}

// ===================== fp16 GEMM, cp.async 3-stage pipeline ==========
// C[M,N] = A[M,1024] * B[N,1024]^T, operands pre-converted fp16 words.
#define NCHUNK 32            // 1024 / 32
#define PADh 20              // 16 k-pair words + 4 pad
#define STGW (2 * 128 * PADh)        // words per stage (A+B)
#define GEMM_SMEM (3 * STGW * 4)     // 61440 B

__global__ __launch_bounds__(256)
void gemm_mma_fp16(const uint32_t* __restrict__ A, const uint32_t* __restrict__ B,
                   float* __restrict__ C, int N) {
    extern __shared__ uint32_t smg[];

    const int tid = threadIdx.x;
    const int wid = tid >> 5, lane = tid & 31;
    const int grp = lane >> 2, qd = lane & 3;
    const int wm = wid >> 1, wn = wid & 1;   // 4 m-warps x 2 n-warps, 32x64 tile
    const int m0 = blockIdx.y * 128;
    const int n0 = blockIdx.x * 128;

    const uint32_t sb = (uint32_t)__cvta_generic_to_shared(smg);
    const int cr = tid >> 2;            // staging row 0..63 base (2 iters -> 128)
    const int cc = tid & 3;             // 4-word chunk 0..3

    float acc[2][8][4];
    #pragma unroll
    for (int i = 0; i < 2; i++)
        #pragma unroll
        for (int j = 0; j < 8; j++)
            #pragma unroll
            for (int q = 0; q < 4; q++) acc[i][j][q] = 0.f;

    // issue chunk ic into stage ic%3
    #define GEMM_ISSUE(ic) do {                                              \
        uint32_t base = sb + ((ic) % 3) * STGW * 4;                          \
        _Pragma("unroll")                                                    \
        for (int i_ = 0; i_ < 2; i_++) {                                     \
            int r_ = cr + i_ * 64;                                           \
            uint32_t doff = (r_ * PADh + cc * 4) * 4;                        \
            cp16(base + doff,                                                \
                 A + (size_t)(m0 + r_) * KW + (ic) * 16 + cc * 4);           \
            cp16(base + 128 * PADh * 4 + doff,                               \
                 B + (size_t)(n0 + r_) * KW + (ic) * 16 + cc * 4);           \
        }                                                                    \
        cp_commit();                                                         \
    } while (0)

    GEMM_ISSUE(0);

    for (int ic = 0; ic < NCHUNK; ic++) {
        if (ic + 1 < NCHUNK) {
            GEMM_ISSUE(ic + 1);
            asm volatile("cp.async.wait_group 1;" ::: "memory");
        } else {
            cp_wait_all();
        }
        __syncthreads();

        const uint32_t* Ab = smg + (ic % 3) * STGW;
        const uint32_t* Bb = Ab + 128 * PADh;
        #pragma unroll
        for (int ks = 0; ks < 2; ks++) {
            int kw = ks * 8 + qd;
            uint32_t af[2][4];
            #pragma unroll
            for (int mt = 0; mt < 2; mt++) {
                int r = wm * 32 + mt * 16 + grp;
                af[mt][0] = Ab[r * PADh + kw];
                af[mt][1] = Ab[(r + 8) * PADh + kw];
                af[mt][2] = Ab[r * PADh + kw + 4];
                af[mt][3] = Ab[(r + 8) * PADh + kw + 4];
            }
            #pragma unroll
            for (int nt = 0; nt < 8; nt++) {
                int c = wn * 64 + nt * 8 + grp;
                uint32_t b0 = Bb[c * PADh + kw];
                uint32_t b1 = Bb[c * PADh + kw + 4];
                mma16816h(acc[0][nt], af[0][0], af[0][1], af[0][2], af[0][3], b0, b1);
                mma16816h(acc[1][nt], af[1][0], af[1][1], af[1][2], af[1][3], b0, b1);
            }
        }
    }

    #pragma unroll
    for (int mt = 0; mt < 2; mt++) {
        #pragma unroll
        for (int nt = 0; nt < 8; nt++) {
            int r = m0 + wm * 32 + mt * 16 + grp;
            int c = n0 + wn * 64 + nt * 8 + qd * 2;
            *(float2*)(C + (size_t)r * N + c) =
                make_float2(acc[mt][nt][0], acc[mt][nt][1]);
            *(float2*)(C + (size_t)(r + 8) * N + c) =
                make_float2(acc[mt][nt][2], acc[mt][nt][3]);
        }
    }
}

// ---------------- block reduction helper (256 threads) ----------------
__device__ __forceinline__ void block_reduce4(float& a, float& b, float& c, float& d) {
    #pragma unroll
    for (int o = 16; o; o >>= 1) {
        a += __shfl_xor_sync(0xffffffffu, a, o);
        b += __shfl_xor_sync(0xffffffffu, b, o);
        c += __shfl_xor_sync(0xffffffffu, c, o);
        d += __shfl_xor_sync(0xffffffffu, d, o);
    }
    __shared__ float s[4][8];
    int w = threadIdx.x >> 5, lane = threadIdx.x & 31;
    if (lane == 0) { s[0][w] = a; s[1][w] = b; s[2][w] = c; s[3][w] = d; }
    __syncthreads();
    a = b = c = d = 0.f;
    #pragma unroll
    for (int i = 0; i < 8; i++) { a += s[0][i]; b += s[1][i]; c += s[2][i]; d += s[3][i]; }
    __syncthreads();
}

// ---------------- kernel 0: RoPE cos/sin table ----------------
__global__ void rope_table_kernel() {
    int idx = blockIdx.x * 256 + threadIdx.x;
    if (idx >= LL * 32) return;
    int l = idx >> 5, fi = idx & 31;
    float invf = powf(10000.0f, -((float)(2 * fi)) / 64.0f);
    float ang  = (float)l * invf;
    g_cs[idx] = make_float2(cosf(ang), sinf(ang));
}

// ---------------- kernel 1: LN1 (fp16 word output) ----------------
__global__ void ln1_kernel(const float* __restrict__ x,
                           const float* __restrict__ w,
                           const float* __restrict__ bia) {
    int t = blockIdx.x;
    int tid = threadIdx.x;
    const float4* xr = (const float4*)(x + (size_t)t * DD);
    float4 v = xr[tid];
    float s  = v.x + v.y + v.z + v.w;
    float ss = v.x*v.x + v.y*v.y + v.z*v.z + v.w*v.w;
    float z0 = 0.f, z1 = 0.f;
    block_reduce4(s, ss, z0, z1);
    float mu  = s * (1.0f / DD);
    float var = ss * (1.0f / DD) - mu * mu;
    float inv = rsqrtf(var + EPS);
    float4 wv = ((const float4*)w)[tid];
    float4 bv = ((const float4*)bia)[tid];
    float4 o;
    o.x = (v.x - mu) * inv * wv.x + bv.x;
    o.y = (v.y - mu) * inv * wv.y + bv.y;
    o.z = (v.z - mu) * inv * wv.z + bv.z;
    o.w = (v.w - mu) * inv * wv.w + bv.w;
    *(uint2*)(g_hh + (size_t)t * KW + tid * 2) =
        make_uint2(h2pack(o.x, o.y), h2pack(o.z, o.w));
}

// ---------------- kernel 3: QK LN + RoPE (table) + pre-split bf16 planes --------
__global__ void qk_rope_kernel(const float* __restrict__ qw,
                               const float* __restrict__ kw) {
    int t = blockIdx.x;
    int b = t >> 11;
    int l = t & 2047;
    int tid = threadIdx.x;
    const float4* row = (const float4*)(g_qkv + (size_t)t * 3 * DD);
    float4 q = row[tid];
    float4 k = row[256 + tid];
    float4 v = row[512 + tid];

    float qs  = q.x + q.y + q.z + q.w;
    float qss = q.x*q.x + q.y*q.y + q.z*q.z + q.w*q.w;
    float ks  = k.x + k.y + k.z + k.w;
    float kss = k.x*k.x + k.y*k.y + k.z*k.z + k.w*k.w;
    block_reduce4(qs, qss, ks, kss);
    float muq = qs * (1.0f / DD);
    float vq  = qss * (1.0f / DD) - muq * muq;
    float iq  = rsqrtf(vq + EPS);
    float muk = ks * (1.0f / DD);
    float vk  = kss * (1.0f / DD) - muk * muk;
    float ik  = rsqrtf(vk + EPS);

    __shared__ float qn[DD];
    __shared__ float kn[DD];
    float4 qwv = ((const float4*)qw)[tid];
    float4 kwv = ((const float4*)kw)[tid];
    int d0 = tid * 4;
    qn[d0+0] = (q.x - muq) * iq * qwv.x;
    qn[d0+1] = (q.y - muq) * iq * qwv.y;
    qn[d0+2] = (q.z - muq) * iq * qwv.z;
    qn[d0+3] = (q.w - muq) * iq * qwv.w;
    kn[d0+0] = (k.x - muk) * ik * kwv.x;
    kn[d0+1] = (k.y - muk) * ik * kwv.y;
    kn[d0+2] = (k.z - muk) * ik * kwv.z;
    kn[d0+3] = (k.w - muk) * ik * kwv.w;
    __syncthreads();

    int h   = d0 >> 6;
    int dh0 = d0 & 63;
    float oq[4], ok[4];
    #pragma unroll
    for (int j = 0; j < 4; j++) {
        int dh = dh0 + j;
        int fi = dh & 31;
        float2 cs = g_cs[l * 32 + fi];
        float c = cs.x, s = cs.y;
        float qv = qn[d0 + j];
        float kv = kn[d0 + j];
        float qp = (dh < 32) ? -qn[d0 + j + 32] : qn[d0 + j - 32];
        float kp = (dh < 32) ? -kn[d0 + j + 32] : kn[d0 + j - 32];
        oq[j] = (qv * c + qp * s) * 0.125f;   // fold 1/sqrt(DH) exactly
        ok[j] = kv * c + kp * s;
    }
    size_t pb = ((size_t)(b * HH + h) * LL + l) * 32 + (dh0 >> 1);
    uint32_t h0, l0, h1, l1;
    bfsplit(oq[0], oq[1], h0, l0);
    bfsplit(oq[2], oq[3], h1, l1);
    g_qh[pb] = h0; g_qh[pb + 1] = h1;
    g_ql[pb] = l0; g_ql[pb + 1] = l1;
    bfsplit(ok[0], ok[1], h0, l0);
    bfsplit(ok[2], ok[3], h1, l1);
    g_kh[pb] = h0; g_kh[pb + 1] = h1;
    g_kl[pb] = l0; g_kl[pb + 1] = l1;

    size_t oidx = (((size_t)(b * HH + h) * LL + l) * DHH + dh0);
    *(float4*)(g_v + oidx) = v;
}

// ---------------- kernel 3b: V transpose + split into tile planes ----------------
__global__ void vtrans_kernel() {
    __shared__ float vs[64 * 65];   // [l][d], pad 65
    const int kt = blockIdx.x, bh = blockIdx.y;
    const int tid = threadIdx.x;
    const float4* Vg = (const float4*)(g_v + ((size_t)bh * LL + kt * 64) * DHH);
    #pragma unroll
    for (int i = 0; i < 8; i++) {
        int idx = tid + i * 128;
        int l = idx >> 4, c4 = idx & 15;
        float4 v = Vg[l * 16 + c4];
        vs[l * 65 + c4 * 4 + 0] = v.x;
        vs[l * 65 + c4 * 4 + 1] = v.y;
        vs[l * 65 + c4 * 4 + 2] = v.z;
        vs[l * 65 + c4 * 4 + 3] = v.w;
    }
    __syncthreads();
    size_t base = ((size_t)bh * 32 + kt) * 64 * 32;
    #pragma unroll
    for (int i = 0; i < 16; i++) {
        int idx = tid + i * 128;
        int d = idx >> 5, lp = idx & 31;
        float a = vs[(2 * lp) * 65 + d];
        float b = vs[(2 * lp + 1) * 65 + d];
        uint32_t h, l;
        bfsplit(a, b, h, l);
        g_vth[base + d * 32 + lp] = h;
        g_vtl[base + d * 32 + lp] = l;
    }
}

// ---------------- kernel 4: flash attention, cp.async staged pre-split planes ----
#define AW 36
#define ATTN_SMEM (6 * 64 * AW * 4)   // 55296 B

__global__ __launch_bounds__(128, 4)
void attn_kernel(const int* __restrict__ seq_id) {
    extern __shared__ uint32_t smw[];
    uint32_t* Qh  = smw;                // [64][AW]
    uint32_t* Ql  = Qh  + 64 * AW;
    uint32_t* KPh = Ql  + 64 * AW;      // K (then P) hi
    uint32_t* KPl = KPh + 64 * AW;
    uint32_t* VTh = KPl + 64 * AW;      // V^T hi
    uint32_t* VTl = VTh + 64 * AW;
    __shared__ int kseq[64];

    const int qt = blockIdx.x, bh = blockIdx.y;
    const int b = bh >> 4, hh = bh & 15;
    const int tid = threadIdx.x;
    const int w = tid >> 5, lane = tid & 31;
    const int grp = lane >> 2, qd = lane & 3;

    const int qbase = b * LL + qt * 64;
    const int qmin = seq_id[qbase];
    const int qmax = seq_id[qbase + 63];

    const uint32_t sb = (uint32_t)__cvta_generic_to_shared(smw);
    const uint32_t sQh = sb, sQl = sb + 64 * AW * 4;
    const uint32_t sKPh = sQl + 64 * AW * 4, sKPl = sKPh + 64 * AW * 4;
    const uint32_t sVTh = sKPl + 64 * AW * 4, sVTl = sVTh + 64 * AW * 4;

    // stage Q hi/lo via cp.async
    {
        const size_t qrow = ((size_t)bh * LL + qt * 64) * 32;
        #pragma unroll
        for (int i = 0; i < 4; i++) {
            int idx = tid + i * 128;
            int r = idx >> 3, c = idx & 7;
            cp16(sQh + (r * AW + c * 4) * 4, g_qh + qrow + r * 32 + c * 4);
        }
        #pragma unroll
        for (int i = 0; i < 4; i++) {
            int idx = tid + i * 128;
            int r = idx >> 3, c = idx & 7;
            cp16(sQl + (r * AW + c * 4) * 4, g_ql + qrow + r * 32 + c * 4);
        }
        cp_commit();
    }
    const int row0 = w * 16 + grp, row1 = row0 + 8;
    const int qs0 = seq_id[qbase + row0];
    const int qs1 = seq_id[qbase + row1];

    float m0 = -1e30f, m1 = -1e30f, l0s = 0.f, l1s = 0.f;
    float O[8][4];
    #pragma unroll
    for (int dt = 0; dt < 8; dt++)
        #pragma unroll
        for (int q = 0; q < 4; q++) O[dt][q] = 0.f;

    for (int kt = 0; kt < LL / 64; kt++) {
        const int kb = b * LL + kt * 64;
        if (seq_id[kb + 63] < qmin || seq_id[kb] > qmax) continue;  // exact no-op tile

        __syncthreads();   // prior-iteration smem reads complete
        // stage K hi/lo + V^T hi/lo via cp.async
        {
            const size_t krow = ((size_t)bh * LL + kt * 64) * 32;
            const size_t vbase = ((size_t)bh * 32 + kt) * 64 * 32;
            #pragma unroll
            for (int i = 0; i < 4; i++) {
                int idx = tid + i * 128;
                int r = idx >> 3, c = idx & 7;
                cp16(sKPh + (r * AW + c * 4) * 4, g_kh + krow + r * 32 + c * 4);
            }
            #pragma unroll
            for (int i = 0; i < 4; i++) {
                int idx = tid + i * 128;
                int r = idx >> 3, c = idx & 7;
                cp16(sKPl + (r * AW + c * 4) * 4, g_kl + krow + r * 32 + c * 4);
            }
            #pragma unroll
            for (int i = 0; i < 4; i++) {
                int idx = tid + i * 128;
                int r = idx >> 3, c = idx & 7;
                cp16(sVTh + (r * AW + c * 4) * 4, g_vth + vbase + r * 32 + c * 4);
            }
            #pragma unroll
            for (int i = 0; i < 4; i++) {
                int idx = tid + i * 128;
                int r = idx >> 3, c = idx & 7;
                cp16(sVTl + (r * AW + c * 4) * 4, g_vtl + vbase + r * 32 + c * 4);
            }
            cp_commit();
        }
        if (tid < 64) kseq[tid] = seq_id[kb + tid];
        cp_wait_all();
        __syncthreads();

        // ---- S = Q K^T (3-term split) ----
        float S[8][4];
        #pragma unroll
        for (int nt = 0; nt < 8; nt++)
            #pragma unroll
            for (int q = 0; q < 4; q++) S[nt][q] = 0.f;
        #pragma unroll
        for (int ks = 0; ks < 4; ks++) {
            int r0w = (w * 16 + grp) * AW, r1w = (w * 16 + grp + 8) * AW;
            int kw0 = ks * 8 + qd;
            uint32_t ah0 = Qh[r0w + kw0],     ah1 = Qh[r1w + kw0];
            uint32_t ah2 = Qh[r0w + kw0 + 4], ah3 = Qh[r1w + kw0 + 4];
            uint32_t al0 = Ql[r0w + kw0],     al1 = Ql[r1w + kw0];
            uint32_t al2 = Ql[r0w + kw0 + 4], al3 = Ql[r1w + kw0 + 4];
            #pragma unroll
            for (int nt = 0; nt < 8; nt++) {
                int nw = (nt * 8 + grp) * AW;
                uint32_t bh0 = KPh[nw + kw0], bh1 = KPh[nw + kw0 + 4];
                uint32_t bl0 = KPl[nw + kw0], bl1 = KPl[nw + kw0 + 4];
                mma16816(S[nt], ah0, ah1, ah2, ah3, bh0, bh1);
                mma16816(S[nt], ah0, ah1, ah2, ah3, bl0, bl1);
                mma16816(S[nt], al0, al1, al2, al3, bh0, bh1);
            }
        }

        // ---- mask ----
        #pragma unroll
        for (int nt = 0; nt < 8; nt++) {
            int c0 = kseq[nt * 8 + 2 * qd];
            int c1 = kseq[nt * 8 + 2 * qd + 1];
            if (c0 != qs0) S[nt][0] = -1e30f;
            if (c1 != qs0) S[nt][1] = -1e30f;
            if (c0 != qs1) S[nt][2] = -1e30f;
            if (c1 != qs1) S[nt][3] = -1e30f;
        }

        // ---- online softmax ----
        float mx0 = -1e30f, mx1 = -1e30f;
        #pragma unroll
        for (int nt = 0; nt < 8; nt++) {
            mx0 = fmaxf(mx0, fmaxf(S[nt][0], S[nt][1]));
            mx1 = fmaxf(mx1, fmaxf(S[nt][2], S[nt][3]));
        }
        mx0 = fmaxf(mx0, __shfl_xor_sync(0xffffffffu, mx0, 1));
        mx0 = fmaxf(mx0, __shfl_xor_sync(0xffffffffu, mx0, 2));
        mx1 = fmaxf(mx1, __shfl_xor_sync(0xffffffffu, mx1, 1));
        mx1 = fmaxf(mx1, __shfl_xor_sync(0xffffffffu, mx1, 2));
        float mn0 = fmaxf(m0, mx0), mn1 = fmaxf(m1, mx1);
        float sc0 = __expf(m0 - mn0), sc1 = __expf(m1 - mn1);
        m0 = mn0; m1 = mn1;
        float s0 = 0.f, s1 = 0.f;
        #pragma unroll
        for (int nt = 0; nt < 8; nt++) {
            S[nt][0] = __expf(S[nt][0] - mn0);
            S[nt][1] = __expf(S[nt][1] - mn0);
            S[nt][2] = __expf(S[nt][2] - mn1);
            S[nt][3] = __expf(S[nt][3] - mn1);
            s0 += S[nt][0] + S[nt][1];
            s1 += S[nt][2] + S[nt][3];
        }
        s0 += __shfl_xor_sync(0xffffffffu, s0, 1);
        s0 += __shfl_xor_sync(0xffffffffu, s0, 2);
        s1 += __shfl_xor_sync(0xffffffffu, s1, 1);
        s1 += __shfl_xor_sync(0xffffffffu, s1, 2);
        l0s = l0s * sc0 + s0;
        l1s = l1s * sc1 + s1;
        #pragma unroll
        for (int dt = 0; dt < 8; dt++) {
            O[dt][0] *= sc0; O[dt][1] *= sc0;
            O[dt][2] *= sc1; O[dt][3] *= sc1;
        }

        __syncthreads();   // all K fragment reads done before P overwrite
        #pragma unroll
        for (int nt = 0; nt < 8; nt++) {
            uint32_t h, l;
            bfsplit(S[nt][0], S[nt][1], h, l);
            KPh[(w * 16 + grp) * AW + nt * 4 + qd] = h;
            KPl[(w * 16 + grp) * AW + nt * 4 + qd] = l;
            bfsplit(S[nt][2], S[nt][3], h, l);
            KPh[(w * 16 + grp + 8) * AW + nt * 4 + qd] = h;
            KPl[(w * 16 + grp + 8) * AW + nt * 4 + qd] = l;
        }
        __syncthreads();

        // ---- O += P V (3-term split) ----
        #pragma unroll
        for (int ks = 0; ks < 4; ks++) {
            int r0w = (w * 16 + grp) * AW, r1w = (w * 16 + grp + 8) * AW;
            int kw0 = ks * 8 + qd;
            uint32_t ah0 = KPh[r0w + kw0],     ah1 = KPh[r1w + kw0];
            uint32_t ah2 = KPh[r0w + kw0 + 4], ah3 = KPh[r1w + kw0 + 4];
            uint32_t al0 = KPl[r0w + kw0],     al1 = KPl[r1w + kw0];
            uint32_t al2 = KPl[r0w + kw0 + 4], al3 = KPl[r1w + kw0 + 4];
            #pragma unroll
            for (int dt = 0; dt < 8; dt++) {
                int dw = (dt * 8 + grp) * AW;
                uint32_t bh0 = VTh[dw + kw0], bh1 = VTh[dw + kw0 + 4];
                uint32_t bl0 = VTl[dw + kw0], bl1 = VTl[dw + kw0 + 4];
                mma16816(O[dt], ah0, ah1, ah2, ah3, bh0, bh1);
                mma16816(O[dt], ah0, ah1, ah2, ah3, bl0, bl1);
                mma16816(O[dt], al0, al1, al2, al3, bh0, bh1);
            }
        }
    }

    // epilogue: write ctx directly as fp16 words (identical rounding to
    // the out-proj staging conversion it replaces)
    float inv0 = 1.0f / l0s, inv1 = 1.0f / l1s;
    const int t0 = b * LL + qt * 64 + row0;
    const int t1 = b * LL + qt * 64 + row1;
    #pragma unroll
    for (int dt = 0; dt < 8; dt++) {
        int c = hh * DHH + dt * 8 + 2 * qd;
        g_ctx16[(size_t)t0 * KW + (c >> 1)] =
            h2pack(O[dt][0] * inv0, O[dt][1] * inv0);
        g_ctx16[(size_t)t1 * KW + (c >> 1)] =
            h2pack(O[dt][2] * inv1, O[dt][3] * inv1);
    }
}

// ---------------- launch ----------------
extern "C" void kernel_launch(void* const* d_in, const int* in_sizes, int n_in,
                              void* d_out, int out_size) {
    const float* x     = (const float*)d_in[0];
    const int*   seq   = (const int*)  d_in[1];
    const float* ln1w  = (const float*)d_in[2];
    const float* ln1b  = (const float*)d_in[3];
    const float* wqkv  = (const float*)d_in[4];
    const float* qlnw  = (const float*)d_in[5];
    const float* klnw  = (const float*)d_in[6];
    const float* outw  = (const float*)d_in[7];
    float* out = (float*)d_out;

    void *phh, *pqkv, *pw16, *po16, *pctx16;
    cudaGetSymbolAddress(&phh, g_hh);
    cudaGetSymbolAddress(&pqkv, g_qkv);
    cudaGetSymbolAddress(&pw16, g_wqkv16);
    cudaGetSymbolAddress(&po16, g_outw16);
    cudaGetSymbolAddress(&pctx16, g_ctx16);

    cudaFuncSetAttribute(gemm_mma_fp16, cudaFuncAttributeMaxDynamicSharedMemorySize, GEMM_SMEM);
    cudaFuncSetAttribute(attn_kernel, cudaFuncAttributeMaxDynamicSharedMemorySize, ATTN_SMEM);

    // 0) RoPE table + weight conversions (cheap, front of pipeline)
    rope_table_kernel<<<(LL * 32 + 255) / 256, 256>>>();
    cvt16_kernel<<<(3 * DD * KW + 255) / 256, 256>>>(wqkv, (uint32_t*)pw16, 3 * DD * KW);
    cvt16_kernel<<<(DD * KW + 255) / 256, 256>>>(outw, (uint32_t*)po16, DD * KW);

    // 1) LN1 -> fp16 words
    ln1_kernel<<<TT, 256>>>(x, ln1w, ln1b);

    // 2) QKV GEMM (fp16 operands, cp.async 3-stage)
    gemm_mma_fp16<<<dim3(3 * DD / 128, TT / 128), 256, GEMM_SMEM>>>(
        (const uint32_t*)phh, (const uint32_t*)pw16, (float*)pqkv, 3 * DD);

    // 3) QK LN + RoPE (table) -> pre-split planes; V row-major
    qk_rope_kernel<<<TT, 256>>>(qlnw, klnw);

    // 3b) V transpose + split
    vtrans_kernel<<<dim3(32, NBH), 128>>>();

    // 4) attention (tile-skip + cp.async staging + bf16-split3 mma)
    attn_kernel<<<dim3(LL / 64, NBH), 128, ATTN_SMEM>>>(seq);

    // 5) output projection (fp16 operands, cp.async 3-stage)
    gemm_mma_fp16<<<dim3(DD / 128, TT / 128), 256, GEMM_SMEM>>>(
        (const uint32_t*)pctx16, (const uint32_t*)po16, out, DD);
}

// round 11
// speedup vs baseline: 2.3735x; 1.1126x over previous
#include <cuda_runtime.h>
#include <cuda_bf16.h>
#include <cuda_fp16.h>
#include <cstdint>
#include <math.h>

// Problem constants
#define BB 2
#define LL 2048
#define DD 1024
#define HH 16
#define DHH 64
#define TT (BB*LL)          // 4096 tokens
#define EPS 1e-5f
#define NBH (BB*HH)         // 32
#define KW 512              // k-pair words per row (GK/2)

// -------- scratch (device globals: allocation-free rule) --------
__device__ float g_qkv[TT * 3 * DD];      // QKV GEMM output (fp32, LN needs it)
__device__ float2 g_cs[LL * 32];          // RoPE cos/sin table [l][fi]
// fp16 operand planes for projection GEMMs (half2 k-pair words)
__device__ __align__(16) uint32_t g_hh[TT * KW];        // LN1 out, fp16
__device__ __align__(16) uint32_t g_wqkv16[3 * DD * KW];
__device__ __align__(16) uint32_t g_outw16[DD * KW];
__device__ __align__(16) uint32_t g_ctx16[TT * KW];     // attention out, fp16
// pre-split bf16 planes, word = bf16x2 of adjacent head-dims: [bh][l][32 words]
__device__ __align__(16) uint32_t g_qh[NBH * LL * 32];
__device__ __align__(16) uint32_t g_ql[NBH * LL * 32];
__device__ __align__(16) uint32_t g_kh[NBH * LL * 32];
__device__ __align__(16) uint32_t g_kl[NBH * LL * 32];
// fp16 transposed V tiles: [bh][kt(32)][d(64)][32 l-pair words]
__device__ __align__(16) uint32_t g_vtf[NBH * 32 * 64 * 32];

// bf16 helpers (attention S path)
__device__ __forceinline__ uint32_t bfpack(float a, float b) {
    __nv_bfloat162 t = __floats2bfloat162_rn(a, b);
    return *reinterpret_cast<uint32_t*>(&t);
}
__device__ __forceinline__ void bfsplit(float a, float b, uint32_t& hi, uint32_t& lo) {
    __nv_bfloat16 ha = __float2bfloat16_rn(a), hb = __float2bfloat16_rn(b);
    float ra = a - __bfloat162float(ha);
    float rb = b - __bfloat162float(hb);
    __nv_bfloat162 h; h.x = ha; h.y = hb;
    hi = *reinterpret_cast<uint32_t*>(&h);
    lo = bfpack(ra, rb);
}
__device__ __forceinline__ uint32_t h2pack(float a, float b) {
    __half2 t = __floats2half2_rn(a, b);
    return *reinterpret_cast<uint32_t*>(&t);
}
// bf16 m16n8k16 (attention S)
__device__ __forceinline__ void mma16816(float* c, uint32_t a0, uint32_t a1,
                                         uint32_t a2, uint32_t a3,
                                         uint32_t b0, uint32_t b1) {
    asm volatile(
        "mma.sync.aligned.m16n8k16.row.col.f32.bf16.bf16.f32 "
        "{%0,%1,%2,%3}, {%4,%5,%6,%7}, {%8,%9}, {%0,%1,%2,%3};"
        : "+f"(c[0]), "+f"(c[1]), "+f"(c[2]), "+f"(c[3])
        : "r"(a0), "r"(a1), "r"(a2), "r"(a3), "r"(b0), "r"(b1));
}
// fp16 m16n8k16 (projection GEMMs + attention PV)
__device__ __forceinline__ void mma16816h(float* c, uint32_t a0, uint32_t a1,
                                          uint32_t a2, uint32_t a3,
                                          uint32_t b0, uint32_t b1) {
    asm volatile(
        "mma.sync.aligned.m16n8k16.row.col.f32.f16.f16.f32 "
        "{%0,%1,%2,%3}, {%4,%5,%6,%7}, {%8,%9}, {%0,%1,%2,%3};"
        : "+f"(c[0]), "+f"(c[1]), "+f"(c[2]), "+f"(c[3])
        : "r"(a0), "r"(a1), "r"(a2), "r"(a3), "r"(b0), "r"(b1));
}

__device__ __forceinline__ void cp16(uint32_t dst, const void* src) {
    asm volatile("cp.async.ca.shared.global [%0], [%1], 16;"
                 :: "r"(dst), "l"(src));
}
__device__ __forceinline__ void cp_commit() {
    asm volatile("cp.async.commit_group;");
}
__device__ __forceinline__ void cp_wait_all() {
    asm volatile("cp.async.wait_all;" ::: "memory");
}

// ---------------- fp32 -> fp16-words conversion ----------------
__global__ void cvt16_kernel(const float* __restrict__ in,
                             uint32_t* __restrict__ out, int nwords) {
    int i = blockIdx.x * 256 + threadIdx.x;
    if (i < nwords) {
        float2 v = ((const float2*)in)[i];
        out[i] = h2pack(v.x, v.y);
    }
}

// ===================== fp16 GEMM, cp.async 3-stage pipeline ==========
#define NCHUNK 32            // 1024 / 32
#define PADh 20              // 16 k-pair words + 4 pad
#define STGW (2 * 128 * PADh)        // words per stage (A+B)
#define GEMM_SMEM (3 * STGW * 4)     // 61440 B

__global__ __launch_bounds__(256)
void gemm_mma_fp16(const uint32_t* __restrict__ A, const uint32_t* __restrict__ B,
                   float* __restrict__ C, int N) {
    extern __shared__ uint32_t smg[];

    const int tid = threadIdx.x;
    const int wid = tid >> 5, lane = tid & 31;
    const int grp = lane >> 2, qd = lane & 3;
    const int wm = wid >> 1, wn = wid & 1;
    const int m0 = blockIdx.y * 128;
    const int n0 = blockIdx.x * 128;

    const uint32_t sb = (uint32_t)__cvta_generic_to_shared(smg);
    const int cr = tid >> 2;
    const int cc = tid & 3;

    float acc[2][8][4];
    #pragma unroll
    for (int i = 0; i < 2; i++)
        #pragma unroll
        for (int j = 0; j < 8; j++)
            #pragma unroll
            for (int q = 0; q < 4; q++) acc[i][j][q] = 0.f;

    #define GEMM_ISSUE(ic) do {                                              \
        uint32_t base = sb + ((ic) % 3) * STGW * 4;                          \
        _Pragma("unroll")                                                    \
        for (int i_ = 0; i_ < 2; i_++) {                                     \
            int r_ = cr + i_ * 64;                                           \
            uint32_t doff = (r_ * PADh + cc * 4) * 4;                        \
            cp16(base + doff,                                                \
                 A + (size_t)(m0 + r_) * KW + (ic) * 16 + cc * 4);           \
            cp16(base + 128 * PADh * 4 + doff,                               \
                 B + (size_t)(n0 + r_) * KW + (ic) * 16 + cc * 4);           \
        }                                                                    \
        cp_commit();                                                         \
    } while (0)

    GEMM_ISSUE(0);

    for (int ic = 0; ic < NCHUNK; ic++) {
        if (ic + 1 < NCHUNK) {
            GEMM_ISSUE(ic + 1);
            asm volatile("cp.async.wait_group 1;" ::: "memory");
        } else {
            cp_wait_all();
        }
        __syncthreads();

        const uint32_t* Ab = smg + (ic % 3) * STGW;
        const uint32_t* Bb = Ab + 128 * PADh;
        #pragma unroll
        for (int ks = 0; ks < 2; ks++) {
            int kw = ks * 8 + qd;
            uint32_t af[2][4];
            #pragma unroll
            for (int mt = 0; mt < 2; mt++) {
                int r = wm * 32 + mt * 16 + grp;
                af[mt][0] = Ab[r * PADh + kw];
                af[mt][1] = Ab[(r + 8) * PADh + kw];
                af[mt][2] = Ab[r * PADh + kw + 4];
                af[mt][3] = Ab[(r + 8) * PADh + kw + 4];
            }
            #pragma unroll
            for (int nt = 0; nt < 8; nt++) {
                int c = wn * 64 + nt * 8 + grp;
                uint32_t b0 = Bb[c * PADh + kw];
                uint32_t b1 = Bb[c * PADh + kw + 4];
                mma16816h(acc[0][nt], af[0][0], af[0][1], af[0][2], af[0][3], b0, b1);
                mma16816h(acc[1][nt], af[1][0], af[1][1], af[1][2], af[1][3], b0, b1);
            }
        }
    }

    #pragma unroll
    for (int mt = 0; mt < 2; mt++) {
        #pragma unroll
        for (int nt = 0; nt < 8; nt++) {
            int r = m0 + wm * 32 + mt * 16 + grp;
            int c = n0 + wn * 64 + nt * 8 + qd * 2;
            *(float2*)(C + (size_t)r * N + c) =
                make_float2(acc[mt][nt][0], acc[mt][nt][1]);
            *(float2*)(C + (size_t)(r + 8) * N + c) =
                make_float2(acc[mt][nt][2], acc[mt][nt][3]);
        }
    }
}

// ---------------- block reduction helper (256 threads) ----------------
__device__ __forceinline__ void block_reduce4(float& a, float& b, float& c, float& d) {
    #pragma unroll
    for (int o = 16; o; o >>= 1) {
        a += __shfl_xor_sync(0xffffffffu, a, o);
        b += __shfl_xor_sync(0xffffffffu, b, o);
        c += __shfl_xor_sync(0xffffffffu, c, o);
        d += __shfl_xor_sync(0xffffffffu, d, o);
    }
    __shared__ float s[4][8];
    int w = threadIdx.x >> 5, lane = threadIdx.x & 31;
    if (lane == 0) { s[0][w] = a; s[1][w] = b; s[2][w] = c; s[3][w] = d; }
    __syncthreads();
    a = b = c = d = 0.f;
    #pragma unroll
    for (int i = 0; i < 8; i++) { a += s[0][i]; b += s[1][i]; c += s[2][i]; d += s[3][i]; }
    __syncthreads();
}

// ---------------- kernel 0: RoPE cos/sin table ----------------
__global__ void rope_table_kernel() {
    int idx = blockIdx.x * 256 + threadIdx.x;
    if (idx >= LL * 32) return;
    int l = idx >> 5, fi = idx & 31;
    float invf = powf(10000.0f, -((float)(2 * fi)) / 64.0f);
    float ang  = (float)l * invf;
    g_cs[idx] = make_float2(cosf(ang), sinf(ang));
}

// ---------------- kernel 1: LN1 (fp16 word output) ----------------
__global__ void ln1_kernel(const float* __restrict__ x,
                           const float* __restrict__ w,
                           const float* __restrict__ bia) {
    int t = blockIdx.x;
    int tid = threadIdx.x;
    const float4* xr = (const float4*)(x + (size_t)t * DD);
    float4 v = xr[tid];
    float s  = v.x + v.y + v.z + v.w;
    float ss = v.x*v.x + v.y*v.y + v.z*v.z + v.w*v.w;
    float z0 = 0.f, z1 = 0.f;
    block_reduce4(s, ss, z0, z1);
    float mu  = s * (1.0f / DD);
    float var = ss * (1.0f / DD) - mu * mu;
    float inv = rsqrtf(var + EPS);
    float4 wv = ((const float4*)w)[tid];
    float4 bv = ((const float4*)bia)[tid];
    float4 o;
    o.x = (v.x - mu) * inv * wv.x + bv.x;
    o.y = (v.y - mu) * inv * wv.y + bv.y;
    o.z = (v.z - mu) * inv * wv.z + bv.z;
    o.w = (v.w - mu) * inv * wv.w + bv.w;
    *(uint2*)(g_hh + (size_t)t * KW + tid * 2) =
        make_uint2(h2pack(o.x, o.y), h2pack(o.z, o.w));
}

// ---------------- kernel 3: QK LN + RoPE (table) + pre-split bf16 planes --------
// V no longer copied here; vtrans reads it straight from g_qkv.
__global__ void qk_rope_kernel(const float* __restrict__ qw,
                               const float* __restrict__ kw) {
    int t = blockIdx.x;
    int b = t >> 11;
    int l = t & 2047;
    int tid = threadIdx.x;
    const float4* row = (const float4*)(g_qkv + (size_t)t * 3 * DD);
    float4 q = row[tid];
    float4 k = row[256 + tid];

    float qs  = q.x + q.y + q.z + q.w;
    float qss = q.x*q.x + q.y*q.y + q.z*q.z + q.w*q.w;
    float ks  = k.x + k.y + k.z + k.w;
    float kss = k.x*k.x + k.y*k.y + k.z*k.z + k.w*k.w;
    block_reduce4(qs, qss, ks, kss);
    float muq = qs * (1.0f / DD);
    float vq  = qss * (1.0f / DD) - muq * muq;
    float iq  = rsqrtf(vq + EPS);
    float muk = ks * (1.0f / DD);
    float vk  = kss * (1.0f / DD) - muk * muk;
    float ik  = rsqrtf(vk + EPS);

    __shared__ float qn[DD];
    __shared__ float kn[DD];
    float4 qwv = ((const float4*)qw)[tid];
    float4 kwv = ((const float4*)kw)[tid];
    int d0 = tid * 4;
    qn[d0+0] = (q.x - muq) * iq * qwv.x;
    qn[d0+1] = (q.y - muq) * iq * qwv.y;
    qn[d0+2] = (q.z - muq) * iq * qwv.z;
    qn[d0+3] = (q.w - muq) * iq * qwv.w;
    kn[d0+0] = (k.x - muk) * ik * kwv.x;
    kn[d0+1] = (k.y - muk) * ik * kwv.y;
    kn[d0+2] = (k.z - muk) * ik * kwv.z;
    kn[d0+3] = (k.w - muk) * ik * kwv.w;
    __syncthreads();

    int h   = d0 >> 6;
    int dh0 = d0 & 63;
    float oq[4], ok[4];
    #pragma unroll
    for (int j = 0; j < 4; j++) {
        int dh = dh0 + j;
        int fi = dh & 31;
        float2 cs = g_cs[l * 32 + fi];
        float c = cs.x, s = cs.y;
        float qv = qn[d0 + j];
        float kv = kn[d0 + j];
        float qp = (dh < 32) ? -qn[d0 + j + 32] : qn[d0 + j - 32];
        float kp = (dh < 32) ? -kn[d0 + j + 32] : kn[d0 + j - 32];
        oq[j] = (qv * c + qp * s) * 0.125f;   // fold 1/sqrt(DH) exactly
        ok[j] = kv * c + kp * s;
    }
    size_t pb = ((size_t)(b * HH + h) * LL + l) * 32 + (dh0 >> 1);
    uint32_t h0, l0, h1, l1;
    bfsplit(oq[0], oq[1], h0, l0);
    bfsplit(oq[2], oq[3], h1, l1);
    g_qh[pb] = h0; g_qh[pb + 1] = h1;
    g_ql[pb] = l0; g_ql[pb + 1] = l1;
    bfsplit(ok[0], ok[1], h0, l0);
    bfsplit(ok[2], ok[3], h1, l1);
    g_kh[pb] = h0; g_kh[pb + 1] = h1;
    g_kl[pb] = l0; g_kl[pb + 1] = l1;
}

// ---------------- kernel 3b: V transpose (from g_qkv) -> fp16 plane -------------
__global__ void vtrans_kernel() {
    __shared__ float vs[64 * 65];   // [l][d], pad 65
    const int kt = blockIdx.x, bh = blockIdx.y;
    const int b = bh >> 4, h = bh & 15;
    const int tid = threadIdx.x;
    const float* Vg = g_qkv + ((size_t)(b * LL + kt * 64)) * 3 * DD + 2 * DD + h * 64;
    #pragma unroll
    for (int i = 0; i < 8; i++) {
        int idx = tid + i * 128;
        int l = idx >> 4, c4 = idx & 15;
        float4 v = *(const float4*)(Vg + (size_t)l * 3 * DD + c4 * 4);
        vs[l * 65 + c4 * 4 + 0] = v.x;
        vs[l * 65 + c4 * 4 + 1] = v.y;
        vs[l * 65 + c4 * 4 + 2] = v.z;
        vs[l * 65 + c4 * 4 + 3] = v.w;
    }
    __syncthreads();
    size_t base = ((size_t)bh * 32 + kt) * 64 * 32;
    #pragma unroll
    for (int i = 0; i < 16; i++) {
        int idx = tid + i * 128;
        int d = idx >> 5, lp = idx & 31;
        g_vtf[base + d * 32 + lp] =
            h2pack(vs[(2 * lp) * 65 + d], vs[(2 * lp + 1) * 65 + d]);
    }
}

// ---------------- kernel 4: flash attention ----
// S: bf16 split-3 (fp32-equivalent). PV: single fp16 MMA (P,V 2^-12 rounding).
#define AW 36
#define ATTN_SMEM (5 * 64 * AW * 4)   // 46080 B

__global__ __launch_bounds__(128, 4)
void attn_kernel(const int* __restrict__ seq_id) {
    extern __shared__ uint32_t smw[];
    uint32_t* Qh  = smw;                // [64][AW]
    uint32_t* Ql  = Qh  + 64 * AW;
    uint32_t* KPh = Ql  + 64 * AW;      // K hi (then P fp16)
    uint32_t* KPl = KPh + 64 * AW;      // K lo
    uint32_t* VTf = KPl + 64 * AW;      // V^T fp16
    __shared__ int kseq[64];

    const int bh = blockIdx.x, qt = blockIdx.y;   // transposed grid: wave leveling
    const int b = bh >> 4, hh = bh & 15;
    const int tid = threadIdx.x;
    const int w = tid >> 5, lane = tid & 31;
    const int grp = lane >> 2, qd = lane & 3;

    const int qbase = b * LL + qt * 64;
    const int qmin = seq_id[qbase];
    const int qmax = seq_id[qbase + 63];

    const uint32_t sb = (uint32_t)__cvta_generic_to_shared(smw);
    const uint32_t sQh = sb, sQl = sb + 64 * AW * 4;
    const uint32_t sKPh = sQl + 64 * AW * 4, sKPl = sKPh + 64 * AW * 4;
    const uint32_t sVTf = sKPl + 64 * AW * 4;

    // stage Q hi/lo via cp.async
    {
        const size_t qrow = ((size_t)bh * LL + qt * 64) * 32;
        #pragma unroll
        for (int i = 0; i < 4; i++) {
            int idx = tid + i * 128;
            int r = idx >> 3, c = idx & 7;
            cp16(sQh + (r * AW + c * 4) * 4, g_qh + qrow + r * 32 + c * 4);
        }
        #pragma unroll
        for (int i = 0; i < 4; i++) {
            int idx = tid + i * 128;
            int r = idx >> 3, c = idx & 7;
            cp16(sQl + (r * AW + c * 4) * 4, g_ql + qrow + r * 32 + c * 4);
        }
        cp_commit();
    }
    const int row0 = w * 16 + grp, row1 = row0 + 8;
    const int qs0 = seq_id[qbase + row0];
    const int qs1 = seq_id[qbase + row1];

    float m0 = -1e30f, m1 = -1e30f, l0s = 0.f, l1s = 0.f;
    float O[8][4];
    #pragma unroll
    for (int dt = 0; dt < 8; dt++)
        #pragma unroll
        for (int q = 0; q < 4; q++) O[dt][q] = 0.f;

    for (int kt = 0; kt < LL / 64; kt++) {
        const int kb = b * LL + kt * 64;
        if (seq_id[kb + 63] < qmin || seq_id[kb] > qmax) continue;  // exact no-op tile

        __syncthreads();
        // stage K hi/lo + V^T fp16 via cp.async
        {
            const size_t krow = ((size_t)bh * LL + kt * 64) * 32;
            const size_t vbase = ((size_t)bh * 32 + kt) * 64 * 32;
            #pragma unroll
            for (int i = 0; i < 4; i++) {
                int idx = tid + i * 128;
                int r = idx >> 3, c = idx & 7;
                cp16(sKPh + (r * AW + c * 4) * 4, g_kh + krow + r * 32 + c * 4);
            }
            #pragma unroll
            for (int i = 0; i < 4; i++) {
                int idx = tid + i * 128;
                int r = idx >> 3, c = idx & 7;
                cp16(sKPl + (r * AW + c * 4) * 4, g_kl + krow + r * 32 + c * 4);
            }
            #pragma unroll
            for (int i = 0; i < 4; i++) {
                int idx = tid + i * 128;
                int r = idx >> 3, c = idx & 7;
                cp16(sVTf + (r * AW + c * 4) * 4, g_vtf + vbase + r * 32 + c * 4);
            }
            cp_commit();
        }
        if (tid < 64) kseq[tid] = seq_id[kb + tid];
        cp_wait_all();
        __syncthreads();

        // ---- S = Q K^T (bf16 3-term split) ----
        float S[8][4];
        #pragma unroll
        for (int nt = 0; nt < 8; nt++)
            #pragma unroll
            for (int q = 0; q < 4; q++) S[nt][q] = 0.f;
        #pragma unroll
        for (int ks = 0; ks < 4; ks++) {
            int r0w = (w * 16 + grp) * AW, r1w = (w * 16 + grp + 8) * AW;
            int kw0 = ks * 8 + qd;
            uint32_t ah0 = Qh[r0w + kw0],     ah1 = Qh[r1w + kw0];
            uint32_t ah2 = Qh[r0w + kw0 + 4], ah3 = Qh[r1w + kw0 + 4];
            uint32_t al0 = Ql[r0w + kw0],     al1 = Ql[r1w + kw0];
            uint32_t al2 = Ql[r0w + kw0 + 4], al3 = Ql[r1w + kw0 + 4];
            #pragma unroll
            for (int nt = 0; nt < 8; nt++) {
                int nw = (nt * 8 + grp) * AW;
                uint32_t bh0 = KPh[nw + kw0], bh1 = KPh[nw + kw0 + 4];
                uint32_t bl0 = KPl[nw + kw0], bl1 = KPl[nw + kw0 + 4];
                mma16816(S[nt], ah0, ah1, ah2, ah3, bh0, bh1);
                mma16816(S[nt], ah0, ah1, ah2, ah3, bl0, bl1);
                mma16816(S[nt], al0, al1, al2, al3, bh0, bh1);
            }
        }

        // ---- mask ----
        #pragma unroll
        for (int nt = 0; nt < 8; nt++) {
            int c0 = kseq[nt * 8 + 2 * qd];
            int c1 = kseq[nt * 8 + 2 * qd + 1];
            if (c0 != qs0) S[nt][0] = -1e30f;
            if (c1 != qs0) S[nt][1] = -1e30f;
            if (c0 != qs1) S[nt][2] = -1e30f;
            if (c1 != qs1) S[nt][3] = -1e30f;
        }

        // ---- online softmax ----
        float mx0 = -1e30f, mx1 = -1e30f;
        #pragma unroll
        for (int nt = 0; nt < 8; nt++) {
            mx0 = fmaxf(mx0, fmaxf(S[nt][0], S[nt][1]));
            mx1 = fmaxf(mx1, fmaxf(S[nt][2], S[nt][3]));
        }
        mx0 = fmaxf(mx0, __shfl_xor_sync(0xffffffffu, mx0, 1));
        mx0 = fmaxf(mx0, __shfl_xor_sync(0xffffffffu, mx0, 2));
        mx1 = fmaxf(mx1, __shfl_xor_sync(0xffffffffu, mx1, 1));
        mx1 = fmaxf(mx1, __shfl_xor_sync(0xffffffffu, mx1, 2));
        float mn0 = fmaxf(m0, mx0), mn1 = fmaxf(m1, mx1);
        float sc0 = __expf(m0 - mn0), sc1 = __expf(m1 - mn1);
        m0 = mn0; m1 = mn1;
        float s0 = 0.f, s1 = 0.f;
        #pragma unroll
        for (int nt = 0; nt < 8; nt++) {
            S[nt][0] = __expf(S[nt][0] - mn0);
            S[nt][1] = __expf(S[nt][1] - mn0);
            S[nt][2] = __expf(S[nt][2] - mn1);
            S[nt][3] = __expf(S[nt][3] - mn1);
            s0 += S[nt][0] + S[nt][1];
            s1 += S[nt][2] + S[nt][3];
        }
        s0 += __shfl_xor_sync(0xffffffffu, s0, 1);
        s0 += __shfl_xor_sync(0xffffffffu, s0, 2);
        s1 += __shfl_xor_sync(0xffffffffu, s1, 1);
        s1 += __shfl_xor_sync(0xffffffffu, s1, 2);
        l0s = l0s * sc0 + s0;
        l1s = l1s * sc1 + s1;
        #pragma unroll
        for (int dt = 0; dt < 8; dt++) {
            O[dt][0] *= sc0; O[dt][1] *= sc0;
            O[dt][2] *= sc1; O[dt][3] *= sc1;
        }

        __syncthreads();   // all K fragment reads done before P overwrite
        // ---- write P as single fp16 plane into KPh ----
        #pragma unroll
        for (int nt = 0; nt < 8; nt++) {
            KPh[(w * 16 + grp) * AW + nt * 4 + qd]     = h2pack(S[nt][0], S[nt][1]);
            KPh[(w * 16 + grp + 8) * AW + nt * 4 + qd] = h2pack(S[nt][2], S[nt][3]);
        }
        __syncthreads();

        // ---- O += P V (single fp16 MMA) ----
        #pragma unroll
        for (int ks = 0; ks < 4; ks++) {
            int r0w = (w * 16 + grp) * AW, r1w = (w * 16 + grp + 8) * AW;
            int kw0 = ks * 8 + qd;
            uint32_t a0 = KPh[r0w + kw0], a1 = KPh[r1w + kw0];
            uint32_t a2 = KPh[r0w + kw0 + 4], a3 = KPh[r1w + kw0 + 4];
            #pragma unroll
            for (int dt = 0; dt < 8; dt++) {
                int dw = (dt * 8 + grp) * AW;
                mma16816h(O[dt], a0, a1, a2, a3, VTf[dw + kw0], VTf[dw + kw0 + 4]);
            }
        }
    }

    // epilogue: fp16 ctx words (same rounding the out-proj would apply)
    float inv0 = 1.0f / l0s, inv1 = 1.0f / l1s;
    const int t0 = b * LL + qt * 64 + row0;
    const int t1 = b * LL + qt * 64 + row1;
    #pragma unroll
    for (int dt = 0; dt < 8; dt++) {
        int c = hh * DHH + dt * 8 + 2 * qd;
        g_ctx16[(size_t)t0 * KW + (c >> 1)] =
            h2pack(O[dt][0] * inv0, O[dt][1] * inv0);
        g_ctx16[(size_t)t1 * KW + (c >> 1)] =
            h2pack(O[dt][2] * inv1, O[dt][3] * inv1);
    }
}

// ---------------- launch ----------------
extern "C" void kernel_launch(void* const* d_in, const int* in_sizes, int n_in,
                              void* d_out, int out_size) {
    const float* x     = (const float*)d_in[0];
    const int*   seq   = (const int*)  d_in[1];
    const float* ln1w  = (const float*)d_in[2];
    const float* ln1b  = (const float*)d_in[3];
    const float* wqkv  = (const float*)d_in[4];
    const float* qlnw  = (const float*)d_in[5];
    const float* klnw  = (const float*)d_in[6];
    const float* outw  = (const float*)d_in[7];
    float* out = (float*)d_out;

    void *phh, *pqkv, *pw16, *po16, *pctx16;
    cudaGetSymbolAddress(&phh, g_hh);
    cudaGetSymbolAddress(&pqkv, g_qkv);
    cudaGetSymbolAddress(&pw16, g_wqkv16);
    cudaGetSymbolAddress(&po16, g_outw16);
    cudaGetSymbolAddress(&pctx16, g_ctx16);

    cudaFuncSetAttribute(gemm_mma_fp16, cudaFuncAttributeMaxDynamicSharedMemorySize, GEMM_SMEM);
    cudaFuncSetAttribute(attn_kernel, cudaFuncAttributeMaxDynamicSharedMemorySize, ATTN_SMEM);

    // 0) RoPE table + weight conversions
    rope_table_kernel<<<(LL * 32 + 255) / 256, 256>>>();
    cvt16_kernel<<<(3 * DD * KW + 255) / 256, 256>>>(wqkv, (uint32_t*)pw16, 3 * DD * KW);
    cvt16_kernel<<<(DD * KW + 255) / 256, 256>>>(outw, (uint32_t*)po16, DD * KW);

    // 1) LN1 -> fp16 words
    ln1_kernel<<<TT, 256>>>(x, ln1w, ln1b);

    // 2) QKV GEMM (fp16 operands, cp.async 3-stage)
    gemm_mma_fp16<<<dim3(3 * DD / 128, TT / 128), 256, GEMM_SMEM>>>(
        (const uint32_t*)phh, (const uint32_t*)pw16, (float*)pqkv, 3 * DD);

    // 3) QK LN + RoPE (table) -> pre-split planes
    qk_rope_kernel<<<TT, 256>>>(qlnw, klnw);

    // 3b) V transpose (from g_qkv) -> fp16 plane
    vtrans_kernel<<<dim3(32, NBH), 128>>>();

    // 4) attention (tile-skip + S split3-bf16 + PV single-fp16)
    attn_kernel<<<dim3(NBH, LL / 64), 128, ATTN_SMEM>>>(seq);

    // 5) output projection (fp16 operands, cp.async 3-stage)
    gemm_mma_fp16<<<dim3(DD / 128, TT / 128), 256, GEMM_SMEM>>>(
        (const uint32_t*)pctx16, (const uint32_t*)po16, out, DD);
}

// round 12
// speedup vs baseline: 2.5923x; 1.0922x over previous
#include <cuda_runtime.h>
#include <cuda_bf16.h>
#include <cuda_fp16.h>
#include <cstdint>
#include <math.h>

// Problem constants
#define BB 2
#define LL 2048
#define DD 1024
#define HH 16
#define DHH 64
#define TT (BB*LL)          // 4096 tokens
#define EPS 1e-5f
#define NBH (BB*HH)         // 32
#define KW 512              // k-pair words per row (GK/2)

// -------- scratch (device globals: allocation-free rule) --------
__device__ float g_qkv[TT * 3 * DD];      // QKV GEMM output (fp32, LN needs it)
__device__ float2 g_cs[LL * 32];          // RoPE cos/sin table [l][fi]
// fp16 operand planes for projection GEMMs (half2 k-pair words)
__device__ __align__(16) uint32_t g_hh[TT * KW];        // LN1 out, fp16
__device__ __align__(16) uint32_t g_wqkv16[3 * DD * KW];
__device__ __align__(16) uint32_t g_outw16[DD * KW];
__device__ __align__(16) uint32_t g_ctx16[TT * KW];     // attention out, fp16
// fp16 Q/K planes, word = half2 of adjacent head-dims: [bh][l][32 words]
__device__ __align__(16) uint32_t g_qf[NBH * LL * 32];
__device__ __align__(16) uint32_t g_kf[NBH * LL * 32];
// fp16 transposed V tiles: [bh][kt(32)][d(64)][32 l-pair words]
__device__ __align__(16) uint32_t g_vtf[NBH * 32 * 64 * 32];

__device__ __forceinline__ uint32_t h2pack(float a, float b) {
    __half2 t = __floats2half2_rn(a, b);
    return *reinterpret_cast<uint32_t*>(&t);
}
// fp16 m16n8k16 (all tensor paths)
__device__ __forceinline__ void mma16816h(float* c, uint32_t a0, uint32_t a1,
                                          uint32_t a2, uint32_t a3,
                                          uint32_t b0, uint32_t b1) {
    asm volatile(
        "mma.sync.aligned.m16n8k16.row.col.f32.f16.f16.f32 "
        "{%0,%1,%2,%3}, {%4,%5,%6,%7}, {%8,%9}, {%0,%1,%2,%3};"
        : "+f"(c[0]), "+f"(c[1]), "+f"(c[2]), "+f"(c[3])
        : "r"(a0), "r"(a1), "r"(a2), "r"(a3), "r"(b0), "r"(b1));
}

__device__ __forceinline__ void cp16(uint32_t dst, const void* src) {
    asm volatile("cp.async.ca.shared.global [%0], [%1], 16;"
                 :: "r"(dst), "l"(src));
}
__device__ __forceinline__ void cp_commit() {
    asm volatile("cp.async.commit_group;");
}
__device__ __forceinline__ void cp_wait_all() {
    asm volatile("cp.async.wait_all;" ::: "memory");
}

// ---------------- fp32 -> fp16-words conversion ----------------
__global__ void cvt16_kernel(const float* __restrict__ in,
                             uint32_t* __restrict__ out, int nwords) {
    int i = blockIdx.x * 256 + threadIdx.x;
    if (i < nwords) {
        float2 v = ((const float2*)in)[i];
        out[i] = h2pack(v.x, v.y);
    }
}

// ===================== fp16 GEMM, cp.async 3-stage pipeline ==========
#define NCHUNK 32            // 1024 / 32
#define PADh 20              // 16 k-pair words + 4 pad
#define STGW (2 * 128 * PADh)        // words per stage (A+B)
#define GEMM_SMEM (3 * STGW * 4)     // 61440 B

__global__ __launch_bounds__(256)
void gemm_mma_fp16(const uint32_t* __restrict__ A, const uint32_t* __restrict__ B,
                   float* __restrict__ C, int N) {
    extern __shared__ uint32_t smg[];

    const int tid = threadIdx.x;
    const int wid = tid >> 5, lane = tid & 31;
    const int grp = lane >> 2, qd = lane & 3;
    const int wm = wid >> 1, wn = wid & 1;
    const int m0 = blockIdx.y * 128;
    const int n0 = blockIdx.x * 128;

    const uint32_t sb = (uint32_t)__cvta_generic_to_shared(smg);
    const int cr = tid >> 2;
    const int cc = tid & 3;

    float acc[2][8][4];
    #pragma unroll
    for (int i = 0; i < 2; i++)
        #pragma unroll
        for (int j = 0; j < 8; j++)
            #pragma unroll
            for (int q = 0; q < 4; q++) acc[i][j][q] = 0.f;

    #define GEMM_ISSUE(ic) do {                                              \
        uint32_t base = sb + ((ic) % 3) * STGW * 4;                          \
        _Pragma("unroll")                                                    \
        for (int i_ = 0; i_ < 2; i_++) {                                     \
            int r_ = cr + i_ * 64;                                           \
            uint32_t doff = (r_ * PADh + cc * 4) * 4;                        \
            cp16(base + doff,                                                \
                 A + (size_t)(m0 + r_) * KW + (ic) * 16 + cc * 4);           \
            cp16(base + 128 * PADh * 4 + doff,                               \
                 B + (size_t)(n0 + r_) * KW + (ic) * 16 + cc * 4);           \
        }                                                                    \
        cp_commit();                                                         \
    } while (0)

    GEMM_ISSUE(0);

    for (int ic = 0; ic < NCHUNK; ic++) {
        if (ic + 1 < NCHUNK) {
            GEMM_ISSUE(ic + 1);
            asm volatile("cp.async.wait_group 1;" ::: "memory");
        } else {
            cp_wait_all();
        }
        __syncthreads();

        const uint32_t* Ab = smg + (ic % 3) * STGW;
        const uint32_t* Bb = Ab + 128 * PADh;
        #pragma unroll
        for (int ks = 0; ks < 2; ks++) {
            int kw = ks * 8 + qd;
            uint32_t af[2][4];
            #pragma unroll
            for (int mt = 0; mt < 2; mt++) {
                int r = wm * 32 + mt * 16 + grp;
                af[mt][0] = Ab[r * PADh + kw];
                af[mt][1] = Ab[(r + 8) * PADh + kw];
                af[mt][2] = Ab[r * PADh + kw + 4];
                af[mt][3] = Ab[(r + 8) * PADh + kw + 4];
            }
            #pragma unroll
            for (int nt = 0; nt < 8; nt++) {
                int c = wn * 64 + nt * 8 + grp;
                uint32_t b0 = Bb[c * PADh + kw];
                uint32_t b1 = Bb[c * PADh + kw + 4];
                mma16816h(acc[0][nt], af[0][0], af[0][1], af[0][2], af[0][3], b0, b1);
                mma16816h(acc[1][nt], af[1][0], af[1][1], af[1][2], af[1][3], b0, b1);
            }
        }
    }

    #pragma unroll
    for (int mt = 0; mt < 2; mt++) {
        #pragma unroll
        for (int nt = 0; nt < 8; nt++) {
            int r = m0 + wm * 32 + mt * 16 + grp;
            int c = n0 + wn * 64 + nt * 8 + qd * 2;
            *(float2*)(C + (size_t)r * N + c) =
                make_float2(acc[mt][nt][0], acc[mt][nt][1]);
            *(float2*)(C + (size_t)(r + 8) * N + c) =
                make_float2(acc[mt][nt][2], acc[mt][nt][3]);
        }
    }
}

// ---------------- block reduction helper (256 threads) ----------------
__device__ __forceinline__ void block_reduce4(float& a, float& b, float& c, float& d) {
    #pragma unroll
    for (int o = 16; o; o >>= 1) {
        a += __shfl_xor_sync(0xffffffffu, a, o);
        b += __shfl_xor_sync(0xffffffffu, b, o);
        c += __shfl_xor_sync(0xffffffffu, c, o);
        d += __shfl_xor_sync(0xffffffffu, d, o);
    }
    __shared__ float s[4][8];
    int w = threadIdx.x >> 5, lane = threadIdx.x & 31;
    if (lane == 0) { s[0][w] = a; s[1][w] = b; s[2][w] = c; s[3][w] = d; }
    __syncthreads();
    a = b = c = d = 0.f;
    #pragma unroll
    for (int i = 0; i < 8; i++) { a += s[0][i]; b += s[1][i]; c += s[2][i]; d += s[3][i]; }
    __syncthreads();
}

// ---------------- kernel 0: RoPE cos/sin table ----------------
__global__ void rope_table_kernel() {
    int idx = blockIdx.x * 256 + threadIdx.x;
    if (idx >= LL * 32) return;
    int l = idx >> 5, fi = idx & 31;
    float invf = powf(10000.0f, -((float)(2 * fi)) / 64.0f);
    float ang  = (float)l * invf;
    g_cs[idx] = make_float2(cosf(ang), sinf(ang));
}

// ---------------- kernel 1: LN1 (fp16 word output) ----------------
__global__ void ln1_kernel(const float* __restrict__ x,
                           const float* __restrict__ w,
                           const float* __restrict__ bia) {
    int t = blockIdx.x;
    int tid = threadIdx.x;
    const float4* xr = (const float4*)(x + (size_t)t * DD);
    float4 v = xr[tid];
    float s  = v.x + v.y + v.z + v.w;
    float ss = v.x*v.x + v.y*v.y + v.z*v.z + v.w*v.w;
    float z0 = 0.f, z1 = 0.f;
    block_reduce4(s, ss, z0, z1);
    float mu  = s * (1.0f / DD);
    float var = ss * (1.0f / DD) - mu * mu;
    float inv = rsqrtf(var + EPS);
    float4 wv = ((const float4*)w)[tid];
    float4 bv = ((const float4*)bia)[tid];
    float4 o;
    o.x = (v.x - mu) * inv * wv.x + bv.x;
    o.y = (v.y - mu) * inv * wv.y + bv.y;
    o.z = (v.z - mu) * inv * wv.z + bv.z;
    o.w = (v.w - mu) * inv * wv.w + bv.w;
    *(uint2*)(g_hh + (size_t)t * KW + tid * 2) =
        make_uint2(h2pack(o.x, o.y), h2pack(o.z, o.w));
}

// ---------------- kernel 3: QK LN + RoPE (table) -> fp16 planes ----------------
__global__ void qk_rope_kernel(const float* __restrict__ qw,
                               const float* __restrict__ kw) {
    int t = blockIdx.x;
    int b = t >> 11;
    int l = t & 2047;
    int tid = threadIdx.x;
    const float4* row = (const float4*)(g_qkv + (size_t)t * 3 * DD);
    float4 q = row[tid];
    float4 k = row[256 + tid];

    float qs  = q.x + q.y + q.z + q.w;
    float qss = q.x*q.x + q.y*q.y + q.z*q.z + q.w*q.w;
    float ks  = k.x + k.y + k.z + k.w;
    float kss = k.x*k.x + k.y*k.y + k.z*k.z + k.w*k.w;
    block_reduce4(qs, qss, ks, kss);
    float muq = qs * (1.0f / DD);
    float vq  = qss * (1.0f / DD) - muq * muq;
    float iq  = rsqrtf(vq + EPS);
    float muk = ks * (1.0f / DD);
    float vk  = kss * (1.0f / DD) - muk * muk;
    float ik  = rsqrtf(vk + EPS);

    __shared__ float qn[DD];
    __shared__ float kn[DD];
    float4 qwv = ((const float4*)qw)[tid];
    float4 kwv = ((const float4*)kw)[tid];
    int d0 = tid * 4;
    qn[d0+0] = (q.x - muq) * iq * qwv.x;
    qn[d0+1] = (q.y - muq) * iq * qwv.y;
    qn[d0+2] = (q.z - muq) * iq * qwv.z;
    qn[d0+3] = (q.w - muq) * iq * qwv.w;
    kn[d0+0] = (k.x - muk) * ik * kwv.x;
    kn[d0+1] = (k.y - muk) * ik * kwv.y;
    kn[d0+2] = (k.z - muk) * ik * kwv.z;
    kn[d0+3] = (k.w - muk) * ik * kwv.w;
    __syncthreads();

    int h   = d0 >> 6;
    int dh0 = d0 & 63;
    float oq[4], ok[4];
    #pragma unroll
    for (int j = 0; j < 4; j++) {
        int dh = dh0 + j;
        int fi = dh & 31;
        float2 cs = g_cs[l * 32 + fi];
        float c = cs.x, s = cs.y;
        float qv = qn[d0 + j];
        float kv = kn[d0 + j];
        float qp = (dh < 32) ? -qn[d0 + j + 32] : qn[d0 + j - 32];
        float kp = (dh < 32) ? -kn[d0 + j + 32] : kn[d0 + j - 32];
        oq[j] = (qv * c + qp * s) * 0.125f;   // fold 1/sqrt(DH) exactly
        ok[j] = kv * c + kp * s;
    }
    size_t pb = ((size_t)(b * HH + h) * LL + l) * 32 + (dh0 >> 1);
    *(uint2*)(g_qf + pb) = make_uint2(h2pack(oq[0], oq[1]), h2pack(oq[2], oq[3]));
    *(uint2*)(g_kf + pb) = make_uint2(h2pack(ok[0], ok[1]), h2pack(ok[2], ok[3]));
}

// ---------------- kernel 3b: V transpose (from g_qkv) -> fp16 plane -------------
__global__ void vtrans_kernel() {
    __shared__ float vs[64 * 65];   // [l][d], pad 65
    const int kt = blockIdx.x, bh = blockIdx.y;
    const int b = bh >> 4, h = bh & 15;
    const int tid = threadIdx.x;
    const float* Vg = g_qkv + ((size_t)(b * LL + kt * 64)) * 3 * DD + 2 * DD + h * 64;
    #pragma unroll
    for (int i = 0; i < 8; i++) {
        int idx = tid + i * 128;
        int l = idx >> 4, c4 = idx & 15;
        float4 v = *(const float4*)(Vg + (size_t)l * 3 * DD + c4 * 4);
        vs[l * 65 + c4 * 4 + 0] = v.x;
        vs[l * 65 + c4 * 4 + 1] = v.y;
        vs[l * 65 + c4 * 4 + 2] = v.z;
        vs[l * 65 + c4 * 4 + 3] = v.w;
    }
    __syncthreads();
    size_t base = ((size_t)bh * 32 + kt) * 64 * 32;
    #pragma unroll
    for (int i = 0; i < 16; i++) {
        int idx = tid + i * 128;
        int d = idx >> 5, lp = idx & 31;
        g_vtf[base + d * 32 + lp] =
            h2pack(vs[(2 * lp) * 65 + d], vs[(2 * lp + 1) * 65 + d]);
    }
}

// ---------------- kernel 4: flash attention, all-fp16 MMA ----
#define AW 36
#define ATTN_SMEM (3 * 64 * AW * 4)   // 27648 B

__global__ __launch_bounds__(128, 4)
void attn_kernel(const int* __restrict__ seq_id) {
    extern __shared__ uint32_t smw[];
    uint32_t* Qf  = smw;                // [64][AW]
    uint32_t* KPf = Qf  + 64 * AW;      // K (then P)
    uint32_t* VTf = KPf + 64 * AW;      // V^T
    __shared__ int kseq[64];

    const int bh = blockIdx.x, qt = blockIdx.y;
    const int b = bh >> 4, hh = bh & 15;
    const int tid = threadIdx.x;
    const int w = tid >> 5, lane = tid & 31;
    const int grp = lane >> 2, qd = lane & 3;

    const int qbase = b * LL + qt * 64;
    const int qmin = seq_id[qbase];
    const int qmax = seq_id[qbase + 63];

    const uint32_t sb = (uint32_t)__cvta_generic_to_shared(smw);
    const uint32_t sQf = sb;
    const uint32_t sKPf = sb + 64 * AW * 4;
    const uint32_t sVTf = sb + 2 * 64 * AW * 4;

    // stage Q via cp.async
    {
        const size_t qrow = ((size_t)bh * LL + qt * 64) * 32;
        #pragma unroll
        for (int i = 0; i < 4; i++) {
            int idx = tid + i * 128;
            int r = idx >> 3, c = idx & 7;
            cp16(sQf + (r * AW + c * 4) * 4, g_qf + qrow + r * 32 + c * 4);
        }
        cp_commit();
    }
    const int row0 = w * 16 + grp, row1 = row0 + 8;
    const int qs0 = seq_id[qbase + row0];
    const int qs1 = seq_id[qbase + row1];

    float m0 = -1e30f, m1 = -1e30f, l0s = 0.f, l1s = 0.f;
    float O[8][4];
    #pragma unroll
    for (int dt = 0; dt < 8; dt++)
        #pragma unroll
        for (int q = 0; q < 4; q++) O[dt][q] = 0.f;

    for (int kt = 0; kt < LL / 64; kt++) {
        const int kb = b * LL + kt * 64;
        if (seq_id[kb + 63] < qmin || seq_id[kb] > qmax) continue;  // exact no-op tile

        __syncthreads();
        // stage K + V^T via cp.async
        {
            const size_t krow = ((size_t)bh * LL + kt * 64) * 32;
            const size_t vbase = ((size_t)bh * 32 + kt) * 64 * 32;
            #pragma unroll
            for (int i = 0; i < 4; i++) {
                int idx = tid + i * 128;
                int r = idx >> 3, c = idx & 7;
                cp16(sKPf + (r * AW + c * 4) * 4, g_kf + krow + r * 32 + c * 4);
            }
            #pragma unroll
            for (int i = 0; i < 4; i++) {
                int idx = tid + i * 128;
                int r = idx >> 3, c = idx & 7;
                cp16(sVTf + (r * AW + c * 4) * 4, g_vtf + vbase + r * 32 + c * 4);
            }
            cp_commit();
        }
        if (tid < 64) kseq[tid] = seq_id[kb + tid];
        cp_wait_all();
        __syncthreads();

        // ---- S = Q K^T (single fp16 MMA) ----
        float S[8][4];
        #pragma unroll
        for (int nt = 0; nt < 8; nt++)
            #pragma unroll
            for (int q = 0; q < 4; q++) S[nt][q] = 0.f;
        #pragma unroll
        for (int ks = 0; ks < 4; ks++) {
            int r0w = (w * 16 + grp) * AW, r1w = (w * 16 + grp + 8) * AW;
            int kw0 = ks * 8 + qd;
            uint32_t a0 = Qf[r0w + kw0],     a1 = Qf[r1w + kw0];
            uint32_t a2 = Qf[r0w + kw0 + 4], a3 = Qf[r1w + kw0 + 4];
            #pragma unroll
            for (int nt = 0; nt < 8; nt++) {
                int nw = (nt * 8 + grp) * AW;
                mma16816h(S[nt], a0, a1, a2, a3, KPf[nw + kw0], KPf[nw + kw0 + 4]);
            }
        }

        // ---- mask ----
        #pragma unroll
        for (int nt = 0; nt < 8; nt++) {
            int c0 = kseq[nt * 8 + 2 * qd];
            int c1 = kseq[nt * 8 + 2 * qd + 1];
            if (c0 != qs0) S[nt][0] = -1e30f;
            if (c1 != qs0) S[nt][1] = -1e30f;
            if (c0 != qs1) S[nt][2] = -1e30f;
            if (c1 != qs1) S[nt][3] = -1e30f;
        }

        // ---- online softmax ----
        float mx0 = -1e30f, mx1 = -1e30f;
        #pragma unroll
        for (int nt = 0; nt < 8; nt++) {
            mx0 = fmaxf(mx0, fmaxf(S[nt][0], S[nt][1]));
            mx1 = fmaxf(mx1, fmaxf(S[nt][2], S[nt][3]));
        }
        mx0 = fmaxf(mx0, __shfl_xor_sync(0xffffffffu, mx0, 1));
        mx0 = fmaxf(mx0, __shfl_xor_sync(0xffffffffu, mx0, 2));
        mx1 = fmaxf(mx1, __shfl_xor_sync(0xffffffffu, mx1, 1));
        mx1 = fmaxf(mx1, __shfl_xor_sync(0xffffffffu, mx1, 2));
        float mn0 = fmaxf(m0, mx0), mn1 = fmaxf(m1, mx1);
        float sc0 = __expf(m0 - mn0), sc1 = __expf(m1 - mn1);
        m0 = mn0; m1 = mn1;
        float s0 = 0.f, s1 = 0.f;
        #pragma unroll
        for (int nt = 0; nt < 8; nt++) {
            S[nt][0] = __expf(S[nt][0] - mn0);
            S[nt][1] = __expf(S[nt][1] - mn0);
            S[nt][2] = __expf(S[nt][2] - mn1);
            S[nt][3] = __expf(S[nt][3] - mn1);
            s0 += S[nt][0] + S[nt][1];
            s1 += S[nt][2] + S[nt][3];
        }
        s0 += __shfl_xor_sync(0xffffffffu, s0, 1);
        s0 += __shfl_xor_sync(0xffffffffu, s0, 2);
        s1 += __shfl_xor_sync(0xffffffffu, s1, 1);
        s1 += __shfl_xor_sync(0xffffffffu, s1, 2);
        l0s = l0s * sc0 + s0;
        l1s = l1s * sc1 + s1;
        #pragma unroll
        for (int dt = 0; dt < 8; dt++) {
            O[dt][0] *= sc0; O[dt][1] *= sc0;
            O[dt][2] *= sc1; O[dt][3] *= sc1;
        }

        __syncthreads();   // all K fragment reads done before P overwrite
        // ---- write P as fp16 into KPf ----
        #pragma unroll
        for (int nt = 0; nt < 8; nt++) {
            KPf[(w * 16 + grp) * AW + nt * 4 + qd]     = h2pack(S[nt][0], S[nt][1]);
            KPf[(w * 16 + grp + 8) * AW + nt * 4 + qd] = h2pack(S[nt][2], S[nt][3]);
        }
        __syncthreads();

        // ---- O += P V (single fp16 MMA) ----
        #pragma unroll
        for (int ks = 0; ks < 4; ks++) {
            int r0w = (w * 16 + grp) * AW, r1w = (w * 16 + grp + 8) * AW;
            int kw0 = ks * 8 + qd;
            uint32_t a0 = KPf[r0w + kw0], a1 = KPf[r1w + kw0];
            uint32_t a2 = KPf[r0w + kw0 + 4], a3 = KPf[r1w + kw0 + 4];
            #pragma unroll
            for (int dt = 0; dt < 8; dt++) {
                int dw = (dt * 8 + grp) * AW;
                mma16816h(O[dt], a0, a1, a2, a3, VTf[dw + kw0], VTf[dw + kw0 + 4]);
            }
        }
    }

    // epilogue: fp16 ctx words
    float inv0 = 1.0f / l0s, inv1 = 1.0f / l1s;
    const int t0 = b * LL + qt * 64 + row0;
    const int t1 = b * LL + qt * 64 + row1;
    #pragma unroll
    for (int dt = 0; dt < 8; dt++) {
        int c = hh * DHH + dt * 8 + 2 * qd;
        g_ctx16[(size_t)t0 * KW + (c >> 1)] =
            h2pack(O[dt][0] * inv0, O[dt][1] * inv0);
        g_ctx16[(size_t)t1 * KW + (c >> 1)] =
            h2pack(O[dt][2] * inv1, O[dt][3] * inv1);
    }
}

// ---------------- launch ----------------
extern "C" void kernel_launch(void* const* d_in, const int* in_sizes, int n_in,
                              void* d_out, int out_size) {
    const float* x     = (const float*)d_in[0];
    const int*   seq   = (const int*)  d_in[1];
    const float* ln1w  = (const float*)d_in[2];
    const float* ln1b  = (const float*)d_in[3];
    const float* wqkv  = (const float*)d_in[4];
    const float* qlnw  = (const float*)d_in[5];
    const float* klnw  = (const float*)d_in[6];
    const float* outw  = (const float*)d_in[7];
    float* out = (float*)d_out;

    void *phh, *pqkv, *pw16, *po16, *pctx16;
    cudaGetSymbolAddress(&phh, g_hh);
    cudaGetSymbolAddress(&pqkv, g_qkv);
    cudaGetSymbolAddress(&pw16, g_wqkv16);
    cudaGetSymbolAddress(&po16, g_outw16);
    cudaGetSymbolAddress(&pctx16, g_ctx16);

    cudaFuncSetAttribute(gemm_mma_fp16, cudaFuncAttributeMaxDynamicSharedMemorySize, GEMM_SMEM);
    cudaFuncSetAttribute(attn_kernel, cudaFuncAttributeMaxDynamicSharedMemorySize, ATTN_SMEM);

    // 0) RoPE table + weight conversions
    rope_table_kernel<<<(LL * 32 + 255) / 256, 256>>>();
    cvt16_kernel<<<(3 * DD * KW + 255) / 256, 256>>>(wqkv, (uint32_t*)pw16, 3 * DD * KW);
    cvt16_kernel<<<(DD * KW + 255) / 256, 256>>>(outw, (uint32_t*)po16, DD * KW);

    // 1) LN1 -> fp16 words
    ln1_kernel<<<TT, 256>>>(x, ln1w, ln1b);

    // 2) QKV GEMM (fp16 operands, cp.async 3-stage)
    gemm_mma_fp16<<<dim3(3 * DD / 128, TT / 128), 256, GEMM_SMEM>>>(
        (const uint32_t*)phh, (const uint32_t*)pw16, (float*)pqkv, 3 * DD);

    // 3) QK LN + RoPE (table) -> fp16 planes
    qk_rope_kernel<<<TT, 256>>>(qlnw, klnw);

    // 3b) V transpose (from g_qkv) -> fp16 plane
    vtrans_kernel<<<dim3(32, NBH), 128>>>();

    // 4) attention (tile-skip + all-fp16 mma)
    attn_kernel<<<dim3(NBH, LL / 64), 128, ATTN_SMEM>>>(seq);

    // 5) output projection (fp16 operands, cp.async 3-stage)
    gemm_mma_fp16<<<dim3(DD / 128, TT / 128), 256, GEMM_SMEM>>>(
        (const uint32_t*)pctx16, (const uint32_t*)po16, out, DD);
}